// round 1
// baseline (speedup 1.0000x reference)
#include <cuda_runtime.h>
#include <math.h>

#define PI_F 3.14159265358979323846f

// Scratch (allocation-free rule: __device__ globals)
__device__ float2 d_Kf[512 * 4097];          // filter half-spectra, pre-scaled by 1/8192
__device__ float  d_g[8ULL * 512 * 4096];    // gelu(conv + skip), fp32

__device__ __forceinline__ float2 cmul(float2 a, float2 b) {
    return make_float2(fmaf(a.x, b.x, -a.y * b.y), fmaf(a.x, b.y, a.y * b.x));
}

// Twiddle for stage s: exp(-i*pi*(tid mod 2^s)/2^s), derived from 2 seeds by
// exact recurrence v_{s-1} = v_s^2 * (-1)^{bit_{s-1}(tid)}. Re-seed at s=6
// bounds phase-error doubling to 2^6 (~2e-5 abs error).
__device__ __forceinline__ float2 stage_tw(int tid, int s, float2 vA, float2 vB) {
    float2 v; int k0;
    if (s >= 6) { v = vA; k0 = 12; } else { v = vB; k0 = 6; }
    #pragma unroll 1
    for (int k = k0; k > s; --k) {
        v = cmul(v, v);
        if ((tid >> (k - 1)) & 1) { v.x = -v.x; v.y = -v.y; }
    }
    return v;
}

// Forward radix-2 DIF, N=8192, 512 threads. Natural in -> bit-reversed out.
__device__ __forceinline__ void fft_fwd(float2* sm, int tid, float2 vA, float2 vB) {
    #pragma unroll 1
    for (int s = 12; s >= 0; --s) {
        const int m = 1 << s;
        float2 v = stage_tw(tid, s, vA, vB);
        if (s >= 10) {
            // twiddle varies across the 8 per-thread butterflies: rotate by
            // C = exp(-i*pi*512/2^s); fix the (mod 2^s) wrap with a sign.
            float2 C = (s == 12) ? make_float2(0.92387953251128674f, -0.38268343236508978f)
                     : (s == 11) ? make_float2(0.70710678118654752f, -0.70710678118654752f)
                                 : make_float2(0.0f, -1.0f);
            float2 w = v;
            #pragma unroll
            for (int it = 0; it < 8; ++it) {
                int p  = tid + it * 512;
                int i1 = ((p >> s) << (s + 1)) | (p & (m - 1));
                int i2 = i1 + m;
                float2 a = sm[i1], b = sm[i2];
                float2 tw = ((p >> s) & 1) ? make_float2(-w.x, -w.y) : w;
                sm[i1] = make_float2(a.x + b.x, a.y + b.y);
                sm[i2] = cmul(make_float2(a.x - b.x, a.y - b.y), tw);
                w = cmul(w, C);
            }
        } else {
            // m <= 512 divides 512: j = tid & (m-1) is it-invariant.
            #pragma unroll
            for (int it = 0; it < 8; ++it) {
                int p  = tid + it * 512;
                int i1 = ((p >> s) << (s + 1)) | (tid & (m - 1));
                int i2 = i1 + m;
                float2 a = sm[i1], b = sm[i2];
                sm[i1] = make_float2(a.x + b.x, a.y + b.y);
                sm[i2] = cmul(make_float2(a.x - b.x, a.y - b.y), v);
            }
        }
        __syncthreads();
    }
}

// Inverse radix-2 DIT (unnormalized; 1/N folded into d_Kf).
// Bit-reversed in -> natural out.
__device__ __forceinline__ void fft_inv(float2* sm, int tid, float2 vA, float2 vB) {
    #pragma unroll 1
    for (int s = 0; s <= 12; ++s) {
        const int m = 1 << s;
        float2 v = stage_tw(tid, s, vA, vB);
        v.y = -v.y;  // conjugate for inverse
        if (s >= 10) {
            float2 C = (s == 12) ? make_float2(0.92387953251128674f, 0.38268343236508978f)
                     : (s == 11) ? make_float2(0.70710678118654752f, 0.70710678118654752f)
                                 : make_float2(0.0f, 1.0f);
            float2 w = v;
            #pragma unroll
            for (int it = 0; it < 8; ++it) {
                int p  = tid + it * 512;
                int i1 = ((p >> s) << (s + 1)) | (p & (m - 1));
                int i2 = i1 + m;
                float2 a = sm[i1], b = sm[i2];
                float2 tw = ((p >> s) & 1) ? make_float2(-w.x, -w.y) : w;
                float2 t = cmul(b, tw);
                sm[i1] = make_float2(a.x + t.x, a.y + t.y);
                sm[i2] = make_float2(a.x - t.x, a.y - t.y);
                w = cmul(w, C);
            }
        } else {
            #pragma unroll
            for (int it = 0; it < 8; ++it) {
                int p  = tid + it * 512;
                int i1 = ((p >> s) << (s + 1)) | (tid & (m - 1));
                int i2 = i1 + m;
                float2 a = sm[i1], b = sm[i2];
                float2 t = cmul(b, v);
                sm[i1] = make_float2(a.x + t.x, a.y + t.y);
                sm[i2] = make_float2(a.x - t.x, a.y - t.y);
            }
        }
        __syncthreads();
    }
}

__device__ __forceinline__ float gelu_erf(float x) {
    return 0.5f * x * (1.0f + erff(x * 0.70710678118654752f));
}

// ---------------- Kernel A: filter spectra -------------------------------
// Two real filter rows per CTA via one complex FFT (two-for-one packing).
__global__ __launch_bounds__(512, 2)
void kfft_kernel(const float* __restrict__ k) {
    extern __shared__ float2 sm[];
    const int tid = threadIdx.x;
    const int hp  = blockIdx.x;
    const int h1  = 2 * hp, h2 = h1 + 1;
    const float* k1 = k + (size_t)h1 * 4096;
    const float* k2 = k + (size_t)h2 * 4096;

    #pragma unroll
    for (int i = 0; i < 8; ++i) {
        int l = tid + i * 512;
        sm[l]        = make_float2(k1[l], k2[l]);
        sm[l + 4096] = make_float2(0.f, 0.f);
    }
    float sn, cs;
    __sincosf(-PI_F * (float)tid * (1.0f / 4096.0f), &sn, &cs);
    float2 vA = make_float2(cs, sn);
    __sincosf(-PI_F * (float)(tid & 63) * (1.0f / 64.0f), &sn, &cs);
    float2 vB = make_float2(cs, sn);
    __syncthreads();

    fft_fwd(sm, tid, vA, vB);

    const float sc = 0.5f / 8192.0f;   // unpack 1/2 times inverse-FFT 1/N
    #pragma unroll 1
    for (int j = tid; j <= 4096; j += 512) {
        int rj = __brev((unsigned)j) >> 19;
        int rn = __brev((unsigned)((8192 - j) & 8191)) >> 19;
        float2 Zj = sm[rj], Zn = sm[rn];
        d_Kf[(size_t)h1 * 4097 + j] = make_float2(sc * (Zj.x + Zn.x), sc * (Zj.y - Zn.y));
        d_Kf[(size_t)h2 * 4097 + j] = make_float2(sc * (Zj.y + Zn.y), sc * (Zn.x - Zj.x));
    }
}

// ---------------- Kernel B: conv + skip + gelu ---------------------------
__global__ __launch_bounds__(512, 2)
void conv_kernel(const float* __restrict__ u, const float* __restrict__ D) {
    extern __shared__ float2 sm[];
    const int tid = threadIdx.x;
    const int hp  = blockIdx.x;
    const int b   = blockIdx.y;
    const int h1  = 2 * hp, h2 = h1 + 1;
    const float* u1 = u + ((size_t)b * 512 + h1) * 4096;
    const float* u2 = u1 + 4096;

    float u1r[8], u2r[8];
    #pragma unroll
    for (int i = 0; i < 8; ++i) {
        int l = tid + i * 512;
        u1r[i] = u1[l];
        u2r[i] = u2[l];
        sm[l]        = make_float2(u1r[i], u2r[i]);
        sm[l + 4096] = make_float2(0.f, 0.f);
    }
    float sn, cs;
    __sincosf(-PI_F * (float)tid * (1.0f / 4096.0f), &sn, &cs);
    float2 vA = make_float2(cs, sn);
    __sincosf(-PI_F * (float)(tid & 63) * (1.0f / 64.0f), &sn, &cs);
    float2 vB = make_float2(cs, sn);
    __syncthreads();

    fft_fwd(sm, tid, vA, vB);

    // Pointwise: unpack two real spectra, multiply by filter spectra, repack.
    // Works entirely in the bit-reversed domain; pairs (j, N-j) partition the
    // array per thread, so no extra sync is needed inside the loop.
    const float2* K1 = d_Kf + (size_t)h1 * 4097;
    const float2* K2 = d_Kf + (size_t)h2 * 4097;
    #pragma unroll 1
    for (int j = tid; j <= 4096; j += 512) {
        int rj = __brev((unsigned)j) >> 19;
        int rn = __brev((unsigned)((8192 - j) & 8191)) >> 19;
        float2 Zj = sm[rj], Zn = sm[rn];
        float2 U1 = make_float2(0.5f * (Zj.x + Zn.x), 0.5f * (Zj.y - Zn.y));
        float2 U2 = make_float2(0.5f * (Zj.y + Zn.y), 0.5f * (Zn.x - Zj.x));
        float2 Y1 = cmul(U1, K1[j]);
        float2 Y2 = cmul(U2, K2[j]);
        sm[rj] = make_float2(Y1.x - Y2.y, Y1.y + Y2.x);          // W(j)   = Y1 + i*Y2
        sm[rn] = make_float2(Y1.x + Y2.y, Y2.x - Y1.y);          // W(N-j) = conj(Y1 - i*Y2)
    }
    __syncthreads();

    fft_inv(sm, tid, vA, vB);   // ends with __syncthreads()

    const float dA = D[h1], dB = D[h2];
    float* g1 = d_g + ((size_t)b * 512 + h1) * 4096;
    float* g2 = g1 + 4096;
    #pragma unroll
    for (int i = 0; i < 8; ++i) {
        int l = tid + i * 512;
        float2 w = sm[l];
        g1[l] = gelu_erf(w.x + dA * u1r[i]);
        g2[l] = gelu_erf(w.y + dB * u2r[i]);
    }
}

// ---------------- Kernel C: pointwise linear (fp32 SGEMM) ----------------
// out[b,d,l] = sum_h W[d,h] * g[b,h,l] + bias[d]
// 128x128 tile, BK=8, 256 threads, 8x8 microtile.
__global__ __launch_bounds__(256, 2)
void gemm_kernel(const float* __restrict__ W, const float* __restrict__ bias,
                 float* __restrict__ out) {
    __shared__ float Ws[8][132];
    __shared__ float Gs[8][132];

    const int bb = blockIdx.z;
    const int d0 = blockIdx.y * 128;
    const int l0 = blockIdx.x * 128;
    const int t  = threadIdx.x;
    const int tx = t & 15, ty = t >> 4;

    const float* gbase = d_g + (size_t)bb * 512 * 4096;

    float acc[8][8];
    #pragma unroll
    for (int i = 0; i < 8; ++i)
        #pragma unroll
        for (int j = 0; j < 8; ++j) acc[i][j] = 0.f;

    const int wrow = t >> 1;            // 0..127
    const int wcol = (t & 1) * 4;       // 0 or 4
    const int grow = t >> 5;            // 0..7
    const int gcol = (t & 31) * 4;      // 0..124

    #pragma unroll 1
    for (int kk = 0; kk < 512; kk += 8) {
        float4 wv = *(const float4*)&W[(size_t)(d0 + wrow) * 512 + kk + wcol];
        float4 gv = *(const float4*)&gbase[(size_t)(kk + grow) * 4096 + l0 + gcol];
        __syncthreads();
        Ws[wcol + 0][wrow] = wv.x;
        Ws[wcol + 1][wrow] = wv.y;
        Ws[wcol + 2][wrow] = wv.z;
        Ws[wcol + 3][wrow] = wv.w;
        *(float4*)&Gs[grow][gcol] = gv;
        __syncthreads();
        #pragma unroll
        for (int k = 0; k < 8; ++k) {
            float a[8], bv[8];
            *(float4*)&a[0]  = *(const float4*)&Ws[k][ty * 4];
            *(float4*)&a[4]  = *(const float4*)&Ws[k][64 + ty * 4];
            *(float4*)&bv[0] = *(const float4*)&Gs[k][tx * 4];
            *(float4*)&bv[4] = *(const float4*)&Gs[k][64 + tx * 4];
            #pragma unroll
            for (int i = 0; i < 8; ++i)
                #pragma unroll
                for (int j = 0; j < 8; ++j)
                    acc[i][j] = fmaf(a[i], bv[j], acc[i][j]);
        }
    }

    #pragma unroll
    for (int ih = 0; ih < 2; ++ih) {
        #pragma unroll
        for (int i = 0; i < 4; ++i) {
            int d = d0 + ih * 64 + ty * 4 + i;
            float bvl = bias[d];
            float* orow = out + ((size_t)bb * 512 + d) * 4096 + l0;
            #pragma unroll
            for (int jh = 0; jh < 2; ++jh) {
                float4 o;
                o.x = acc[ih * 4 + i][jh * 4 + 0] + bvl;
                o.y = acc[ih * 4 + i][jh * 4 + 1] + bvl;
                o.z = acc[ih * 4 + i][jh * 4 + 2] + bvl;
                o.w = acc[ih * 4 + i][jh * 4 + 3] + bvl;
                *(float4*)&orow[jh * 64 + tx * 4] = o;
            }
        }
    }
}

// ---------------- Launch ---------------------------------------------------
extern "C" void kernel_launch(void* const* d_in, const int* in_sizes, int n_in,
                              void* d_out, int out_size) {
    const float* u    = (const float*)d_in[0];   // (8, 512, 4096)
    const float* k    = (const float*)d_in[1];   // (1, 512, 4096)
    const float* D    = (const float*)d_in[2];   // (1, 512)
    const float* W    = (const float*)d_in[3];   // (512, 512)
    const float* bias = (const float*)d_in[4];   // (512,)
    float* out = (float*)d_out;                  // (8, 512, 4096)

    const size_t smem = 8192 * sizeof(float2);   // 64 KB
    cudaFuncSetAttribute(kfft_kernel, cudaFuncAttributeMaxDynamicSharedMemorySize, (int)smem);
    cudaFuncSetAttribute(conv_kernel, cudaFuncAttributeMaxDynamicSharedMemorySize, (int)smem);

    kfft_kernel<<<256, 512, smem>>>(k);
    conv_kernel<<<dim3(256, 8), 512, smem>>>(u, D);
    gemm_kernel<<<dim3(4096 / 128, 512 / 128, 8), 256>>>(W, bias, out);
}

// round 5
// speedup vs baseline: 1.3119x; 1.3119x over previous
#include <cuda_runtime.h>
#include <math.h>

#define PI_F 3.14159265358979323846f

// Scratch (allocation-free rule: __device__ globals)
__device__ float2 d_Kf[512 * 4097];          // filter half-spectra, pre-scaled by 1/8192
__device__ float  d_g[8ULL * 512 * 4096];    // gelu(conv + skip), fp32

// ---------------- complex helpers ----------------------------------------
__device__ __forceinline__ float2 cadd(float2 a, float2 b){ return make_float2(a.x+b.x, a.y+b.y); }
__device__ __forceinline__ float2 csub(float2 a, float2 b){ return make_float2(a.x-b.x, a.y-b.y); }
__device__ __forceinline__ float2 cmul(float2 a, float2 b){
    return make_float2(fmaf(a.x, b.x, -a.y*b.y), fmaf(a.x, b.y, a.y*b.x));
}
__device__ __forceinline__ float2 csqr(float2 a){
    return make_float2(fmaf(a.x,a.x,-a.y*a.y), 2.f*a.x*a.y);
}
__device__ __forceinline__ float2 conjf2(float2 a){ return make_float2(a.x, -a.y); }
__device__ __forceinline__ float2 mi_neg(float2 a){ return make_float2(a.y, -a.x); }  // -i*a
__device__ __forceinline__ float2 mi_pos(float2 a){ return make_float2(-a.y, a.x); }  // +i*a
// multiply by i^r
__device__ __forceinline__ float2 irot(float2 a, int r){
    float x = a.x, y = a.y;
    if (r & 1){ float t = x; x = -y; y = t; }
    if (r & 2){ x = -x; y = -y; }
    return make_float2(x, y);
}

// radix-4 butterflies (in-place on a,b,c,d = y0..y3 slots)
__device__ __forceinline__ void bf4_fwd(float2&a, float2&b, float2&c, float2&d,
                                        float2 w1, float2 w2, float2 w3){
    float2 t0=cadd(a,c), t1=csub(a,c), t2=cadd(b,d), t3=mi_neg(csub(b,d));
    a = cadd(t0,t2);
    b = cmul(cadd(t1,t3), w1);
    c = cmul(csub(t0,t2), w2);
    d = cmul(csub(t1,t3), w3);
}
__device__ __forceinline__ void bf4_inv(float2&a, float2&b, float2&c, float2&d,
                                        float2 w1c, float2 w2c, float2 w3c){
    float2 z1=cmul(b,w1c), z2=cmul(c,w2c), z3=cmul(d,w3c);
    float2 A=cadd(a,z2), B=csub(a,z2), Cc=cadd(z1,z3), Dd=csub(z1,z3);
    float2 iD = mi_pos(Dd);
    a = cadd(A,Cc); c = csub(A,Cc);
    b = cadd(B,iD); d = csub(B,iD);
}

// smem padding: 1 float2 pad per 16 elements -> conflict-free stage strides
#define SPAD(i) ((i) + ((i) >> 4))

// position of frequency j in the permuted output of [r2, r4 x6] DIF
__device__ __forceinline__ int posf(int j){
    int j0 = j & 1, jp = j >> 1;                 // 12-bit jp
    int y = __brev((unsigned)jp) >> 20;          // bit-reverse 12 bits
    int z = ((y & 0x555) << 1) | ((y >> 1) & 0x555);  // swap adjacent bits -> base-4 digit reversal
    return (j0 << 12) + z;
}

// ---------------- radix-4 stages ------------------------------------------
// M = 4096 stage: q spans [0,1024) -> two twiddle variants per thread
template<bool INV>
__device__ __forceinline__ void r4_stage4096(float2* __restrict__ sm, int tid, float2 wA){
    const float R2 = 0.70710678118654752440f;
    float2 w1a = INV ? conjf2(wA) : wA;
    float2 S   = INV ? make_float2(R2, R2) : make_float2(R2, -R2);  // exp(∓i*pi/4)
    float2 w1b = cmul(w1a, S);
    float2 w2a = csqr(w1a), w3a = cmul(w1a, w2a);
    float2 w2b = csqr(w1b), w3b = cmul(w1b, w2b);
    #pragma unroll
    for (int it = 0; it < 4; ++it){
        int q  = ((it & 1) << 9) + tid;
        int i0 = ((it >> 1) << 12) + q;
        int pi = SPAD(i0);
        float2 a = sm[pi], b = sm[pi+1088], c = sm[pi+2176], d = sm[pi+3264];
        if (it & 1){
            if (!INV) bf4_fwd(a,b,c,d, w1b,w2b,w3b); else bf4_inv(a,b,c,d, w1b,w2b,w3b);
        } else {
            if (!INV) bf4_fwd(a,b,c,d, w1a,w2a,w3a); else bf4_inv(a,b,c,d, w1a,w2a,w3a);
        }
        sm[pi] = a; sm[pi+1088] = b; sm[pi+2176] = c; sm[pi+3264] = d;
    }
    __syncthreads();
}

// generic stage for M in {1024, 256, 64}: q = tid & (M/4-1), invariant across it
template<int M, bool INV>
__device__ __forceinline__ void r4_stage(float2* __restrict__ sm, int tid, float2 w1in){
    float2 w1 = INV ? conjf2(w1in) : w1in;
    float2 w2 = csqr(w1), w3 = cmul(w1, w2);
    const int mq   = M >> 2;
    const int doff = mq + (mq >> 4);
    #pragma unroll
    for (int it = 0; it < 4; ++it){
        int p  = tid + it * 512;
        int i0 = ((p & ~(mq-1)) << 2) | (p & (mq-1));
        int pi = SPAD(i0);
        float2 a = sm[pi], b = sm[pi+doff], c = sm[pi+2*doff], d = sm[pi+3*doff];
        if (!INV) bf4_fwd(a,b,c,d, w1,w2,w3); else bf4_inv(a,b,c,d, w1,w2,w3);
        sm[pi] = a; sm[pi+doff] = b; sm[pi+2*doff] = c; sm[pi+3*doff] = d;
    }
    __syncthreads();
}

// merged M=16 + M=4 stages in registers (one contiguous 16-block per thread)
// Twiddles are powers of w16 = exp(-i*pi/8):
//   W1[q] = w16^q, W2[q] = w16^{2q}, W3[q] = w16^{3q}
template<bool INV>
__device__ __forceinline__ void stage_16_4(float2* __restrict__ sm, int tid){
    const int pb = tid * 17;   // SPAD(16*tid)
    float2 r[16];
    #pragma unroll
    for (int i = 0; i < 16; ++i) r[i] = sm[pb + i];

    const float CP8 = 0.92387953251128675613f;  // cos(pi/8)
    const float SP8 = 0.38268343236508977173f;  // sin(pi/8)
    const float R2  = 0.70710678118654752440f;
    const float C3  = 0.38268343236508977173f;  // cos(3pi/8)
    const float S3v = 0.92387953251128675613f;  // sin(3pi/8)
    const float sg = INV ? 1.f : -1.f;
    float2 W1[4] = { make_float2(1,0), make_float2(CP8, sg*SP8), make_float2(R2, sg*R2),   make_float2(C3, sg*S3v) };
    float2 W2[4] = { make_float2(1,0), make_float2(R2, sg*R2),   make_float2(0.f, sg),     make_float2(-R2, sg*R2) };
    float2 W3[4] = { make_float2(1,0), make_float2(C3, sg*S3v),  make_float2(-R2, sg*R2),  make_float2(-CP8, -sg*SP8) };

    if (!INV){
        #pragma unroll
        for (int q = 0; q < 4; ++q)
            bf4_fwd(r[q], r[q+4], r[q+8], r[q+12], W1[q], W2[q], W3[q]);
        #pragma unroll
        for (int g = 0; g < 4; ++g){
            float2 a=r[4*g], b=r[4*g+1], c=r[4*g+2], d=r[4*g+3];
            float2 t0=cadd(a,c), t1=csub(a,c), t2=cadd(b,d), t3=mi_neg(csub(b,d));
            r[4*g]=cadd(t0,t2); r[4*g+1]=cadd(t1,t3); r[4*g+2]=csub(t0,t2); r[4*g+3]=csub(t1,t3);
        }
    } else {
        #pragma unroll
        for (int g = 0; g < 4; ++g){
            float2 y0=r[4*g], y1=r[4*g+1], y2=r[4*g+2], y3=r[4*g+3];
            float2 A=cadd(y0,y2), B=csub(y0,y2), Cc=cadd(y1,y3), Dd=csub(y1,y3);
            float2 iD=mi_pos(Dd);
            r[4*g]=cadd(A,Cc); r[4*g+2]=csub(A,Cc);
            r[4*g+1]=cadd(B,iD); r[4*g+3]=csub(B,iD);
        }
        #pragma unroll
        for (int q = 0; q < 4; ++q)
            bf4_inv(r[q], r[q+4], r[q+8], r[q+12], W1[q], W2[q], W3[q]);
    }
    #pragma unroll
    for (int i = 0; i < 16; ++i) sm[pb + i] = r[i];
    __syncthreads();
}

// derive per-thread stage twiddles from seeds
struct Tw { float2 wA, w1024, w256, wB, wC; };
__device__ __forceinline__ Tw make_tw(int tid){
    Tw t; float sn, cs;
    __sincosf(-PI_F * (float)tid * (1.0f/2048.0f), &sn, &cs);  t.wA = make_float2(cs, sn); // e^{-2pi i tid/4096}
    __sincosf(-PI_F * (float)(tid & 15) * (1.0f/32.0f), &sn, &cs); t.wB = make_float2(cs, sn); // e^{-2pi i (tid&15)/64}
    __sincosf(-PI_F * (float)tid * (1.0f/4096.0f), &sn, &cs);  t.wC = make_float2(cs, sn); // e^{-2pi i tid/8192}
    t.w1024 = irot(csqr(csqr(t.wA)),   (tid >> 8) & 3);
    t.w256  = irot(csqr(csqr(t.w1024)),(tid >> 6) & 3);
    return t;
}

__device__ __forceinline__ float gelu_erf(float x){
    return 0.5f * x * (1.0f + erff(x * 0.70710678118654752f));
}

// C8 = exp(-2*pi*i*512/8192) = exp(-i*pi/8): per-512 increment of the
// length-8192 half-twiddle chain
#define C8X 0.92387953251128675613f
#define C8Y (-0.38268343236508977173f)

// ---------------- Kernel A: filter spectra --------------------------------
__global__ __launch_bounds__(512, 2)
void kfft_kernel(const float* __restrict__ k){
    extern __shared__ float2 sm[];
    const int tid = threadIdx.x;
    const int hp  = blockIdx.x;
    const int h1  = 2*hp, h2 = h1 + 1;
    const float* k1 = k + (size_t)h1 * 4096;
    const float* k2 = k + (size_t)h2 * 4096;

    Tw tw = make_tw(tid);
    const float2 C8 = make_float2(C8X, C8Y);

    // fused load + radix-2 (zero-padded top half): E=x, O=x*w8192^l
    float2 w = tw.wC;
    #pragma unroll
    for (int it = 0; it < 8; ++it){
        int l = tid + it * 512;
        float2 v = make_float2(k1[l], k2[l]);
        sm[SPAD(l)] = v;
        sm[SPAD(l + 4096)] = cmul(v, w);
        w = cmul(w, C8);
    }
    __syncthreads();

    r4_stage4096<false>(sm, tid, tw.wA);
    r4_stage<1024,false>(sm, tid, tw.w1024);
    r4_stage<256, false>(sm, tid, tw.w256);
    r4_stage<64,  false>(sm, tid, tw.wB);
    stage_16_4<false>(sm, tid);

    const float sc = 0.5f / 8192.0f;
    #pragma unroll 1
    for (int j = tid; j <= 4096; j += 512){
        int rj = SPAD(posf(j));
        int rn = SPAD(posf((8192 - j) & 8191));
        float2 Zj = sm[rj], Zn = sm[rn];
        d_Kf[(size_t)h1 * 4097 + j] = make_float2(sc*(Zj.x + Zn.x), sc*(Zj.y - Zn.y));
        d_Kf[(size_t)h2 * 4097 + j] = make_float2(sc*(Zj.y + Zn.y), sc*(Zn.x - Zj.x));
    }
}

// ---------------- Kernel B: conv + skip + gelu -----------------------------
__global__ __launch_bounds__(512, 2)
void conv_kernel(const float* __restrict__ u, const float* __restrict__ D){
    extern __shared__ float2 sm[];
    const int tid = threadIdx.x;
    const int hp  = blockIdx.x;
    const int b   = blockIdx.y;
    const int h1  = 2*hp, h2 = h1 + 1;
    const float* u1 = u + ((size_t)b * 512 + h1) * 4096;
    const float* u2 = u1 + 4096;

    Tw tw = make_tw(tid);
    const float2 C8 = make_float2(C8X, C8Y);

    // fused load + radix-2
    float2 w = tw.wC;
    #pragma unroll
    for (int it = 0; it < 8; ++it){
        int l = tid + it * 512;
        float2 v = make_float2(u1[l], u2[l]);
        sm[SPAD(l)] = v;
        sm[SPAD(l + 4096)] = cmul(v, w);
        w = cmul(w, C8);
    }
    __syncthreads();

    r4_stage4096<false>(sm, tid, tw.wA);
    r4_stage<1024,false>(sm, tid, tw.w1024);
    r4_stage<256, false>(sm, tid, tw.w256);
    r4_stage<64,  false>(sm, tid, tw.wB);
    stage_16_4<false>(sm, tid);

    // pointwise: unpack two real spectra, multiply, repack (permuted domain)
    const float2* K1 = d_Kf + (size_t)h1 * 4097;
    const float2* K2 = d_Kf + (size_t)h2 * 4097;
    #pragma unroll 1
    for (int j = tid; j <= 4096; j += 512){
        int rj = SPAD(posf(j));
        int rn = SPAD(posf((8192 - j) & 8191));
        float2 Zj = sm[rj], Zn = sm[rn];
        float2 U1 = make_float2(0.5f*(Zj.x + Zn.x), 0.5f*(Zj.y - Zn.y));
        float2 U2 = make_float2(0.5f*(Zj.y + Zn.y), 0.5f*(Zn.x - Zj.x));
        float2 Y1 = cmul(U1, K1[j]);
        float2 Y2 = cmul(U2, K2[j]);
        sm[rj] = make_float2(Y1.x - Y2.y, Y1.y + Y2.x);   // W(j)   = Y1 + i*Y2
        sm[rn] = make_float2(Y1.x + Y2.y, Y2.x - Y1.y);   // W(N-j) = conj(Y1 - i*Y2)
    }
    __syncthreads();

    stage_16_4<true>(sm, tid);
    r4_stage<64,  true>(sm, tid, tw.wB);
    r4_stage<256, true>(sm, tid, tw.w256);
    r4_stage<1024,true>(sm, tid, tw.w1024);
    r4_stage4096<true>(sm, tid, tw.wA);

    // fused final radix-2 (only first 4096 outputs) + skip + gelu + store
    const float dA = D[h1], dB = D[h2];
    float* g1 = d_g + ((size_t)b * 512 + h1) * 4096;
    float* g2 = g1 + 4096;
    w = tw.wC;
    #pragma unroll
    for (int it = 0; it < 8; ++it){
        int l = tid + it * 512;
        float2 E = sm[SPAD(l)], O = sm[SPAD(l + 4096)];
        float2 y = cadd(E, cmul(O, conjf2(w)));
        g1[l] = gelu_erf(y.x + dA * u1[l]);
        g2[l] = gelu_erf(y.y + dB * u2[l]);
        w = cmul(w, C8);
    }
}

// ---------------- Kernel C: pointwise linear (fp32 SGEMM) -----------------
__global__ __launch_bounds__(256, 2)
void gemm_kernel(const float* __restrict__ W, const float* __restrict__ bias,
                 float* __restrict__ out){
    __shared__ float Ws[8][132];
    __shared__ float Gs[8][132];

    const int bb = blockIdx.z;
    const int d0 = blockIdx.y * 128;
    const int l0 = blockIdx.x * 128;
    const int t  = threadIdx.x;
    const int tx = t & 15, ty = t >> 4;

    const float* gbase = d_g + (size_t)bb * 512 * 4096;

    float acc[8][8];
    #pragma unroll
    for (int i = 0; i < 8; ++i)
        #pragma unroll
        for (int j = 0; j < 8; ++j) acc[i][j] = 0.f;

    const int wrow = t >> 1;
    const int wcol = (t & 1) * 4;
    const int grow = t >> 5;
    const int gcol = (t & 31) * 4;

    #pragma unroll 1
    for (int kk = 0; kk < 512; kk += 8){
        float4 wv = *(const float4*)&W[(size_t)(d0 + wrow) * 512 + kk + wcol];
        float4 gv = *(const float4*)&gbase[(size_t)(kk + grow) * 4096 + l0 + gcol];
        __syncthreads();
        Ws[wcol + 0][wrow] = wv.x;
        Ws[wcol + 1][wrow] = wv.y;
        Ws[wcol + 2][wrow] = wv.z;
        Ws[wcol + 3][wrow] = wv.w;
        *(float4*)&Gs[grow][gcol] = gv;
        __syncthreads();
        #pragma unroll
        for (int k = 0; k < 8; ++k){
            float a[8], bv[8];
            *(float4*)&a[0]  = *(const float4*)&Ws[k][ty * 4];
            *(float4*)&a[4]  = *(const float4*)&Ws[k][64 + ty * 4];
            *(float4*)&bv[0] = *(const float4*)&Gs[k][tx * 4];
            *(float4*)&bv[4] = *(const float4*)&Gs[k][64 + tx * 4];
            #pragma unroll
            for (int i = 0; i < 8; ++i)
                #pragma unroll
                for (int j = 0; j < 8; ++j)
                    acc[i][j] = fmaf(a[i], bv[j], acc[i][j]);
        }
    }

    #pragma unroll
    for (int ih = 0; ih < 2; ++ih){
        #pragma unroll
        for (int i = 0; i < 4; ++i){
            int d = d0 + ih * 64 + ty * 4 + i;
            float bvl = bias[d];
            float* orow = out + ((size_t)bb * 512 + d) * 4096 + l0;
            #pragma unroll
            for (int jh = 0; jh < 2; ++jh){
                float4 o;
                o.x = acc[ih*4+i][jh*4+0] + bvl;
                o.y = acc[ih*4+i][jh*4+1] + bvl;
                o.z = acc[ih*4+i][jh*4+2] + bvl;
                o.w = acc[ih*4+i][jh*4+3] + bvl;
                *(float4*)&orow[jh * 64 + tx * 4] = o;
            }
        }
    }
}

// ---------------- Launch ---------------------------------------------------
extern "C" void kernel_launch(void* const* d_in, const int* in_sizes, int n_in,
                              void* d_out, int out_size){
    const float* u    = (const float*)d_in[0];   // (8, 512, 4096)
    const float* k    = (const float*)d_in[1];   // (1, 512, 4096)
    const float* D    = (const float*)d_in[2];   // (1, 512)
    const float* W    = (const float*)d_in[3];   // (512, 512)
    const float* bias = (const float*)d_in[4];   // (512,)
    float* out = (float*)d_out;                  // (8, 512, 4096)

    const size_t smem = 8704 * sizeof(float2);   // 68 KB (padded)
    cudaFuncSetAttribute(kfft_kernel, cudaFuncAttributeMaxDynamicSharedMemorySize, (int)smem);
    cudaFuncSetAttribute(conv_kernel, cudaFuncAttributeMaxDynamicSharedMemorySize, (int)smem);

    kfft_kernel<<<256, 512, smem>>>(k);
    conv_kernel<<<dim3(256, 8), 512, smem>>>(u, D);
    gemm_kernel<<<dim3(4096 / 128, 512 / 128, 8), 256>>>(W, bias, out);
}

// round 6
// speedup vs baseline: 1.3864x; 1.0568x over previous
#include <cuda_runtime.h>
#include <math.h>

#define PI_F 3.14159265358979323846f

// Scratch (allocation-free rule: __device__ globals)
__device__ float2 d_Kf[512 * 4097];          // filter half-spectra, pre-scaled by 1/8192
__device__ float  d_g[8ULL * 512 * 4096];    // gelu(conv + skip), fp32

// ---------------- complex helpers ----------------------------------------
__device__ __forceinline__ float2 cadd(float2 a, float2 b){ return make_float2(a.x+b.x, a.y+b.y); }
__device__ __forceinline__ float2 csub(float2 a, float2 b){ return make_float2(a.x-b.x, a.y-b.y); }
__device__ __forceinline__ float2 cmul(float2 a, float2 b){
    return make_float2(fmaf(a.x, b.x, -a.y*b.y), fmaf(a.x, b.y, a.y*b.x));
}
__device__ __forceinline__ float2 csqr(float2 a){
    return make_float2(fmaf(a.x,a.x,-a.y*a.y), 2.f*a.x*a.y);
}
__device__ __forceinline__ float2 conjf2(float2 a){ return make_float2(a.x, -a.y); }
__device__ __forceinline__ float2 mi_neg(float2 a){ return make_float2(a.y, -a.x); }  // -i*a
__device__ __forceinline__ float2 mi_pos(float2 a){ return make_float2(-a.y, a.x); }  // +i*a
// multiply by i^r
__device__ __forceinline__ float2 irot(float2 a, int r){
    float x = a.x, y = a.y;
    if (r & 1){ float t = x; x = -y; y = t; }
    if (r & 2){ x = -x; y = -y; }
    return make_float2(x, y);
}

// radix-4 butterflies (in-place on a,b,c,d = y0..y3 slots)
__device__ __forceinline__ void bf4_fwd(float2&a, float2&b, float2&c, float2&d,
                                        float2 w1, float2 w2, float2 w3){
    float2 t0=cadd(a,c), t1=csub(a,c), t2=cadd(b,d), t3=mi_neg(csub(b,d));
    a = cadd(t0,t2);
    b = cmul(cadd(t1,t3), w1);
    c = cmul(csub(t0,t2), w2);
    d = cmul(csub(t1,t3), w3);
}
__device__ __forceinline__ void bf4_inv(float2&a, float2&b, float2&c, float2&d,
                                        float2 w1c, float2 w2c, float2 w3c){
    float2 z1=cmul(b,w1c), z2=cmul(c,w2c), z3=cmul(d,w3c);
    float2 A=cadd(a,z2), B=csub(a,z2), Cc=cadd(z1,z3), Dd=csub(z1,z3);
    float2 iD = mi_pos(Dd);
    a = cadd(A,Cc); c = csub(A,Cc);
    b = cadd(B,iD); d = csub(B,iD);
}

// smem padding: 1 float2 pad per 16 elements -> conflict-free stage strides
#define SPAD(i) ((i) + ((i) >> 4))

// position of frequency j in the permuted output of [r2, r4 x6] DIF
__device__ __forceinline__ int posf(int j){
    int j0 = j & 1, jp = j >> 1;                 // 12-bit jp
    int y = __brev((unsigned)jp) >> 20;          // bit-reverse 12 bits
    int z = ((y & 0x555) << 1) | ((y >> 1) & 0x555);  // swap adjacent bits -> base-4 digit reversal
    return (j0 << 12) + z;
}

// ---------------- radix-4 stages ------------------------------------------
// M = 4096 stage: q spans [0,1024) -> two twiddle variants per thread
template<bool INV>
__device__ __forceinline__ void r4_stage4096(float2* __restrict__ sm, int tid, float2 wA){
    const float R2 = 0.70710678118654752440f;
    float2 w1a = INV ? conjf2(wA) : wA;
    float2 S   = INV ? make_float2(R2, R2) : make_float2(R2, -R2);  // exp(∓i*pi/4)
    float2 w1b = cmul(w1a, S);
    float2 w2a = csqr(w1a), w3a = cmul(w1a, w2a);
    float2 w2b = csqr(w1b), w3b = cmul(w1b, w2b);
    #pragma unroll
    for (int it = 0; it < 4; ++it){
        int q  = ((it & 1) << 9) + tid;
        int i0 = ((it >> 1) << 12) + q;
        int pi = SPAD(i0);
        float2 a = sm[pi], b = sm[pi+1088], c = sm[pi+2176], d = sm[pi+3264];
        if (it & 1){
            if (!INV) bf4_fwd(a,b,c,d, w1b,w2b,w3b); else bf4_inv(a,b,c,d, w1b,w2b,w3b);
        } else {
            if (!INV) bf4_fwd(a,b,c,d, w1a,w2a,w3a); else bf4_inv(a,b,c,d, w1a,w2a,w3a);
        }
        sm[pi] = a; sm[pi+1088] = b; sm[pi+2176] = c; sm[pi+3264] = d;
    }
    __syncthreads();
}

// generic stage for M in {1024, 256, 64}: q = tid & (M/4-1), invariant across it
template<int M, bool INV>
__device__ __forceinline__ void r4_stage(float2* __restrict__ sm, int tid, float2 w1in){
    float2 w1 = INV ? conjf2(w1in) : w1in;
    float2 w2 = csqr(w1), w3 = cmul(w1, w2);
    const int mq   = M >> 2;
    const int doff = mq + (mq >> 4);
    #pragma unroll
    for (int it = 0; it < 4; ++it){
        int p  = tid + it * 512;
        int i0 = ((p & ~(mq-1)) << 2) | (p & (mq-1));
        int pi = SPAD(i0);
        float2 a = sm[pi], b = sm[pi+doff], c = sm[pi+2*doff], d = sm[pi+3*doff];
        if (!INV) bf4_fwd(a,b,c,d, w1,w2,w3); else bf4_inv(a,b,c,d, w1,w2,w3);
        sm[pi] = a; sm[pi+doff] = b; sm[pi+2*doff] = c; sm[pi+3*doff] = d;
    }
    __syncthreads();
}

// merged M=16 + M=4 stages in registers (one contiguous 16-block per thread)
// Twiddles are powers of w16 = exp(-i*pi/8):
//   W1[q] = w16^q, W2[q] = w16^{2q}, W3[q] = w16^{3q}
template<bool INV>
__device__ __forceinline__ void stage_16_4(float2* __restrict__ sm, int tid){
    const int pb = tid * 17;   // SPAD(16*tid)
    float2 r[16];
    #pragma unroll
    for (int i = 0; i < 16; ++i) r[i] = sm[pb + i];

    const float CP8 = 0.92387953251128675613f;  // cos(pi/8)
    const float SP8 = 0.38268343236508977173f;  // sin(pi/8)
    const float R2  = 0.70710678118654752440f;
    const float C3  = 0.38268343236508977173f;  // cos(3pi/8)
    const float S3v = 0.92387953251128675613f;  // sin(3pi/8)
    const float sg = INV ? 1.f : -1.f;
    float2 W1[4] = { make_float2(1,0), make_float2(CP8, sg*SP8), make_float2(R2, sg*R2),   make_float2(C3, sg*S3v) };
    float2 W2[4] = { make_float2(1,0), make_float2(R2, sg*R2),   make_float2(0.f, sg),     make_float2(-R2, sg*R2) };
    float2 W3[4] = { make_float2(1,0), make_float2(C3, sg*S3v),  make_float2(-R2, sg*R2),  make_float2(-CP8, -sg*SP8) };

    if (!INV){
        #pragma unroll
        for (int q = 0; q < 4; ++q)
            bf4_fwd(r[q], r[q+4], r[q+8], r[q+12], W1[q], W2[q], W3[q]);
        #pragma unroll
        for (int g = 0; g < 4; ++g){
            float2 a=r[4*g], b=r[4*g+1], c=r[4*g+2], d=r[4*g+3];
            float2 t0=cadd(a,c), t1=csub(a,c), t2=cadd(b,d), t3=mi_neg(csub(b,d));
            r[4*g]=cadd(t0,t2); r[4*g+1]=cadd(t1,t3); r[4*g+2]=csub(t0,t2); r[4*g+3]=csub(t1,t3);
        }
    } else {
        #pragma unroll
        for (int g = 0; g < 4; ++g){
            float2 y0=r[4*g], y1=r[4*g+1], y2=r[4*g+2], y3=r[4*g+3];
            float2 A=cadd(y0,y2), B=csub(y0,y2), Cc=cadd(y1,y3), Dd=csub(y1,y3);
            float2 iD=mi_pos(Dd);
            r[4*g]=cadd(A,Cc); r[4*g+2]=csub(A,Cc);
            r[4*g+1]=cadd(B,iD); r[4*g+3]=csub(B,iD);
        }
        #pragma unroll
        for (int q = 0; q < 4; ++q)
            bf4_inv(r[q], r[q+4], r[q+8], r[q+12], W1[q], W2[q], W3[q]);
    }
    #pragma unroll
    for (int i = 0; i < 16; ++i) sm[pb + i] = r[i];
    __syncthreads();
}

// derive per-thread stage twiddles from seeds
struct Tw { float2 wA, w1024, w256, wB, wC; };
__device__ __forceinline__ Tw make_tw(int tid){
    Tw t; float sn, cs;
    __sincosf(-PI_F * (float)tid * (1.0f/2048.0f), &sn, &cs);  t.wA = make_float2(cs, sn); // e^{-2pi i tid/4096}
    __sincosf(-PI_F * (float)(tid & 15) * (1.0f/32.0f), &sn, &cs); t.wB = make_float2(cs, sn); // e^{-2pi i (tid&15)/64}
    __sincosf(-PI_F * (float)tid * (1.0f/4096.0f), &sn, &cs);  t.wC = make_float2(cs, sn); // e^{-2pi i tid/8192}
    t.w1024 = irot(csqr(csqr(t.wA)),   (tid >> 8) & 3);
    t.w256  = irot(csqr(csqr(t.w1024)),(tid >> 6) & 3);
    return t;
}

__device__ __forceinline__ float gelu_erf(float x){
    return 0.5f * x * (1.0f + erff(x * 0.70710678118654752f));
}

// C8 = exp(-2*pi*i*512/8192) = exp(-i*pi/8): per-512 increment of the
// length-8192 half-twiddle chain
#define C8X 0.92387953251128675613f
#define C8Y (-0.38268343236508977173f)

// ---------------- Kernel A: filter spectra --------------------------------
__global__ __launch_bounds__(512, 2)
void kfft_kernel(const float* __restrict__ k){
    extern __shared__ float2 sm[];
    const int tid = threadIdx.x;
    const int hp  = blockIdx.x;
    const int h1  = 2*hp, h2 = h1 + 1;
    const float* k1 = k + (size_t)h1 * 4096;
    const float* k2 = k + (size_t)h2 * 4096;

    Tw tw = make_tw(tid);
    const float2 C8 = make_float2(C8X, C8Y);

    // fused load + radix-2 (zero-padded top half): E=x, O=x*w8192^l
    float2 w = tw.wC;
    #pragma unroll
    for (int it = 0; it < 8; ++it){
        int l = tid + it * 512;
        float2 v = make_float2(k1[l], k2[l]);
        sm[SPAD(l)] = v;
        sm[SPAD(l + 4096)] = cmul(v, w);
        w = cmul(w, C8);
    }
    __syncthreads();

    r4_stage4096<false>(sm, tid, tw.wA);
    r4_stage<1024,false>(sm, tid, tw.w1024);
    r4_stage<256, false>(sm, tid, tw.w256);
    r4_stage<64,  false>(sm, tid, tw.wB);
    stage_16_4<false>(sm, tid);

    const float sc = 0.5f / 8192.0f;
    #pragma unroll 1
    for (int j = tid; j <= 4096; j += 512){
        int rj = SPAD(posf(j));
        int rn = SPAD(posf((8192 - j) & 8191));
        float2 Zj = sm[rj], Zn = sm[rn];
        d_Kf[(size_t)h1 * 4097 + j] = make_float2(sc*(Zj.x + Zn.x), sc*(Zj.y - Zn.y));
        d_Kf[(size_t)h2 * 4097 + j] = make_float2(sc*(Zj.y + Zn.y), sc*(Zn.x - Zj.x));
    }
}

// ---------------- Kernel B: conv + skip + gelu -----------------------------
__global__ __launch_bounds__(512, 2)
void conv_kernel(const float* __restrict__ u, const float* __restrict__ D){
    extern __shared__ float2 sm[];
    const int tid = threadIdx.x;
    const int hp  = blockIdx.x;
    const int b   = blockIdx.y;
    const int h1  = 2*hp, h2 = h1 + 1;
    const float* u1 = u + ((size_t)b * 512 + h1) * 4096;
    const float* u2 = u1 + 4096;

    Tw tw = make_tw(tid);
    const float2 C8 = make_float2(C8X, C8Y);

    // fused load + radix-2
    float2 w = tw.wC;
    #pragma unroll
    for (int it = 0; it < 8; ++it){
        int l = tid + it * 512;
        float2 v = make_float2(u1[l], u2[l]);
        sm[SPAD(l)] = v;
        sm[SPAD(l + 4096)] = cmul(v, w);
        w = cmul(w, C8);
    }
    __syncthreads();

    r4_stage4096<false>(sm, tid, tw.wA);
    r4_stage<1024,false>(sm, tid, tw.w1024);
    r4_stage<256, false>(sm, tid, tw.w256);
    r4_stage<64,  false>(sm, tid, tw.wB);
    stage_16_4<false>(sm, tid);

    // pointwise: unpack two real spectra, multiply, repack (permuted domain)
    const float2* K1 = d_Kf + (size_t)h1 * 4097;
    const float2* K2 = d_Kf + (size_t)h2 * 4097;
    #pragma unroll 1
    for (int j = tid; j <= 4096; j += 512){
        int rj = SPAD(posf(j));
        int rn = SPAD(posf((8192 - j) & 8191));
        float2 Zj = sm[rj], Zn = sm[rn];
        float2 U1 = make_float2(0.5f*(Zj.x + Zn.x), 0.5f*(Zj.y - Zn.y));
        float2 U2 = make_float2(0.5f*(Zj.y + Zn.y), 0.5f*(Zn.x - Zj.x));
        float2 Y1 = cmul(U1, K1[j]);
        float2 Y2 = cmul(U2, K2[j]);
        sm[rj] = make_float2(Y1.x - Y2.y, Y1.y + Y2.x);   // W(j)   = Y1 + i*Y2
        sm[rn] = make_float2(Y1.x + Y2.y, Y2.x - Y1.y);   // W(N-j) = conj(Y1 - i*Y2)
    }
    __syncthreads();

    stage_16_4<true>(sm, tid);
    r4_stage<64,  true>(sm, tid, tw.wB);
    r4_stage<256, true>(sm, tid, tw.w256);
    r4_stage<1024,true>(sm, tid, tw.w1024);
    r4_stage4096<true>(sm, tid, tw.wA);

    // fused final radix-2 (only first 4096 outputs) + skip + gelu + store
    const float dA = D[h1], dB = D[h2];
    float* g1 = d_g + ((size_t)b * 512 + h1) * 4096;
    float* g2 = g1 + 4096;
    w = tw.wC;
    #pragma unroll
    for (int it = 0; it < 8; ++it){
        int l = tid + it * 512;
        float2 E = sm[SPAD(l)], O = sm[SPAD(l + 4096)];
        float2 y = cadd(E, cmul(O, conjf2(w)));
        g1[l] = gelu_erf(y.x + dA * u1[l]);
        g2[l] = gelu_erf(y.y + dB * u2[l]);
        w = cmul(w, C8);
    }
}

// ---------------- packed f32x2 helpers (Blackwell FFMA2) -------------------
typedef unsigned long long u64t;

__device__ __forceinline__ u64t pack2dup(float x){
    u64t r;
    unsigned xi = __float_as_uint(x);
    asm("mov.b64 %0, {%1, %1};" : "=l"(r) : "r"(xi));
    return r;
}
__device__ __forceinline__ void fma2(u64t& d, u64t a, u64t b, u64t c){
    asm("fma.rn.f32x2 %0, %1, %2, %3;" : "=l"(d) : "l"(a), "l"(b), "l"(c));
}
__device__ __forceinline__ float2 unpack2(u64t v){
    unsigned lo, hi;
    asm("mov.b64 {%0, %1}, %2;" : "=r"(lo), "=r"(hi) : "l"(v));
    return make_float2(__uint_as_float(lo), __uint_as_float(hi));
}

// ---------------- Kernel C: pointwise linear (f32x2 SGEMM) -----------------
// out[b,d,l] = sum_h W[d,h] * g[b,h,l] + bias[d]
// 128x128 tile, BK=8, 256 threads, 8x8 microtile; columns processed as
// packed f32x2 pairs via FFMA2 (2 fp32 FMA per fma-pipe issue).
__global__ __launch_bounds__(256, 2)
void gemm_kernel(const float* __restrict__ W, const float* __restrict__ bias,
                 float* __restrict__ out){
    __shared__ float Ws[8][132];
    __shared__ float Gs[8][132];

    const int bb = blockIdx.z;
    const int d0 = blockIdx.y * 128;
    const int l0 = blockIdx.x * 128;
    const int t  = threadIdx.x;
    const int tx = t & 15, ty = t >> 4;

    const float* gbase = d_g + (size_t)bb * 512 * 4096;

    // acc2[i][jp]: packed pair of output columns (2*jp, 2*jp+1) within the
    // thread's 8-column slice {tx*4..tx*4+3, 64+tx*4..64+tx*4+3}
    u64t acc2[8][4];
    #pragma unroll
    for (int i = 0; i < 8; ++i)
        #pragma unroll
        for (int j = 0; j < 4; ++j) acc2[i][j] = 0ull;

    const int wrow = t >> 1;
    const int wcol = (t & 1) * 4;
    const int grow = t >> 5;
    const int gcol = (t & 31) * 4;

    #pragma unroll 1
    for (int kk = 0; kk < 512; kk += 8){
        float4 wv = *(const float4*)&W[(size_t)(d0 + wrow) * 512 + kk + wcol];
        float4 gv = *(const float4*)&gbase[(size_t)(kk + grow) * 4096 + l0 + gcol];
        __syncthreads();
        Ws[wcol + 0][wrow] = wv.x;
        Ws[wcol + 1][wrow] = wv.y;
        Ws[wcol + 2][wrow] = wv.z;
        Ws[wcol + 3][wrow] = wv.w;
        *(float4*)&Gs[grow][gcol] = gv;
        __syncthreads();
        #pragma unroll
        for (int k = 0; k < 8; ++k){
            float a[8];
            *(float4*)&a[0] = *(const float4*)&Ws[k][ty * 4];
            *(float4*)&a[4] = *(const float4*)&Ws[k][64 + ty * 4];
            // B pairs come pre-packed: contiguous floats reinterpreted as f32x2
            ulonglong2 b01 = *(const ulonglong2*)&Gs[k][tx * 4];
            ulonglong2 b23 = *(const ulonglong2*)&Gs[k][64 + tx * 4];
            u64t bp0 = b01.x, bp1 = b01.y, bp2 = b23.x, bp3 = b23.y;
            #pragma unroll
            for (int i = 0; i < 8; ++i){
                u64t ap = pack2dup(a[i]);
                fma2(acc2[i][0], ap, bp0, acc2[i][0]);
                fma2(acc2[i][1], ap, bp1, acc2[i][1]);
                fma2(acc2[i][2], ap, bp2, acc2[i][2]);
                fma2(acc2[i][3], ap, bp3, acc2[i][3]);
            }
        }
    }

    #pragma unroll
    for (int ih = 0; ih < 2; ++ih){
        #pragma unroll
        for (int i = 0; i < 4; ++i){
            int d = d0 + ih * 64 + ty * 4 + i;
            float bvl = bias[d];
            float* orow = out + ((size_t)bb * 512 + d) * 4096 + l0;
            #pragma unroll
            for (int jh = 0; jh < 2; ++jh){
                float2 p0 = unpack2(acc2[ih * 4 + i][jh * 2 + 0]);
                float2 p1 = unpack2(acc2[ih * 4 + i][jh * 2 + 1]);
                float4 o;
                o.x = p0.x + bvl;
                o.y = p0.y + bvl;
                o.z = p1.x + bvl;
                o.w = p1.y + bvl;
                *(float4*)&orow[jh * 64 + tx * 4] = o;
            }
        }
    }
}

// ---------------- Launch ---------------------------------------------------
extern "C" void kernel_launch(void* const* d_in, const int* in_sizes, int n_in,
                              void* d_out, int out_size){
    const float* u    = (const float*)d_in[0];   // (8, 512, 4096)
    const float* k    = (const float*)d_in[1];   // (1, 512, 4096)
    const float* D    = (const float*)d_in[2];   // (1, 512)
    const float* W    = (const float*)d_in[3];   // (512, 512)
    const float* bias = (const float*)d_in[4];   // (512,)
    float* out = (float*)d_out;                  // (8, 512, 4096)

    const size_t smem = 8704 * sizeof(float2);   // 68 KB (padded)
    cudaFuncSetAttribute(kfft_kernel, cudaFuncAttributeMaxDynamicSharedMemorySize, (int)smem);
    cudaFuncSetAttribute(conv_kernel, cudaFuncAttributeMaxDynamicSharedMemorySize, (int)smem);

    kfft_kernel<<<256, 512, smem>>>(k);
    conv_kernel<<<dim3(256, 8), 512, smem>>>(u, D);
    gemm_kernel<<<dim3(4096 / 128, 512 / 128, 8), 256>>>(W, bias, out);
}

// round 7
// speedup vs baseline: 1.4195x; 1.0238x over previous
#include <cuda_runtime.h>
#include <math.h>

#define PI_F 3.14159265358979323846f

// Scratch (allocation-free rule: __device__ globals)
__device__ float2 d_Kf[512 * 4097];          // filter half-spectra, pre-scaled by 1/8192
__device__ float  d_g[8ULL * 512 * 4096];    // gelu(conv + skip), fp32

// ---------------- complex helpers ----------------------------------------
__device__ __forceinline__ float2 cadd(float2 a, float2 b){ return make_float2(a.x+b.x, a.y+b.y); }
__device__ __forceinline__ float2 csub(float2 a, float2 b){ return make_float2(a.x-b.x, a.y-b.y); }
__device__ __forceinline__ float2 cmul(float2 a, float2 b){
    return make_float2(fmaf(a.x, b.x, -a.y*b.y), fmaf(a.x, b.y, a.y*b.x));
}
__device__ __forceinline__ float2 csqr(float2 a){
    return make_float2(fmaf(a.x,a.x,-a.y*a.y), 2.f*a.x*a.y);
}
__device__ __forceinline__ float2 conjf2(float2 a){ return make_float2(a.x, -a.y); }
__device__ __forceinline__ float2 mi_neg(float2 a){ return make_float2(a.y, -a.x); }  // -i*a
__device__ __forceinline__ float2 mi_pos(float2 a){ return make_float2(-a.y, a.x); }  // +i*a

// radix-4 butterflies (in-place on a,b,c,d = y0..y3 slots)
__device__ __forceinline__ void bf4_fwd(float2&a, float2&b, float2&c, float2&d,
                                        float2 w1, float2 w2, float2 w3){
    float2 t0=cadd(a,c), t1=csub(a,c), t2=cadd(b,d), t3=mi_neg(csub(b,d));
    a = cadd(t0,t2);
    b = cmul(cadd(t1,t3), w1);
    c = cmul(csub(t0,t2), w2);
    d = cmul(csub(t1,t3), w3);
}
__device__ __forceinline__ void bf4_inv(float2&a, float2&b, float2&c, float2&d,
                                        float2 w1c, float2 w2c, float2 w3c){
    float2 z1=cmul(b,w1c), z2=cmul(c,w2c), z3=cmul(d,w3c);
    float2 A=cadd(a,z2), B=csub(a,z2), Cc=cadd(z1,z3), Dd=csub(z1,z3);
    float2 iD = mi_pos(Dd);
    a = cadd(A,Cc); c = csub(A,Cc);
    b = cadd(B,iD); d = csub(B,iD);
}

// smem padding: 1 float2 pad per 16 elements -> conflict-free stage strides
#define SPAD(i) ((i) + ((i) >> 4))

// position of frequency j in the permuted output of [r2, r4 x6] DIF
__device__ __forceinline__ int posf(int j){
    int j0 = j & 1, jp = j >> 1;                 // 12-bit jp
    int y = __brev((unsigned)jp) >> 20;          // bit-reverse 12 bits
    int z = ((y & 0x555) << 1) | ((y >> 1) & 0x555);  // swap adjacent bits -> base-4 digit reversal
    return (j0 << 12) + z;
}

// w16 = exp(-i*pi/8) components (forward sense)
#define C8X 0.92387953251128675613f
#define C8Y (-0.38268343236508977173f)

// ---------------- merged radix-16 smem stage -------------------------------
// Covers two consecutive radix-4 DIF stages of sizes (M, M/4) within each
// length-4096 half. Each thread owns one radix-16 butterfly: 16 elements at
// stride S = M/16. Layer 1 (stride 4 in j) = size-M radix-4 with twiddles
// w_M^{q + jm*S} = w_M^q * w16^jm; layer 2 (stride 1) = size-M/4 radix-4 with
// w_{M/4}^q = (w_M^q)^4. Inverse runs the layers mirrored with conj twiddles.
// Stride is a multiple of 16 so SPAD is linear: SPAD(base+j*S)=SPAD(base)+j*SP.
template<int M, bool INV>
__device__ __forceinline__ void stage16big(float2* __restrict__ sm, int tid){
    const int S  = M >> 4;
    const int SP = S + (S >> 4);
    const int half = tid >> 8;
    const int rem  = tid & 255;
    const int g = (M == 4096) ? 0   : (rem >> 4);
    const int q = (M == 4096) ? rem : (rem & 15);
    const int base = half * 4096 + g * M + q;
    const int pb = SPAD(base);

    float2 r[16];
    #pragma unroll
    for (int j = 0; j < 16; ++j) r[j] = sm[pb + j * SP];

    float sn, cs;
    __sincosf(-PI_F * (float)q * (2.0f / (float)M), &sn, &cs);
    float2 w1 = make_float2(cs, INV ? -sn : sn);            // w_M^q (conj for INV)
    const float2 wst = make_float2(C8X, INV ? -C8Y : C8Y);  // w16 step (conj for INV)

    float2 v1 = csqr(csqr(w1));          // w_{M/4}^q, exact 4th power
    float2 v2 = csqr(v1), v3 = cmul(v1, v2);

    if (!INV){
        float2 t1 = w1;
        #pragma unroll
        for (int jm = 0; jm < 4; ++jm){
            float2 t2 = csqr(t1), t3 = cmul(t1, t2);
            bf4_fwd(r[jm], r[jm+4], r[jm+8], r[jm+12], t1, t2, t3);
            t1 = cmul(t1, wst);
        }
        #pragma unroll
        for (int rr = 0; rr < 4; ++rr)
            bf4_fwd(r[4*rr], r[4*rr+1], r[4*rr+2], r[4*rr+3], v1, v2, v3);
    } else {
        #pragma unroll
        for (int rr = 0; rr < 4; ++rr)
            bf4_inv(r[4*rr], r[4*rr+1], r[4*rr+2], r[4*rr+3], v1, v2, v3);
        float2 t1 = w1;
        #pragma unroll
        for (int jm = 0; jm < 4; ++jm){
            float2 t2 = csqr(t1), t3 = cmul(t1, t2);
            bf4_inv(r[jm], r[jm+4], r[jm+8], r[jm+12], t1, t2, t3);
            t1 = cmul(t1, wst);
        }
    }
    #pragma unroll
    for (int j = 0; j < 16; ++j) sm[pb + j * SP] = r[j];
    __syncthreads();
}

// merged M=16 + M=4 stages in registers (one contiguous 16-block per thread)
template<bool INV>
__device__ __forceinline__ void stage_16_4(float2* __restrict__ sm, int tid){
    const int pb = tid * 17;   // SPAD(16*tid)
    float2 r[16];
    #pragma unroll
    for (int i = 0; i < 16; ++i) r[i] = sm[pb + i];

    const float CP8 = 0.92387953251128675613f;  // cos(pi/8)
    const float SP8 = 0.38268343236508977173f;  // sin(pi/8)
    const float R2  = 0.70710678118654752440f;
    const float C3  = 0.38268343236508977173f;  // cos(3pi/8)
    const float S3v = 0.92387953251128675613f;  // sin(3pi/8)
    const float sg = INV ? 1.f : -1.f;
    float2 W1[4] = { make_float2(1,0), make_float2(CP8, sg*SP8), make_float2(R2, sg*R2),   make_float2(C3, sg*S3v) };
    float2 W2[4] = { make_float2(1,0), make_float2(R2, sg*R2),   make_float2(0.f, sg),     make_float2(-R2, sg*R2) };
    float2 W3[4] = { make_float2(1,0), make_float2(C3, sg*S3v),  make_float2(-R2, sg*R2),  make_float2(-CP8, -sg*SP8) };

    if (!INV){
        #pragma unroll
        for (int q = 0; q < 4; ++q)
            bf4_fwd(r[q], r[q+4], r[q+8], r[q+12], W1[q], W2[q], W3[q]);
        #pragma unroll
        for (int g = 0; g < 4; ++g){
            float2 a=r[4*g], b=r[4*g+1], c=r[4*g+2], d=r[4*g+3];
            float2 t0=cadd(a,c), t1=csub(a,c), t2=cadd(b,d), t3=mi_neg(csub(b,d));
            r[4*g]=cadd(t0,t2); r[4*g+1]=cadd(t1,t3); r[4*g+2]=csub(t0,t2); r[4*g+3]=csub(t1,t3);
        }
    } else {
        #pragma unroll
        for (int g = 0; g < 4; ++g){
            float2 y0=r[4*g], y1=r[4*g+1], y2=r[4*g+2], y3=r[4*g+3];
            float2 A=cadd(y0,y2), B=csub(y0,y2), Cc=cadd(y1,y3), Dd=csub(y1,y3);
            float2 iD=mi_pos(Dd);
            r[4*g]=cadd(A,Cc); r[4*g+2]=csub(A,Cc);
            r[4*g+1]=cadd(B,iD); r[4*g+3]=csub(B,iD);
        }
        #pragma unroll
        for (int q = 0; q < 4; ++q)
            bf4_inv(r[q], r[q+4], r[q+8], r[q+12], W1[q], W2[q], W3[q]);
    }
    #pragma unroll
    for (int i = 0; i < 16; ++i) sm[pb + i] = r[i];
    __syncthreads();
}

__device__ __forceinline__ float gelu_erf(float x){
    return 0.5f * x * (1.0f + erff(x * 0.70710678118654752f));
}

// ---------------- Kernel A: filter spectra --------------------------------
__global__ __launch_bounds__(512, 2)
void kfft_kernel(const float* __restrict__ k){
    extern __shared__ float2 sm[];
    const int tid = threadIdx.x;
    const int hp  = blockIdx.x;
    const int h1  = 2*hp, h2 = h1 + 1;
    const float* k1 = k + (size_t)h1 * 4096;
    const float* k2 = k + (size_t)h2 * 4096;

    float sn, cs;
    __sincosf(-PI_F * (float)tid * (1.0f/4096.0f), &sn, &cs);
    float2 wC = make_float2(cs, sn);                 // e^{-2pi i tid/8192}
    const float2 C8 = make_float2(C8X, C8Y);

    // fused load + radix-2 (zero-padded top half): E=x, O=x*w8192^l
    float2 w = wC;
    #pragma unroll
    for (int it = 0; it < 8; ++it){
        int l = tid + it * 512;
        float2 v = make_float2(k1[l], k2[l]);
        sm[SPAD(l)] = v;
        sm[SPAD(l + 4096)] = cmul(v, w);
        w = cmul(w, C8);
    }
    __syncthreads();

    stage16big<4096,false>(sm, tid);
    stage16big<256, false>(sm, tid);
    stage_16_4<false>(sm, tid);

    const float sc = 0.5f / 8192.0f;
    #pragma unroll 1
    for (int j = tid; j <= 4096; j += 512){
        int rj = SPAD(posf(j));
        int rn = SPAD(posf((8192 - j) & 8191));
        float2 Zj = sm[rj], Zn = sm[rn];
        d_Kf[(size_t)h1 * 4097 + j] = make_float2(sc*(Zj.x + Zn.x), sc*(Zj.y - Zn.y));
        d_Kf[(size_t)h2 * 4097 + j] = make_float2(sc*(Zj.y + Zn.y), sc*(Zn.x - Zj.x));
    }
}

// ---------------- Kernel B: conv + skip + gelu -----------------------------
__global__ __launch_bounds__(512, 2)
void conv_kernel(const float* __restrict__ u, const float* __restrict__ D){
    extern __shared__ float2 sm[];
    const int tid = threadIdx.x;
    const int hp  = blockIdx.x;
    const int b   = blockIdx.y;
    const int h1  = 2*hp, h2 = h1 + 1;
    const float* u1 = u + ((size_t)b * 512 + h1) * 4096;
    const float* u2 = u1 + 4096;

    float sn, cs;
    __sincosf(-PI_F * (float)tid * (1.0f/4096.0f), &sn, &cs);
    float2 wC = make_float2(cs, sn);
    const float2 C8 = make_float2(C8X, C8Y);

    // fused load + radix-2
    float2 w = wC;
    #pragma unroll
    for (int it = 0; it < 8; ++it){
        int l = tid + it * 512;
        float2 v = make_float2(u1[l], u2[l]);
        sm[SPAD(l)] = v;
        sm[SPAD(l + 4096)] = cmul(v, w);
        w = cmul(w, C8);
    }
    __syncthreads();

    stage16big<4096,false>(sm, tid);
    stage16big<256, false>(sm, tid);
    stage_16_4<false>(sm, tid);

    // pointwise: unpack two real spectra, multiply, repack (permuted domain)
    const float2* K1 = d_Kf + (size_t)h1 * 4097;
    const float2* K2 = d_Kf + (size_t)h2 * 4097;
    #pragma unroll 1
    for (int j = tid; j <= 4096; j += 512){
        int rj = SPAD(posf(j));
        int rn = SPAD(posf((8192 - j) & 8191));
        float2 Zj = sm[rj], Zn = sm[rn];
        float2 U1 = make_float2(0.5f*(Zj.x + Zn.x), 0.5f*(Zj.y - Zn.y));
        float2 U2 = make_float2(0.5f*(Zj.y + Zn.y), 0.5f*(Zn.x - Zj.x));
        float2 Y1 = cmul(U1, K1[j]);
        float2 Y2 = cmul(U2, K2[j]);
        sm[rj] = make_float2(Y1.x - Y2.y, Y1.y + Y2.x);   // W(j)   = Y1 + i*Y2
        sm[rn] = make_float2(Y1.x + Y2.y, Y2.x - Y1.y);   // W(N-j) = conj(Y1 - i*Y2)
    }
    __syncthreads();

    stage_16_4<true>(sm, tid);
    stage16big<256, true>(sm, tid);
    stage16big<4096,true>(sm, tid);

    // fused final radix-2 (only first 4096 outputs) + skip + gelu + store
    const float dA = D[h1], dB = D[h2];
    float* g1 = d_g + ((size_t)b * 512 + h1) * 4096;
    float* g2 = g1 + 4096;
    w = wC;
    #pragma unroll
    for (int it = 0; it < 8; ++it){
        int l = tid + it * 512;
        float2 E = sm[SPAD(l)], O = sm[SPAD(l + 4096)];
        float2 y = cadd(E, cmul(O, conjf2(w)));
        g1[l] = gelu_erf(y.x + dA * u1[l]);
        g2[l] = gelu_erf(y.y + dB * u2[l]);
        w = cmul(w, C8);
    }
}

// ---------------- packed f32x2 helpers (Blackwell FFMA2) -------------------
typedef unsigned long long u64t;

__device__ __forceinline__ u64t pack2dup(float x){
    u64t r;
    unsigned xi = __float_as_uint(x);
    asm("mov.b64 %0, {%1, %1};" : "=l"(r) : "r"(xi));
    return r;
}
__device__ __forceinline__ void fma2(u64t& d, u64t a, u64t b, u64t c){
    asm("fma.rn.f32x2 %0, %1, %2, %3;" : "=l"(d) : "l"(a), "l"(b), "l"(c));
}
__device__ __forceinline__ float2 unpack2(u64t v){
    unsigned lo, hi;
    asm("mov.b64 {%0, %1}, %2;" : "=r"(lo), "=r"(hi) : "l"(v));
    return make_float2(__uint_as_float(lo), __uint_as_float(hi));
}

// ---------------- Kernel C: pointwise linear (f32x2 SGEMM) -----------------
__global__ __launch_bounds__(256, 2)
void gemm_kernel(const float* __restrict__ W, const float* __restrict__ bias,
                 float* __restrict__ out){
    __shared__ float Ws[8][132];
    __shared__ float Gs[8][132];

    const int bb = blockIdx.z;
    const int d0 = blockIdx.y * 128;
    const int l0 = blockIdx.x * 128;
    const int t  = threadIdx.x;
    const int tx = t & 15, ty = t >> 4;

    const float* gbase = d_g + (size_t)bb * 512 * 4096;

    u64t acc2[8][4];
    #pragma unroll
    for (int i = 0; i < 8; ++i)
        #pragma unroll
        for (int j = 0; j < 4; ++j) acc2[i][j] = 0ull;

    const int wrow = t >> 1;
    const int wcol = (t & 1) * 4;
    const int grow = t >> 5;
    const int gcol = (t & 31) * 4;

    #pragma unroll 1
    for (int kk = 0; kk < 512; kk += 8){
        float4 wv = *(const float4*)&W[(size_t)(d0 + wrow) * 512 + kk + wcol];
        float4 gv = *(const float4*)&gbase[(size_t)(kk + grow) * 4096 + l0 + gcol];
        __syncthreads();
        Ws[wcol + 0][wrow] = wv.x;
        Ws[wcol + 1][wrow] = wv.y;
        Ws[wcol + 2][wrow] = wv.z;
        Ws[wcol + 3][wrow] = wv.w;
        *(float4*)&Gs[grow][gcol] = gv;
        __syncthreads();
        #pragma unroll
        for (int k = 0; k < 8; ++k){
            float a[8];
            *(float4*)&a[0] = *(const float4*)&Ws[k][ty * 4];
            *(float4*)&a[4] = *(const float4*)&Ws[k][64 + ty * 4];
            ulonglong2 b01 = *(const ulonglong2*)&Gs[k][tx * 4];
            ulonglong2 b23 = *(const ulonglong2*)&Gs[k][64 + tx * 4];
            u64t bp0 = b01.x, bp1 = b01.y, bp2 = b23.x, bp3 = b23.y;
            #pragma unroll
            for (int i = 0; i < 8; ++i){
                u64t ap = pack2dup(a[i]);
                fma2(acc2[i][0], ap, bp0, acc2[i][0]);
                fma2(acc2[i][1], ap, bp1, acc2[i][1]);
                fma2(acc2[i][2], ap, bp2, acc2[i][2]);
                fma2(acc2[i][3], ap, bp3, acc2[i][3]);
            }
        }
    }

    #pragma unroll
    for (int ih = 0; ih < 2; ++ih){
        #pragma unroll
        for (int i = 0; i < 4; ++i){
            int d = d0 + ih * 64 + ty * 4 + i;
            float bvl = bias[d];
            float* orow = out + ((size_t)bb * 512 + d) * 4096 + l0;
            #pragma unroll
            for (int jh = 0; jh < 2; ++jh){
                float2 p0 = unpack2(acc2[ih * 4 + i][jh * 2 + 0]);
                float2 p1 = unpack2(acc2[ih * 4 + i][jh * 2 + 1]);
                float4 o;
                o.x = p0.x + bvl;
                o.y = p0.y + bvl;
                o.z = p1.x + bvl;
                o.w = p1.y + bvl;
                *(float4*)&orow[jh * 64 + tx * 4] = o;
            }
        }
    }
}

// ---------------- Launch ---------------------------------------------------
extern "C" void kernel_launch(void* const* d_in, const int* in_sizes, int n_in,
                              void* d_out, int out_size){
    const float* u    = (const float*)d_in[0];   // (8, 512, 4096)
    const float* k    = (const float*)d_in[1];   // (1, 512, 4096)
    const float* D    = (const float*)d_in[2];   // (1, 512)
    const float* W    = (const float*)d_in[3];   // (512, 512)
    const float* bias = (const float*)d_in[4];   // (512,)
    float* out = (float*)d_out;                  // (8, 512, 4096)

    const size_t smem = 8704 * sizeof(float2);   // 68 KB (padded)
    cudaFuncSetAttribute(kfft_kernel, cudaFuncAttributeMaxDynamicSharedMemorySize, (int)smem);
    cudaFuncSetAttribute(conv_kernel, cudaFuncAttributeMaxDynamicSharedMemorySize, (int)smem);

    kfft_kernel<<<256, 512, smem>>>(k);
    conv_kernel<<<dim3(256, 8), 512, smem>>>(u, D);
    gemm_kernel<<<dim3(4096 / 128, 512 / 128, 8), 256>>>(W, bias, out);
}

// round 8
// speedup vs baseline: 1.4223x; 1.0020x over previous
#include <cuda_runtime.h>
#include <math.h>

#define PI_F 3.14159265358979323846f

// Scratch (allocation-free rule: __device__ globals)
__device__ float2 d_Kf[512 * 4097];          // filter half-spectra, pre-scaled by 1/8192
__device__ float  d_g[8ULL * 512 * 4096];    // gelu(conv + skip), fp32

// ---------------- complex helpers ----------------------------------------
__device__ __forceinline__ float2 cadd(float2 a, float2 b){ return make_float2(a.x+b.x, a.y+b.y); }
__device__ __forceinline__ float2 csub(float2 a, float2 b){ return make_float2(a.x-b.x, a.y-b.y); }
__device__ __forceinline__ float2 cmul(float2 a, float2 b){
    return make_float2(fmaf(a.x, b.x, -a.y*b.y), fmaf(a.x, b.y, a.y*b.x));
}
__device__ __forceinline__ float2 csqr(float2 a){
    return make_float2(fmaf(a.x,a.x,-a.y*a.y), 2.f*a.x*a.y);
}
__device__ __forceinline__ float2 conjf2(float2 a){ return make_float2(a.x, -a.y); }
__device__ __forceinline__ float2 mi_neg(float2 a){ return make_float2(a.y, -a.x); }  // -i*a
__device__ __forceinline__ float2 mi_pos(float2 a){ return make_float2(-a.y, a.x); }  // +i*a

// radix-4 butterflies (in-place on a,b,c,d = y0..y3 slots)
__device__ __forceinline__ void bf4_fwd(float2&a, float2&b, float2&c, float2&d,
                                        float2 w1, float2 w2, float2 w3){
    float2 t0=cadd(a,c), t1=csub(a,c), t2=cadd(b,d), t3=mi_neg(csub(b,d));
    a = cadd(t0,t2);
    b = cmul(cadd(t1,t3), w1);
    c = cmul(csub(t0,t2), w2);
    d = cmul(csub(t1,t3), w3);
}
__device__ __forceinline__ void bf4_inv(float2&a, float2&b, float2&c, float2&d,
                                        float2 w1c, float2 w2c, float2 w3c){
    float2 z1=cmul(b,w1c), z2=cmul(c,w2c), z3=cmul(d,w3c);
    float2 A=cadd(a,z2), B=csub(a,z2), Cc=cadd(z1,z3), Dd=csub(z1,z3);
    float2 iD = mi_pos(Dd);
    a = cadd(A,Cc); c = csub(A,Cc);
    b = cadd(B,iD); d = csub(B,iD);
}

// smem padding: 1 float2 pad per 16 elements -> conflict-free stage strides
#define SPAD(i) ((i) + ((i) >> 4))

// position of frequency j in the permuted output of [r2, r4 x6] DIF
__device__ __forceinline__ int posf(int j){
    int j0 = j & 1, jp = j >> 1;                 // 12-bit jp
    int y = __brev((unsigned)jp) >> 20;          // bit-reverse 12 bits
    int z = ((y & 0x555) << 1) | ((y >> 1) & 0x555);  // swap adjacent bits -> base-4 digit reversal
    return (j0 << 12) + z;
}

// w16 = exp(-i*pi/8) components (forward sense)
#define C8X 0.92387953251128675613f
#define C8Y (-0.38268343236508977173f)

// ---------------- merged radix-16 smem stage -------------------------------
// Covers two consecutive radix-4 DIF stages of sizes (M, M/4) within each
// length-4096 half. Each thread owns one radix-16 butterfly: 16 elements at
// stride S = M/16. Layer 1 (stride 4 in j) = size-M radix-4 with twiddles
// w_M^{q + jm*S} = w_M^q * w16^jm; layer 2 (stride 1) = size-M/4 radix-4 with
// w_{M/4}^q = (w_M^q)^4. Inverse runs the layers mirrored with conj twiddles.
// Stride is a multiple of 16 so SPAD is linear: SPAD(base+j*S)=SPAD(base)+j*SP.
template<int M, bool INV>
__device__ __forceinline__ void stage16big(float2* __restrict__ sm, int tid){
    const int S  = M >> 4;
    const int SP = S + (S >> 4);
    const int half = tid >> 8;
    const int rem  = tid & 255;
    const int g = (M == 4096) ? 0   : (rem >> 4);
    const int q = (M == 4096) ? rem : (rem & 15);
    const int base = half * 4096 + g * M + q;
    const int pb = SPAD(base);

    float2 r[16];
    #pragma unroll
    for (int j = 0; j < 16; ++j) r[j] = sm[pb + j * SP];

    float sn, cs;
    __sincosf(-PI_F * (float)q * (2.0f / (float)M), &sn, &cs);
    float2 w1 = make_float2(cs, INV ? -sn : sn);            // w_M^q (conj for INV)
    const float2 wst = make_float2(C8X, INV ? -C8Y : C8Y);  // w16 step (conj for INV)

    float2 v1 = csqr(csqr(w1));          // w_{M/4}^q, exact 4th power
    float2 v2 = csqr(v1), v3 = cmul(v1, v2);

    if (!INV){
        float2 t1 = w1;
        #pragma unroll
        for (int jm = 0; jm < 4; ++jm){
            float2 t2 = csqr(t1), t3 = cmul(t1, t2);
            bf4_fwd(r[jm], r[jm+4], r[jm+8], r[jm+12], t1, t2, t3);
            t1 = cmul(t1, wst);
        }
        #pragma unroll
        for (int rr = 0; rr < 4; ++rr)
            bf4_fwd(r[4*rr], r[4*rr+1], r[4*rr+2], r[4*rr+3], v1, v2, v3);
    } else {
        #pragma unroll
        for (int rr = 0; rr < 4; ++rr)
            bf4_inv(r[4*rr], r[4*rr+1], r[4*rr+2], r[4*rr+3], v1, v2, v3);
        float2 t1 = w1;
        #pragma unroll
        for (int jm = 0; jm < 4; ++jm){
            float2 t2 = csqr(t1), t3 = cmul(t1, t2);
            bf4_inv(r[jm], r[jm+4], r[jm+8], r[jm+12], t1, t2, t3);
            t1 = cmul(t1, wst);
        }
    }
    #pragma unroll
    for (int j = 0; j < 16; ++j) sm[pb + j * SP] = r[j];
    __syncthreads();
}

// merged M=16 + M=4 stages in registers (one contiguous 16-block per thread)
template<bool INV>
__device__ __forceinline__ void stage_16_4(float2* __restrict__ sm, int tid){
    const int pb = tid * 17;   // SPAD(16*tid)
    float2 r[16];
    #pragma unroll
    for (int i = 0; i < 16; ++i) r[i] = sm[pb + i];

    const float CP8 = 0.92387953251128675613f;  // cos(pi/8)
    const float SP8 = 0.38268343236508977173f;  // sin(pi/8)
    const float R2  = 0.70710678118654752440f;
    const float C3  = 0.38268343236508977173f;  // cos(3pi/8)
    const float S3v = 0.92387953251128675613f;  // sin(3pi/8)
    const float sg = INV ? 1.f : -1.f;
    float2 W1[4] = { make_float2(1,0), make_float2(CP8, sg*SP8), make_float2(R2, sg*R2),   make_float2(C3, sg*S3v) };
    float2 W2[4] = { make_float2(1,0), make_float2(R2, sg*R2),   make_float2(0.f, sg),     make_float2(-R2, sg*R2) };
    float2 W3[4] = { make_float2(1,0), make_float2(C3, sg*S3v),  make_float2(-R2, sg*R2),  make_float2(-CP8, -sg*SP8) };

    if (!INV){
        #pragma unroll
        for (int q = 0; q < 4; ++q)
            bf4_fwd(r[q], r[q+4], r[q+8], r[q+12], W1[q], W2[q], W3[q]);
        #pragma unroll
        for (int g = 0; g < 4; ++g){
            float2 a=r[4*g], b=r[4*g+1], c=r[4*g+2], d=r[4*g+3];
            float2 t0=cadd(a,c), t1=csub(a,c), t2=cadd(b,d), t3=mi_neg(csub(b,d));
            r[4*g]=cadd(t0,t2); r[4*g+1]=cadd(t1,t3); r[4*g+2]=csub(t0,t2); r[4*g+3]=csub(t1,t3);
        }
    } else {
        #pragma unroll
        for (int g = 0; g < 4; ++g){
            float2 y0=r[4*g], y1=r[4*g+1], y2=r[4*g+2], y3=r[4*g+3];
            float2 A=cadd(y0,y2), B=csub(y0,y2), Cc=cadd(y1,y3), Dd=csub(y1,y3);
            float2 iD=mi_pos(Dd);
            r[4*g]=cadd(A,Cc); r[4*g+2]=csub(A,Cc);
            r[4*g+1]=cadd(B,iD); r[4*g+3]=csub(B,iD);
        }
        #pragma unroll
        for (int q = 0; q < 4; ++q)
            bf4_inv(r[q], r[q+4], r[q+8], r[q+12], W1[q], W2[q], W3[q]);
    }
    #pragma unroll
    for (int i = 0; i < 16; ++i) sm[pb + i] = r[i];
    __syncthreads();
}

__device__ __forceinline__ float gelu_erf(float x){
    return 0.5f * x * (1.0f + erff(x * 0.70710678118654752f));
}

// ---------------- Kernel A: filter spectra --------------------------------
__global__ __launch_bounds__(512, 2)
void kfft_kernel(const float* __restrict__ k){
    extern __shared__ float2 sm[];
    const int tid = threadIdx.x;
    const int hp  = blockIdx.x;
    const int h1  = 2*hp, h2 = h1 + 1;
    const float* k1 = k + (size_t)h1 * 4096;
    const float* k2 = k + (size_t)h2 * 4096;

    float sn, cs;
    __sincosf(-PI_F * (float)tid * (1.0f/4096.0f), &sn, &cs);
    float2 wC = make_float2(cs, sn);                 // e^{-2pi i tid/8192}
    const float2 C8 = make_float2(C8X, C8Y);

    // fused load + radix-2 (zero-padded top half): E=x, O=x*w8192^l
    float2 w = wC;
    #pragma unroll
    for (int it = 0; it < 8; ++it){
        int l = tid + it * 512;
        float2 v = make_float2(k1[l], k2[l]);
        sm[SPAD(l)] = v;
        sm[SPAD(l + 4096)] = cmul(v, w);
        w = cmul(w, C8);
    }
    __syncthreads();

    stage16big<4096,false>(sm, tid);
    stage16big<256, false>(sm, tid);
    stage_16_4<false>(sm, tid);

    const float sc = 0.5f / 8192.0f;
    #pragma unroll 1
    for (int j = tid; j <= 4096; j += 512){
        int rj = SPAD(posf(j));
        int rn = SPAD(posf((8192 - j) & 8191));
        float2 Zj = sm[rj], Zn = sm[rn];
        d_Kf[(size_t)h1 * 4097 + j] = make_float2(sc*(Zj.x + Zn.x), sc*(Zj.y - Zn.y));
        d_Kf[(size_t)h2 * 4097 + j] = make_float2(sc*(Zj.y + Zn.y), sc*(Zn.x - Zj.x));
    }
}

// ---------------- Kernel B: conv + skip + gelu -----------------------------
__global__ __launch_bounds__(512, 2)
void conv_kernel(const float* __restrict__ u, const float* __restrict__ D){
    extern __shared__ float2 sm[];
    const int tid = threadIdx.x;
    const int hp  = blockIdx.x;
    const int b   = blockIdx.y;
    const int h1  = 2*hp, h2 = h1 + 1;
    const float* u1 = u + ((size_t)b * 512 + h1) * 4096;
    const float* u2 = u1 + 4096;

    float sn, cs;
    __sincosf(-PI_F * (float)tid * (1.0f/4096.0f), &sn, &cs);
    float2 wC = make_float2(cs, sn);
    const float2 C8 = make_float2(C8X, C8Y);

    // fused load + radix-2
    float2 w = wC;
    #pragma unroll
    for (int it = 0; it < 8; ++it){
        int l = tid + it * 512;
        float2 v = make_float2(u1[l], u2[l]);
        sm[SPAD(l)] = v;
        sm[SPAD(l + 4096)] = cmul(v, w);
        w = cmul(w, C8);
    }
    __syncthreads();

    stage16big<4096,false>(sm, tid);
    stage16big<256, false>(sm, tid);
    stage_16_4<false>(sm, tid);

    // pointwise: unpack two real spectra, multiply, repack (permuted domain)
    const float2* K1 = d_Kf + (size_t)h1 * 4097;
    const float2* K2 = d_Kf + (size_t)h2 * 4097;
    #pragma unroll 1
    for (int j = tid; j <= 4096; j += 512){
        int rj = SPAD(posf(j));
        int rn = SPAD(posf((8192 - j) & 8191));
        float2 Zj = sm[rj], Zn = sm[rn];
        float2 U1 = make_float2(0.5f*(Zj.x + Zn.x), 0.5f*(Zj.y - Zn.y));
        float2 U2 = make_float2(0.5f*(Zj.y + Zn.y), 0.5f*(Zn.x - Zj.x));
        float2 Y1 = cmul(U1, K1[j]);
        float2 Y2 = cmul(U2, K2[j]);
        sm[rj] = make_float2(Y1.x - Y2.y, Y1.y + Y2.x);   // W(j)   = Y1 + i*Y2
        sm[rn] = make_float2(Y1.x + Y2.y, Y2.x - Y1.y);   // W(N-j) = conj(Y1 - i*Y2)
    }
    __syncthreads();

    stage_16_4<true>(sm, tid);
    stage16big<256, true>(sm, tid);
    stage16big<4096,true>(sm, tid);

    // fused final radix-2 (only first 4096 outputs) + skip + gelu + store
    const float dA = D[h1], dB = D[h2];
    float* g1 = d_g + ((size_t)b * 512 + h1) * 4096;
    float* g2 = g1 + 4096;
    w = wC;
    #pragma unroll
    for (int it = 0; it < 8; ++it){
        int l = tid + it * 512;
        float2 E = sm[SPAD(l)], O = sm[SPAD(l + 4096)];
        float2 y = cadd(E, cmul(O, conjf2(w)));
        g1[l] = gelu_erf(y.x + dA * u1[l]);
        g2[l] = gelu_erf(y.y + dB * u2[l]);
        w = cmul(w, C8);
    }
}

// ---------------- packed f32x2 helpers (Blackwell FFMA2) -------------------
typedef unsigned long long u64t;

__device__ __forceinline__ u64t pack2dup(float x){
    u64t r;
    unsigned xi = __float_as_uint(x);
    asm("mov.b64 %0, {%1, %1};" : "=l"(r) : "r"(xi));
    return r;
}
__device__ __forceinline__ void fma2(u64t& d, u64t a, u64t b, u64t c){
    asm("fma.rn.f32x2 %0, %1, %2, %3;" : "=l"(d) : "l"(a), "l"(b), "l"(c));
}
__device__ __forceinline__ float2 unpack2(u64t v){
    unsigned lo, hi;
    asm("mov.b64 {%0, %1}, %2;" : "=r"(lo), "=r"(hi) : "l"(v));
    return make_float2(__uint_as_float(lo), __uint_as_float(hi));
}

// ---------------- Kernel C: pointwise linear (f32x2 SGEMM) -----------------
__global__ __launch_bounds__(256, 2)
void gemm_kernel(const float* __restrict__ W, const float* __restrict__ bias,
                 float* __restrict__ out){
    __shared__ float Ws[8][132];
    __shared__ float Gs[8][132];

    const int bb = blockIdx.z;
    const int d0 = blockIdx.y * 128;
    const int l0 = blockIdx.x * 128;
    const int t  = threadIdx.x;
    const int tx = t & 15, ty = t >> 4;

    const float* gbase = d_g + (size_t)bb * 512 * 4096;

    u64t acc2[8][4];
    #pragma unroll
    for (int i = 0; i < 8; ++i)
        #pragma unroll
        for (int j = 0; j < 4; ++j) acc2[i][j] = 0ull;

    const int wrow = t >> 1;
    const int wcol = (t & 1) * 4;
    const int grow = t >> 5;
    const int gcol = (t & 31) * 4;

    #pragma unroll 1
    for (int kk = 0; kk < 512; kk += 8){
        float4 wv = *(const float4*)&W[(size_t)(d0 + wrow) * 512 + kk + wcol];
        float4 gv = *(const float4*)&gbase[(size_t)(kk + grow) * 4096 + l0 + gcol];
        __syncthreads();
        Ws[wcol + 0][wrow] = wv.x;
        Ws[wcol + 1][wrow] = wv.y;
        Ws[wcol + 2][wrow] = wv.z;
        Ws[wcol + 3][wrow] = wv.w;
        *(float4*)&Gs[grow][gcol] = gv;
        __syncthreads();
        #pragma unroll
        for (int k = 0; k < 8; ++k){
            float a[8];
            *(float4*)&a[0] = *(const float4*)&Ws[k][ty * 4];
            *(float4*)&a[4] = *(const float4*)&Ws[k][64 + ty * 4];
            ulonglong2 b01 = *(const ulonglong2*)&Gs[k][tx * 4];
            ulonglong2 b23 = *(const ulonglong2*)&Gs[k][64 + tx * 4];
            u64t bp0 = b01.x, bp1 = b01.y, bp2 = b23.x, bp3 = b23.y;
            #pragma unroll
            for (int i = 0; i < 8; ++i){
                u64t ap = pack2dup(a[i]);
                fma2(acc2[i][0], ap, bp0, acc2[i][0]);
                fma2(acc2[i][1], ap, bp1, acc2[i][1]);
                fma2(acc2[i][2], ap, bp2, acc2[i][2]);
                fma2(acc2[i][3], ap, bp3, acc2[i][3]);
            }
        }
    }

    #pragma unroll
    for (int ih = 0; ih < 2; ++ih){
        #pragma unroll
        for (int i = 0; i < 4; ++i){
            int d = d0 + ih * 64 + ty * 4 + i;
            float bvl = bias[d];
            float* orow = out + ((size_t)bb * 512 + d) * 4096 + l0;
            #pragma unroll
            for (int jh = 0; jh < 2; ++jh){
                float2 p0 = unpack2(acc2[ih * 4 + i][jh * 2 + 0]);
                float2 p1 = unpack2(acc2[ih * 4 + i][jh * 2 + 1]);
                float4 o;
                o.x = p0.x + bvl;
                o.y = p0.y + bvl;
                o.z = p1.x + bvl;
                o.w = p1.y + bvl;
                *(float4*)&orow[jh * 64 + tx * 4] = o;
            }
        }
    }
}

// ---------------- Launch ---------------------------------------------------
extern "C" void kernel_launch(void* const* d_in, const int* in_sizes, int n_in,
                              void* d_out, int out_size){
    const float* u    = (const float*)d_in[0];   // (8, 512, 4096)
    const float* k    = (const float*)d_in[1];   // (1, 512, 4096)
    const float* D    = (const float*)d_in[2];   // (1, 512)
    const float* W    = (const float*)d_in[3];   // (512, 512)
    const float* bias = (const float*)d_in[4];   // (512,)
    float* out = (float*)d_out;                  // (8, 512, 4096)

    const size_t smem = 8704 * sizeof(float2);   // 68 KB (padded)
    cudaFuncSetAttribute(kfft_kernel, cudaFuncAttributeMaxDynamicSharedMemorySize, (int)smem);
    cudaFuncSetAttribute(conv_kernel, cudaFuncAttributeMaxDynamicSharedMemorySize, (int)smem);

    kfft_kernel<<<256, 512, smem>>>(k);
    conv_kernel<<<dim3(256, 8), 512, smem>>>(u, D);
    gemm_kernel<<<dim3(4096 / 128, 512 / 128, 8), 256>>>(W, bias, out);
}

// round 9
// speedup vs baseline: 1.6266x; 1.1436x over previous
#include <cuda_runtime.h>
#include <math.h>

#define PI_F 3.14159265358979323846f

// Scratch (allocation-free rule: __device__ globals)
__device__ float2 d_Kf[512 * 4097];          // filter half-spectra, pre-scaled by 1/4096
__device__ float  d_g[8ULL * 512 * 4096];    // gelu(conv + skip), fp32

// ---------------- complex helpers ----------------------------------------
__device__ __forceinline__ float2 cadd(float2 a, float2 b){ return make_float2(a.x+b.x, a.y+b.y); }
__device__ __forceinline__ float2 csub(float2 a, float2 b){ return make_float2(a.x-b.x, a.y-b.y); }
__device__ __forceinline__ float2 cmul(float2 a, float2 b){
    return make_float2(fmaf(a.x, b.x, -a.y*b.y), fmaf(a.x, b.y, a.y*b.x));
}
__device__ __forceinline__ float2 csqr(float2 a){
    return make_float2(fmaf(a.x,a.x,-a.y*a.y), 2.f*a.x*a.y);
}
__device__ __forceinline__ float2 conjf2(float2 a){ return make_float2(a.x, -a.y); }
__device__ __forceinline__ float2 mi_neg(float2 a){ return make_float2(a.y, -a.x); }  // -i*a
__device__ __forceinline__ float2 mi_pos(float2 a){ return make_float2(-a.y, a.x); }  // +i*a

// radix-4 butterflies
__device__ __forceinline__ void bf4_fwd(float2&a, float2&b, float2&c, float2&d,
                                        float2 w1, float2 w2, float2 w3){
    float2 t0=cadd(a,c), t1=csub(a,c), t2=cadd(b,d), t3=mi_neg(csub(b,d));
    a = cadd(t0,t2);
    b = cmul(cadd(t1,t3), w1);
    c = cmul(csub(t0,t2), w2);
    d = cmul(csub(t1,t3), w3);
}
__device__ __forceinline__ void bf4_inv(float2&a, float2&b, float2&c, float2&d,
                                        float2 w1c, float2 w2c, float2 w3c){
    float2 z1=cmul(b,w1c), z2=cmul(c,w2c), z3=cmul(d,w3c);
    float2 A=cadd(a,z2), B=csub(a,z2), Cc=cadd(z1,z3), Dd=csub(z1,z3);
    float2 iD = mi_pos(Dd);
    a = cadd(A,Cc); c = csub(A,Cc);
    b = cadd(B,iD); d = csub(B,iD);
}

// smem padding: 1 float2 pad per 16 -> conflict-free strides
#define SPAD(i) ((i) + ((i) >> 4))

// base-4 digit reversal of 12-bit index (N=4096 DIF output position)
__device__ __forceinline__ int pos4(int j){
    int y = __brev((unsigned)j) >> 20;
    return ((y & 0x555) << 1) | ((y >> 1) & 0x555);
}

// w16 = exp(-i*pi/8)
#define C8X 0.92387953251128675613f
#define C8Y (-0.38268343236508977173f)
// w_8192^256 = exp(-i*pi/16)
#define C16X 0.98078528040323044913f
#define C16Y (-0.19509032201612826785f)

// ---------------- merged radix-16 smem stage (N=4096, 256 threads) --------
template<int M, bool INV>
__device__ __forceinline__ void stage16N(float2* __restrict__ sm, int tid){
    const int S  = M >> 4;
    const int SP = S + (S >> 4);
    const int g  = (M == 4096) ? 0   : (tid >> 4);
    const int q  = (M == 4096) ? tid : (tid & 15);
    const int pb = SPAD(g * M + q);

    float2 r[16];
    #pragma unroll
    for (int j = 0; j < 16; ++j) r[j] = sm[pb + j * SP];

    float sn, cs;
    __sincosf(-PI_F * (float)q * (2.0f / (float)M), &sn, &cs);
    float2 w1 = make_float2(cs, INV ? -sn : sn);
    const float2 wst = make_float2(C8X, INV ? -C8Y : C8Y);

    float2 v1 = csqr(csqr(w1));
    float2 v2 = csqr(v1), v3 = cmul(v1, v2);

    if (!INV){
        float2 t1 = w1;
        #pragma unroll
        for (int jm = 0; jm < 4; ++jm){
            float2 t2 = csqr(t1), t3 = cmul(t1, t2);
            bf4_fwd(r[jm], r[jm+4], r[jm+8], r[jm+12], t1, t2, t3);
            t1 = cmul(t1, wst);
        }
        #pragma unroll
        for (int rr = 0; rr < 4; ++rr)
            bf4_fwd(r[4*rr], r[4*rr+1], r[4*rr+2], r[4*rr+3], v1, v2, v3);
    } else {
        #pragma unroll
        for (int rr = 0; rr < 4; ++rr)
            bf4_inv(r[4*rr], r[4*rr+1], r[4*rr+2], r[4*rr+3], v1, v2, v3);
        float2 t1 = w1;
        #pragma unroll
        for (int jm = 0; jm < 4; ++jm){
            float2 t2 = csqr(t1), t3 = cmul(t1, t2);
            bf4_inv(r[jm], r[jm+4], r[jm+8], r[jm+12], t1, t2, t3);
            t1 = cmul(t1, wst);
        }
    }
    #pragma unroll
    for (int j = 0; j < 16; ++j) sm[pb + j * SP] = r[j];
    __syncthreads();
}

// merged M=16 + M=4 stages in registers
template<bool INV>
__device__ __forceinline__ void stage_16_4(float2* __restrict__ sm, int tid){
    const int pb = tid * 17;   // SPAD(16*tid)
    float2 r[16];
    #pragma unroll
    for (int i = 0; i < 16; ++i) r[i] = sm[pb + i];

    const float CP8 = 0.92387953251128675613f;
    const float SP8 = 0.38268343236508977173f;
    const float R2  = 0.70710678118654752440f;
    const float C3  = 0.38268343236508977173f;
    const float S3v = 0.92387953251128675613f;
    const float sg = INV ? 1.f : -1.f;
    float2 W1[4] = { make_float2(1,0), make_float2(CP8, sg*SP8), make_float2(R2, sg*R2),   make_float2(C3, sg*S3v) };
    float2 W2[4] = { make_float2(1,0), make_float2(R2, sg*R2),   make_float2(0.f, sg),     make_float2(-R2, sg*R2) };
    float2 W3[4] = { make_float2(1,0), make_float2(C3, sg*S3v),  make_float2(-R2, sg*R2),  make_float2(-CP8, -sg*SP8) };

    if (!INV){
        #pragma unroll
        for (int q = 0; q < 4; ++q)
            bf4_fwd(r[q], r[q+4], r[q+8], r[q+12], W1[q], W2[q], W3[q]);
        #pragma unroll
        for (int g = 0; g < 4; ++g){
            float2 a=r[4*g], b=r[4*g+1], c=r[4*g+2], d=r[4*g+3];
            float2 t0=cadd(a,c), t1=csub(a,c), t2=cadd(b,d), t3=mi_neg(csub(b,d));
            r[4*g]=cadd(t0,t2); r[4*g+1]=cadd(t1,t3); r[4*g+2]=csub(t0,t2); r[4*g+3]=csub(t1,t3);
        }
    } else {
        #pragma unroll
        for (int g = 0; g < 4; ++g){
            float2 y0=r[4*g], y1=r[4*g+1], y2=r[4*g+2], y3=r[4*g+3];
            float2 A=cadd(y0,y2), B=csub(y0,y2), Cc=cadd(y1,y3), Dd=csub(y1,y3);
            float2 iD=mi_pos(Dd);
            r[4*g]=cadd(A,Cc); r[4*g+2]=csub(A,Cc);
            r[4*g+1]=cadd(B,iD); r[4*g+3]=csub(B,iD);
        }
        #pragma unroll
        for (int q = 0; q < 4; ++q)
            bf4_inv(r[q], r[q+4], r[q+8], r[q+12], W1[q], W2[q], W3[q]);
    }
    #pragma unroll
    for (int i = 0; i < 16; ++i) sm[pb + i] = r[i];
    __syncthreads();
}

__device__ __forceinline__ float gelu_erf(float x){
    return 0.5f * x * (1.0f + erff(x * 0.70710678118654752f));
}

// forward 4096-pt FFT over packed even/odd real row (zero-padded top half)
__device__ __forceinline__ void fft4096_fwd(float2* sm, int tid, const float2* __restrict__ src){
    #pragma unroll
    for (int it = 0; it < 8; ++it){
        int l = tid + it * 256;
        sm[SPAD(l)]        = src[l];
        sm[SPAD(l + 2048)] = make_float2(0.f, 0.f);
    }
    __syncthreads();
    stage16N<4096,false>(sm, tid);
    stage16N<256, false>(sm, tid);
    stage_16_4<false>(sm, tid);
}

// ---------------- Kernel A: filter spectra --------------------------------
// One real filter row per CTA. X[j] = E + w^j O; X[4096-j] = conj(E - w^j O).
__global__ __launch_bounds__(256, 5)
void kfft_kernel(const float* __restrict__ k){
    extern __shared__ float2 sm[];
    const int tid = threadIdx.x;
    const int h   = blockIdx.x;

    fft4096_fwd(sm, tid, (const float2*)(k + (size_t)h * 4096));

    const float sc = 1.0f / 4096.0f;   // inverse-FFT norm folded into K
    float sn, cs;
    __sincosf(-PI_F * (float)tid * (1.0f/4096.0f), &sn, &cs);
    float2 w = make_float2(cs, sn);                 // w_8192^tid
    const float2 CS = make_float2(C16X, C16Y);
    float2* Kf = d_Kf + (size_t)h * 4097;
    #pragma unroll 1
    for (int j = tid; j <= 2048; j += 256){
        int jn = 4096 - j;
        float2 Zj = sm[SPAD(pos4(j & 4095))];
        float2 Zn = sm[SPAD(pos4(jn & 4095))];
        float2 E = make_float2(0.5f*(Zj.x + Zn.x), 0.5f*(Zj.y - Zn.y));
        float2 O = make_float2(0.5f*(Zj.y + Zn.y), 0.5f*(Zn.x - Zj.x));
        float2 T = cmul(w, O);
        float2 Xj = cadd(E, T);
        float2 Xn = conjf2(csub(E, T));
        Kf[j]  = make_float2(sc*Xj.x, sc*Xj.y);
        Kf[jn] = make_float2(sc*Xn.x, sc*Xn.y);
        w = cmul(w, CS);
    }
}

// ---------------- Kernel B: conv + skip + gelu -----------------------------
__global__ __launch_bounds__(256, 5)
void conv_kernel(const float* __restrict__ u, const float* __restrict__ D){
    extern __shared__ float2 sm[];
    const int tid = threadIdx.x;
    const int h   = blockIdx.x;
    const int b   = blockIdx.y;
    const float2* uv = (const float2*)(u + ((size_t)b * 512 + h) * 4096);

    fft4096_fwd(sm, tid, uv);

    // pointwise in digit-reversed domain: unpack X, multiply K, repack Q
    const float2* Kf = d_Kf + (size_t)h * 4097;
    float sn, cs;
    __sincosf(-PI_F * (float)tid * (1.0f/4096.0f), &sn, &cs);
    float2 w = make_float2(cs, sn);                 // w_8192^j
    const float2 CS = make_float2(C16X, C16Y);
    #pragma unroll 1
    for (int j = tid; j <= 2048; j += 256){
        int jn = 4096 - j;
        int sj = SPAD(pos4(j & 4095));
        int sn2 = SPAD(pos4(jn & 4095));
        float2 Zj = sm[sj], Zn = sm[sn2];
        float2 E = make_float2(0.5f*(Zj.x + Zn.x), 0.5f*(Zj.y - Zn.y));
        float2 O = make_float2(0.5f*(Zj.y + Zn.y), 0.5f*(Zn.x - Zj.x));
        float2 T = cmul(w, O);
        float2 Xj = cadd(E, T);
        float2 Xn = conjf2(csub(E, T));
        float2 Yj = cmul(Xj, Kf[j]);
        float2 Yn = cmul(Xn, Kf[jn]);
        // Q[j] = (Yj + conj(Yn))/2 + i*conj(w)*(Yj - conj(Yn))/2
        float2 P  = make_float2(0.5f*(Yj.x + Yn.x), 0.5f*(Yj.y - Yn.y));
        float2 Mv = make_float2(0.5f*(Yj.x - Yn.x), 0.5f*(Yj.y + Yn.y));
        sm[sj] = cadd(P, mi_pos(cmul(conjf2(w), Mv)));
        if (j != 0){
            // Q[jn] = (Yn + conj(Yj))/2 - i*w*(Yn - conj(Yj))/2
            float2 P2 = make_float2(0.5f*(Yn.x + Yj.x), 0.5f*(Yn.y - Yj.y));
            float2 M2 = make_float2(0.5f*(Yn.x - Yj.x), 0.5f*(Yn.y + Yj.y));
            sm[sn2] = cadd(P2, mi_neg(cmul(w, M2)));
        }
        w = cmul(w, CS);
    }
    __syncthreads();

    stage_16_4<true>(sm, tid);
    stage16N<256, true>(sm, tid);
    stage16N<4096,true>(sm, tid);

    // epilogue: y[2l]=Re z', y[2l+1]=Im z' (first 2048 only) + skip + gelu
    const float dA = D[h];
    float2* gv = (float2*)(d_g + ((size_t)b * 512 + h) * 4096);
    #pragma unroll
    for (int it = 0; it < 8; ++it){
        int l = tid + it * 256;
        float2 z = sm[SPAD(l)];
        float2 uu = uv[l];
        float2 o;
        o.x = gelu_erf(z.x + dA * uu.x);
        o.y = gelu_erf(z.y + dA * uu.y);
        gv[l] = o;
    }
}

// ---------------- packed f32x2 helpers (Blackwell FFMA2) -------------------
typedef unsigned long long u64t;

__device__ __forceinline__ u64t pack2dup(float x){
    u64t r;
    unsigned xi = __float_as_uint(x);
    asm("mov.b64 %0, {%1, %1};" : "=l"(r) : "r"(xi));
    return r;
}
__device__ __forceinline__ void fma2(u64t& d, u64t a, u64t b, u64t c){
    asm("fma.rn.f32x2 %0, %1, %2, %3;" : "=l"(d) : "l"(a), "l"(b), "l"(c));
}
__device__ __forceinline__ float2 unpack2(u64t v){
    unsigned lo, hi;
    asm("mov.b64 {%0, %1}, %2;" : "=r"(lo), "=r"(hi) : "l"(v));
    return make_float2(__uint_as_float(lo), __uint_as_float(hi));
}

// ---------------- Kernel C: pointwise linear (f32x2 SGEMM, double-buffered)
__global__ __launch_bounds__(256, 2)
void gemm_kernel(const float* __restrict__ W, const float* __restrict__ bias,
                 float* __restrict__ out){
    __shared__ float Ws[2][8][132];
    __shared__ float Gs[2][8][132];

    const int bb = blockIdx.z;
    const int d0 = blockIdx.y * 128;
    const int l0 = blockIdx.x * 128;
    const int t  = threadIdx.x;
    const int tx = t & 15, ty = t >> 4;

    const float* gbase = d_g + (size_t)bb * 512 * 4096;

    u64t acc2[8][4];
    #pragma unroll
    for (int i = 0; i < 8; ++i)
        #pragma unroll
        for (int j = 0; j < 4; ++j) acc2[i][j] = 0ull;

    const int wrow = t >> 1;
    const int wcol = (t & 1) * 4;
    const int grow = t >> 5;
    const int gcol = (t & 31) * 4;

    // prologue: load tile 0
    {
        float4 wv = *(const float4*)&W[(size_t)(d0 + wrow) * 512 + wcol];
        float4 gvv = *(const float4*)&gbase[(size_t)grow * 4096 + l0 + gcol];
        Ws[0][wcol + 0][wrow] = wv.x;
        Ws[0][wcol + 1][wrow] = wv.y;
        Ws[0][wcol + 2][wrow] = wv.z;
        Ws[0][wcol + 3][wrow] = wv.w;
        *(float4*)&Gs[0][grow][gcol] = gvv;
    }
    __syncthreads();

    int p = 0;
    #pragma unroll 1
    for (int kk = 0; kk < 512; kk += 8){
        float4 wn, gn;
        const bool has_next = (kk + 8 < 512);
        if (has_next){
            wn = *(const float4*)&W[(size_t)(d0 + wrow) * 512 + kk + 8 + wcol];
            gn = *(const float4*)&gbase[(size_t)(kk + 8 + grow) * 4096 + l0 + gcol];
        }
        #pragma unroll
        for (int k = 0; k < 8; ++k){
            float a[8];
            *(float4*)&a[0] = *(const float4*)&Ws[p][k][ty * 4];
            *(float4*)&a[4] = *(const float4*)&Ws[p][k][64 + ty * 4];
            ulonglong2 b01 = *(const ulonglong2*)&Gs[p][k][tx * 4];
            ulonglong2 b23 = *(const ulonglong2*)&Gs[p][k][64 + tx * 4];
            u64t bp0 = b01.x, bp1 = b01.y, bp2 = b23.x, bp3 = b23.y;
            #pragma unroll
            for (int i = 0; i < 8; ++i){
                u64t ap = pack2dup(a[i]);
                fma2(acc2[i][0], ap, bp0, acc2[i][0]);
                fma2(acc2[i][1], ap, bp1, acc2[i][1]);
                fma2(acc2[i][2], ap, bp2, acc2[i][2]);
                fma2(acc2[i][3], ap, bp3, acc2[i][3]);
            }
        }
        if (has_next){
            int q = p ^ 1;
            Ws[q][wcol + 0][wrow] = wn.x;
            Ws[q][wcol + 1][wrow] = wn.y;
            Ws[q][wcol + 2][wrow] = wn.z;
            Ws[q][wcol + 3][wrow] = wn.w;
            *(float4*)&Gs[q][grow][gcol] = gn;
            __syncthreads();
            p = q;
        }
    }

    #pragma unroll
    for (int ih = 0; ih < 2; ++ih){
        #pragma unroll
        for (int i = 0; i < 4; ++i){
            int d = d0 + ih * 64 + ty * 4 + i;
            float bvl = bias[d];
            float* orow = out + ((size_t)bb * 512 + d) * 4096 + l0;
            #pragma unroll
            for (int jh = 0; jh < 2; ++jh){
                float2 p0 = unpack2(acc2[ih * 4 + i][jh * 2 + 0]);
                float2 p1 = unpack2(acc2[ih * 4 + i][jh * 2 + 1]);
                float4 o;
                o.x = p0.x + bvl;
                o.y = p0.y + bvl;
                o.z = p1.x + bvl;
                o.w = p1.y + bvl;
                *(float4*)&orow[jh * 64 + tx * 4] = o;
            }
        }
    }
}

// ---------------- Launch ---------------------------------------------------
extern "C" void kernel_launch(void* const* d_in, const int* in_sizes, int n_in,
                              void* d_out, int out_size){
    const float* u    = (const float*)d_in[0];   // (8, 512, 4096)
    const float* k    = (const float*)d_in[1];   // (1, 512, 4096)
    const float* D    = (const float*)d_in[2];   // (1, 512)
    const float* W    = (const float*)d_in[3];   // (512, 512)
    const float* bias = (const float*)d_in[4];   // (512,)
    float* out = (float*)d_out;                  // (8, 512, 4096)

    const size_t smem = 4352 * sizeof(float2);   // 34 KB (4096 + pad)
    cudaFuncSetAttribute(kfft_kernel, cudaFuncAttributeMaxDynamicSharedMemorySize, (int)smem);
    cudaFuncSetAttribute(conv_kernel, cudaFuncAttributeMaxDynamicSharedMemorySize, (int)smem);

    kfft_kernel<<<512, 256, smem>>>(k);
    conv_kernel<<<dim3(512, 8), 256, smem>>>(u, D);
    gemm_kernel<<<dim3(4096 / 128, 512 / 128, 8), 256>>>(W, bias, out);
}

// round 10
// speedup vs baseline: 1.6519x; 1.0155x over previous
#include <cuda_runtime.h>
#include <math.h>

#define PI_F 3.14159265358979323846f

// Scratch (allocation-free rule: __device__ globals)
__device__ float2 d_Kf[512 * 4097];          // filter half-spectra, pre-scaled by 1/4096
__device__ float  d_g[8ULL * 512 * 4096];    // gelu(conv + skip), fp32

// ---------------- complex helpers ----------------------------------------
__device__ __forceinline__ float2 cadd(float2 a, float2 b){ return make_float2(a.x+b.x, a.y+b.y); }
__device__ __forceinline__ float2 csub(float2 a, float2 b){ return make_float2(a.x-b.x, a.y-b.y); }
__device__ __forceinline__ float2 cmul(float2 a, float2 b){
    return make_float2(fmaf(a.x, b.x, -a.y*b.y), fmaf(a.x, b.y, a.y*b.x));
}
__device__ __forceinline__ float2 csqr(float2 a){
    return make_float2(fmaf(a.x,a.x,-a.y*a.y), 2.f*a.x*a.y);
}
__device__ __forceinline__ float2 conjf2(float2 a){ return make_float2(a.x, -a.y); }
__device__ __forceinline__ float2 mi_neg(float2 a){ return make_float2(a.y, -a.x); }  // -i*a
__device__ __forceinline__ float2 mi_pos(float2 a){ return make_float2(-a.y, a.x); }  // +i*a

// radix-4 butterflies
__device__ __forceinline__ void bf4_fwd(float2&a, float2&b, float2&c, float2&d,
                                        float2 w1, float2 w2, float2 w3){
    float2 t0=cadd(a,c), t1=csub(a,c), t2=cadd(b,d), t3=mi_neg(csub(b,d));
    a = cadd(t0,t2);
    b = cmul(cadd(t1,t3), w1);
    c = cmul(csub(t0,t2), w2);
    d = cmul(csub(t1,t3), w3);
}
__device__ __forceinline__ void bf4_inv(float2&a, float2&b, float2&c, float2&d,
                                        float2 w1c, float2 w2c, float2 w3c){
    float2 z1=cmul(b,w1c), z2=cmul(c,w2c), z3=cmul(d,w3c);
    float2 A=cadd(a,z2), B=csub(a,z2), Cc=cadd(z1,z3), Dd=csub(z1,z3);
    float2 iD = mi_pos(Dd);
    a = cadd(A,Cc); c = csub(A,Cc);
    b = cadd(B,iD); d = csub(B,iD);
}

// smem padding: 1 float2 pad per 16 -> conflict-free strides
#define SPAD(i) ((i) + ((i) >> 4))

// base-4 digit reversal of 12-bit index (N=4096 DIF output position)
__device__ __forceinline__ int pos4(int j){
    int y = __brev((unsigned)j) >> 20;
    return ((y & 0x555) << 1) | ((y >> 1) & 0x555);
}

// w16 = exp(-i*pi/8)
#define C8X 0.92387953251128675613f
#define C8Y (-0.38268343236508977173f)
// w_8192^256 = exp(-i*pi/16)
#define C16X 0.98078528040323044913f
#define C16Y (-0.19509032201612826785f)

// ---------------- merged radix-16 smem stage (M=256 middle stage) ---------
template<int M, bool INV>
__device__ __forceinline__ void stage16N(float2* __restrict__ sm, int tid){
    const int S  = M >> 4;
    const int SP = S + (S >> 4);
    const int g  = (M == 4096) ? 0   : (tid >> 4);
    const int q  = (M == 4096) ? tid : (tid & 15);
    const int pb = SPAD(g * M + q);

    float2 r[16];
    #pragma unroll
    for (int j = 0; j < 16; ++j) r[j] = sm[pb + j * SP];

    float sn, cs;
    __sincosf(-PI_F * (float)q * (2.0f / (float)M), &sn, &cs);
    float2 w1 = make_float2(cs, INV ? -sn : sn);
    const float2 wst = make_float2(C8X, INV ? -C8Y : C8Y);

    float2 v1 = csqr(csqr(w1));
    float2 v2 = csqr(v1), v3 = cmul(v1, v2);

    if (!INV){
        float2 t1 = w1;
        #pragma unroll
        for (int jm = 0; jm < 4; ++jm){
            float2 t2 = csqr(t1), t3 = cmul(t1, t2);
            bf4_fwd(r[jm], r[jm+4], r[jm+8], r[jm+12], t1, t2, t3);
            t1 = cmul(t1, wst);
        }
        #pragma unroll
        for (int rr = 0; rr < 4; ++rr)
            bf4_fwd(r[4*rr], r[4*rr+1], r[4*rr+2], r[4*rr+3], v1, v2, v3);
    } else {
        #pragma unroll
        for (int rr = 0; rr < 4; ++rr)
            bf4_inv(r[4*rr], r[4*rr+1], r[4*rr+2], r[4*rr+3], v1, v2, v3);
        float2 t1 = w1;
        #pragma unroll
        for (int jm = 0; jm < 4; ++jm){
            float2 t2 = csqr(t1), t3 = cmul(t1, t2);
            bf4_inv(r[jm], r[jm+4], r[jm+8], r[jm+12], t1, t2, t3);
            t1 = cmul(t1, wst);
        }
    }
    #pragma unroll
    for (int j = 0; j < 16; ++j) sm[pb + j * SP] = r[j];
    __syncthreads();
}

// ---------------- fused forward stage 1 (M=4096, zero-padded, gmem load) --
// Loads the 8 nonzero elements (positions q + j*256 < 2048) straight from
// gmem; top half is the zero pad. Layer-1 butterflies simplified for c=d=0:
// y0=a+b, y1=(a-ib)w1, y2=(a-b)w2, y3=(a+ib)w3.
__device__ __forceinline__ void stage1_fwd_fused(float2* __restrict__ sm, int tid,
                                                 const float2* __restrict__ src){
    const int q  = tid;
    const int SP = 272;              // 256 + pad
    const int pb = SPAD(q);

    float2 r[16];
    #pragma unroll
    for (int j = 0; j < 8; ++j) r[j] = src[q + j * 256];

    float sn, cs;
    __sincosf(-PI_F * (float)q * (2.0f / 4096.0f), &sn, &cs);
    float2 w1 = make_float2(cs, sn);
    const float2 wst = make_float2(C8X, C8Y);
    float2 v1 = csqr(csqr(w1));
    float2 v2 = csqr(v1), v3 = cmul(v1, v2);

    float2 t1 = w1;
    #pragma unroll
    for (int jm = 0; jm < 4; ++jm){
        float2 t2 = csqr(t1), t3 = cmul(t1, t2);
        float2 a = r[jm], b = r[jm + 4];
        float2 ib = mi_pos(b);
        r[jm]      = cadd(a, b);
        r[jm + 4]  = cmul(csub(a, ib), t1);
        r[jm + 8]  = cmul(csub(a, b),  t2);
        r[jm + 12] = cmul(cadd(a, ib), t3);
        t1 = cmul(t1, wst);
    }
    #pragma unroll
    for (int rr = 0; rr < 4; ++rr)
        bf4_fwd(r[4*rr], r[4*rr+1], r[4*rr+2], r[4*rr+3], v1, v2, v3);
    #pragma unroll
    for (int j = 0; j < 16; ++j) sm[pb + j * SP] = r[j];
    __syncthreads();
}

__device__ __forceinline__ float gelu_erf(float x){
    return 0.5f * x * (1.0f + erff(x * 0.70710678118654752f));
}

// ---------------- fused inverse stage 1 + epilogue (conv only) ------------
// Final inverse stage (M=4096): outputs r[j] are positions q + j*256; only
// j<8 (<2048) are needed. Layer-1 inverse computes just y0,y1 per quad, and
// the gelu/skip epilogue runs straight out of registers (coalesced stores).
__device__ __forceinline__ void stage1_inv_fused_epi(float2* __restrict__ sm, int tid,
                                                     float dA,
                                                     const float2* __restrict__ uv,
                                                     float2* __restrict__ gv){
    const int q  = tid;
    const int SP = 272;
    const int pb = SPAD(q);

    float2 r[16];
    #pragma unroll
    for (int j = 0; j < 16; ++j) r[j] = sm[pb + j * SP];

    float sn, cs;
    __sincosf(-PI_F * (float)q * (2.0f / 4096.0f), &sn, &cs);
    float2 w1 = make_float2(cs, -sn);               // conj
    const float2 wst = make_float2(C8X, -C8Y);      // conj step
    float2 v1 = csqr(csqr(w1));
    float2 v2 = csqr(v1), v3 = cmul(v1, v2);

    #pragma unroll
    for (int rr = 0; rr < 4; ++rr)
        bf4_inv(r[4*rr], r[4*rr+1], r[4*rr+2], r[4*rr+3], v1, v2, v3);

    float2 t1 = w1;
    #pragma unroll
    for (int jm = 0; jm < 4; ++jm){
        float2 t2 = csqr(t1), t3 = cmul(t1, t2);
        // inverse butterfly, outputs y0,y1 only
        float2 z1 = cmul(r[jm+4],  t1);
        float2 z2 = cmul(r[jm+8],  t2);
        float2 z3 = cmul(r[jm+12], t3);
        float2 A  = cadd(r[jm], z2);
        float2 B  = csub(r[jm], z2);
        float2 Cc = cadd(z1, z3);
        float2 Dd = csub(z1, z3);
        r[jm]     = cadd(A, Cc);            // y0 -> position q + jm*256
        r[jm + 4] = cadd(B, mi_pos(Dd));    // y1 -> position q + (jm+4)*256
        t1 = cmul(t1, wst);
    }

    #pragma unroll
    for (int j = 0; j < 8; ++j){
        int l = q + j * 256;
        float2 uu = uv[l];
        float2 o;
        o.x = gelu_erf(r[j].x + dA * uu.x);
        o.y = gelu_erf(r[j].y + dA * uu.y);
        gv[l] = o;
    }
}

// merged M=16 + M=4 stages in registers
template<bool INV>
__device__ __forceinline__ void stage_16_4(float2* __restrict__ sm, int tid){
    const int pb = tid * 17;   // SPAD(16*tid)
    float2 r[16];
    #pragma unroll
    for (int i = 0; i < 16; ++i) r[i] = sm[pb + i];

    const float CP8 = 0.92387953251128675613f;
    const float SP8 = 0.38268343236508977173f;
    const float R2  = 0.70710678118654752440f;
    const float C3  = 0.38268343236508977173f;
    const float S3v = 0.92387953251128675613f;
    const float sg = INV ? 1.f : -1.f;
    float2 W1[4] = { make_float2(1,0), make_float2(CP8, sg*SP8), make_float2(R2, sg*R2),   make_float2(C3, sg*S3v) };
    float2 W2[4] = { make_float2(1,0), make_float2(R2, sg*R2),   make_float2(0.f, sg),     make_float2(-R2, sg*R2) };
    float2 W3[4] = { make_float2(1,0), make_float2(C3, sg*S3v),  make_float2(-R2, sg*R2),  make_float2(-CP8, -sg*SP8) };

    if (!INV){
        #pragma unroll
        for (int q = 0; q < 4; ++q)
            bf4_fwd(r[q], r[q+4], r[q+8], r[q+12], W1[q], W2[q], W3[q]);
        #pragma unroll
        for (int g = 0; g < 4; ++g){
            float2 a=r[4*g], b=r[4*g+1], c=r[4*g+2], d=r[4*g+3];
            float2 t0=cadd(a,c), t1=csub(a,c), t2=cadd(b,d), t3=mi_neg(csub(b,d));
            r[4*g]=cadd(t0,t2); r[4*g+1]=cadd(t1,t3); r[4*g+2]=csub(t0,t2); r[4*g+3]=csub(t1,t3);
        }
    } else {
        #pragma unroll
        for (int g = 0; g < 4; ++g){
            float2 y0=r[4*g], y1=r[4*g+1], y2=r[4*g+2], y3=r[4*g+3];
            float2 A=cadd(y0,y2), B=csub(y0,y2), Cc=cadd(y1,y3), Dd=csub(y1,y3);
            float2 iD=mi_pos(Dd);
            r[4*g]=cadd(A,Cc); r[4*g+2]=csub(A,Cc);
            r[4*g+1]=cadd(B,iD); r[4*g+3]=csub(B,iD);
        }
        #pragma unroll
        for (int q = 0; q < 4; ++q)
            bf4_inv(r[q], r[q+4], r[q+8], r[q+12], W1[q], W2[q], W3[q]);
    }
    #pragma unroll
    for (int i = 0; i < 16; ++i) sm[pb + i] = r[i];
    __syncthreads();
}

// ---------------- Kernel A: filter spectra --------------------------------
__global__ __launch_bounds__(256, 5)
void kfft_kernel(const float* __restrict__ k){
    extern __shared__ float2 sm[];
    const int tid = threadIdx.x;
    const int h   = blockIdx.x;

    stage1_fwd_fused(sm, tid, (const float2*)(k + (size_t)h * 4096));
    stage16N<256, false>(sm, tid);
    stage_16_4<false>(sm, tid);

    const float sc = 1.0f / 4096.0f;   // inverse-FFT norm folded into K
    float sn, cs;
    __sincosf(-PI_F * (float)tid * (1.0f/4096.0f), &sn, &cs);
    float2 w = make_float2(cs, sn);                 // w_8192^tid
    const float2 CS = make_float2(C16X, C16Y);
    float2* Kf = d_Kf + (size_t)h * 4097;
    #pragma unroll 1
    for (int j = tid; j <= 2048; j += 256){
        int jn = 4096 - j;
        float2 Zj = sm[SPAD(pos4(j & 4095))];
        float2 Zn = sm[SPAD(pos4(jn & 4095))];
        float2 E = make_float2(0.5f*(Zj.x + Zn.x), 0.5f*(Zj.y - Zn.y));
        float2 O = make_float2(0.5f*(Zj.y + Zn.y), 0.5f*(Zn.x - Zj.x));
        float2 T = cmul(w, O);
        float2 Xj = cadd(E, T);
        float2 Xn = conjf2(csub(E, T));
        Kf[j]  = make_float2(sc*Xj.x, sc*Xj.y);
        Kf[jn] = make_float2(sc*Xn.x, sc*Xn.y);
        w = cmul(w, CS);
    }
}

// ---------------- Kernel B: conv + skip + gelu -----------------------------
__global__ __launch_bounds__(256, 5)
void conv_kernel(const float* __restrict__ u, const float* __restrict__ D){
    extern __shared__ float2 sm[];
    const int tid = threadIdx.x;
    const int h   = blockIdx.x;
    const int b   = blockIdx.y;
    const float2* uv = (const float2*)(u + ((size_t)b * 512 + h) * 4096);

    stage1_fwd_fused(sm, tid, uv);
    stage16N<256, false>(sm, tid);
    stage_16_4<false>(sm, tid);

    // pointwise in digit-reversed domain: unpack X, multiply K, repack Q
    const float2* Kf = d_Kf + (size_t)h * 4097;
    float sn, cs;
    __sincosf(-PI_F * (float)tid * (1.0f/4096.0f), &sn, &cs);
    float2 w = make_float2(cs, sn);                 // w_8192^j
    const float2 CS = make_float2(C16X, C16Y);
    #pragma unroll 1
    for (int j = tid; j <= 2048; j += 256){
        int jn = 4096 - j;
        int sj  = SPAD(pos4(j & 4095));
        int sn2 = SPAD(pos4(jn & 4095));
        float2 Zj = sm[sj], Zn = sm[sn2];
        float2 E = make_float2(0.5f*(Zj.x + Zn.x), 0.5f*(Zj.y - Zn.y));
        float2 O = make_float2(0.5f*(Zj.y + Zn.y), 0.5f*(Zn.x - Zj.x));
        float2 T = cmul(w, O);
        float2 Xj = cadd(E, T);
        float2 Xn = conjf2(csub(E, T));
        float2 Yj = cmul(Xj, Kf[j]);
        float2 Yn = cmul(Xn, Kf[jn]);
        // Q[j] = (Yj + conj(Yn))/2 + i*conj(w)*(Yj - conj(Yn))/2
        float2 P  = make_float2(0.5f*(Yj.x + Yn.x), 0.5f*(Yj.y - Yn.y));
        float2 Mv = make_float2(0.5f*(Yj.x - Yn.x), 0.5f*(Yj.y + Yn.y));
        sm[sj] = cadd(P, mi_pos(cmul(conjf2(w), Mv)));
        if (j != 0){
            float2 P2 = make_float2(0.5f*(Yn.x + Yj.x), 0.5f*(Yn.y - Yj.y));
            float2 M2 = make_float2(0.5f*(Yn.x - Yj.x), 0.5f*(Yn.y + Yj.y));
            sm[sn2] = cadd(P2, mi_neg(cmul(w, M2)));
        }
        w = cmul(w, CS);
    }
    __syncthreads();

    stage_16_4<true>(sm, tid);
    stage16N<256, true>(sm, tid);
    stage1_inv_fused_epi(sm, tid, D[h], uv,
                         (float2*)(d_g + ((size_t)b * 512 + h) * 4096));
}

// ---------------- packed f32x2 helpers (Blackwell FFMA2) -------------------
typedef unsigned long long u64t;

__device__ __forceinline__ u64t pack2dup(float x){
    u64t r;
    unsigned xi = __float_as_uint(x);
    asm("mov.b64 %0, {%1, %1};" : "=l"(r) : "r"(xi));
    return r;
}
__device__ __forceinline__ void fma2(u64t& d, u64t a, u64t b, u64t c){
    asm("fma.rn.f32x2 %0, %1, %2, %3;" : "=l"(d) : "l"(a), "l"(b), "l"(c));
}
__device__ __forceinline__ float2 unpack2(u64t v){
    unsigned lo, hi;
    asm("mov.b64 {%0, %1}, %2;" : "=r"(lo), "=r"(hi) : "l"(v));
    return make_float2(__uint_as_float(lo), __uint_as_float(hi));
}

// ---------------- Kernel C: pointwise linear (f32x2 SGEMM, double-buffered)
__global__ __launch_bounds__(256, 2)
void gemm_kernel(const float* __restrict__ W, const float* __restrict__ bias,
                 float* __restrict__ out){
    __shared__ float Ws[2][8][132];
    __shared__ float Gs[2][8][132];

    const int bb = blockIdx.z;
    const int d0 = blockIdx.y * 128;
    const int l0 = blockIdx.x * 128;
    const int t  = threadIdx.x;
    const int tx = t & 15, ty = t >> 4;

    const float* gbase = d_g + (size_t)bb * 512 * 4096;

    u64t acc2[8][4];
    #pragma unroll
    for (int i = 0; i < 8; ++i)
        #pragma unroll
        for (int j = 0; j < 4; ++j) acc2[i][j] = 0ull;

    const int wrow = t >> 1;
    const int wcol = (t & 1) * 4;
    const int grow = t >> 5;
    const int gcol = (t & 31) * 4;

    {
        float4 wv = *(const float4*)&W[(size_t)(d0 + wrow) * 512 + wcol];
        float4 gvv = *(const float4*)&gbase[(size_t)grow * 4096 + l0 + gcol];
        Ws[0][wcol + 0][wrow] = wv.x;
        Ws[0][wcol + 1][wrow] = wv.y;
        Ws[0][wcol + 2][wrow] = wv.z;
        Ws[0][wcol + 3][wrow] = wv.w;
        *(float4*)&Gs[0][grow][gcol] = gvv;
    }
    __syncthreads();

    int p = 0;
    #pragma unroll 1
    for (int kk = 0; kk < 512; kk += 8){
        float4 wn, gn;
        const bool has_next = (kk + 8 < 512);
        if (has_next){
            wn = *(const float4*)&W[(size_t)(d0 + wrow) * 512 + kk + 8 + wcol];
            gn = *(const float4*)&gbase[(size_t)(kk + 8 + grow) * 4096 + l0 + gcol];
        }
        #pragma unroll
        for (int k = 0; k < 8; ++k){
            float a[8];
            *(float4*)&a[0] = *(const float4*)&Ws[p][k][ty * 4];
            *(float4*)&a[4] = *(const float4*)&Ws[p][k][64 + ty * 4];
            ulonglong2 b01 = *(const ulonglong2*)&Gs[p][k][tx * 4];
            ulonglong2 b23 = *(const ulonglong2*)&Gs[p][k][64 + tx * 4];
            u64t bp0 = b01.x, bp1 = b01.y, bp2 = b23.x, bp3 = b23.y;
            #pragma unroll
            for (int i = 0; i < 8; ++i){
                u64t ap = pack2dup(a[i]);
                fma2(acc2[i][0], ap, bp0, acc2[i][0]);
                fma2(acc2[i][1], ap, bp1, acc2[i][1]);
                fma2(acc2[i][2], ap, bp2, acc2[i][2]);
                fma2(acc2[i][3], ap, bp3, acc2[i][3]);
            }
        }
        if (has_next){
            int q = p ^ 1;
            Ws[q][wcol + 0][wrow] = wn.x;
            Ws[q][wcol + 1][wrow] = wn.y;
            Ws[q][wcol + 2][wrow] = wn.z;
            Ws[q][wcol + 3][wrow] = wn.w;
            *(float4*)&Gs[q][grow][gcol] = gn;
            __syncthreads();
            p = q;
        }
    }

    #pragma unroll
    for (int ih = 0; ih < 2; ++ih){
        #pragma unroll
        for (int i = 0; i < 4; ++i){
            int d = d0 + ih * 64 + ty * 4 + i;
            float bvl = bias[d];
            float* orow = out + ((size_t)bb * 512 + d) * 4096 + l0;
            #pragma unroll
            for (int jh = 0; jh < 2; ++jh){
                float2 p0 = unpack2(acc2[ih * 4 + i][jh * 2 + 0]);
                float2 p1 = unpack2(acc2[ih * 4 + i][jh * 2 + 1]);
                float4 o;
                o.x = p0.x + bvl;
                o.y = p0.y + bvl;
                o.z = p1.x + bvl;
                o.w = p1.y + bvl;
                *(float4*)&orow[jh * 64 + tx * 4] = o;
            }
        }
    }
}

// ---------------- Launch ---------------------------------------------------
extern "C" void kernel_launch(void* const* d_in, const int* in_sizes, int n_in,
                              void* d_out, int out_size){
    const float* u    = (const float*)d_in[0];   // (8, 512, 4096)
    const float* k    = (const float*)d_in[1];   // (1, 512, 4096)
    const float* D    = (const float*)d_in[2];   // (1, 512)
    const float* W    = (const float*)d_in[3];   // (512, 512)
    const float* bias = (const float*)d_in[4];   // (512,)
    float* out = (float*)d_out;                  // (8, 512, 4096)

    const size_t smem = 4352 * sizeof(float2);   // 34 KB (4096 + pad)
    cudaFuncSetAttribute(kfft_kernel, cudaFuncAttributeMaxDynamicSharedMemorySize, (int)smem);
    cudaFuncSetAttribute(conv_kernel, cudaFuncAttributeMaxDynamicSharedMemorySize, (int)smem);

    kfft_kernel<<<512, 256, smem>>>(k);
    conv_kernel<<<dim3(512, 8), 256, smem>>>(u, D);
    gemm_kernel<<<dim3(4096 / 128, 512 / 128, 8), 256>>>(W, bias, out);
}

// round 13
// speedup vs baseline: 2.4054x; 1.4562x over previous
#include <cuda_runtime.h>
#include <cuda_bf16.h>
#include <cstdint>
#include <math.h>

#define PI_F 3.14159265358979323846f

// Scratch (allocation-free rule: __device__ globals)
__device__ float2 d_Kf[512 * 4097];                    // filter half-spectra
__device__ __nv_bfloat16 d_gh[8ULL * 512 * 4096];      // gelu(conv+skip) hi
__device__ __nv_bfloat16 d_gl[8ULL * 512 * 4096];      // gelu(conv+skip) lo
__device__ __nv_bfloat16 d_Wh[512 * 512];              // W hi
__device__ __nv_bfloat16 d_Wl[512 * 512];              // W lo

// ---------------- complex helpers ----------------------------------------
__device__ __forceinline__ float2 cadd(float2 a, float2 b){ return make_float2(a.x+b.x, a.y+b.y); }
__device__ __forceinline__ float2 csub(float2 a, float2 b){ return make_float2(a.x-b.x, a.y-b.y); }
__device__ __forceinline__ float2 cmul(float2 a, float2 b){
    return make_float2(fmaf(a.x, b.x, -a.y*b.y), fmaf(a.x, b.y, a.y*b.x));
}
__device__ __forceinline__ float2 csqr(float2 a){
    return make_float2(fmaf(a.x,a.x,-a.y*a.y), 2.f*a.x*a.y);
}
__device__ __forceinline__ float2 conjf2(float2 a){ return make_float2(a.x, -a.y); }
__device__ __forceinline__ float2 mi_neg(float2 a){ return make_float2(a.y, -a.x); }
__device__ __forceinline__ float2 mi_pos(float2 a){ return make_float2(-a.y, a.x); }

__device__ __forceinline__ void bf4_fwd(float2&a, float2&b, float2&c, float2&d,
                                        float2 w1, float2 w2, float2 w3){
    float2 t0=cadd(a,c), t1=csub(a,c), t2=cadd(b,d), t3=mi_neg(csub(b,d));
    a = cadd(t0,t2);
    b = cmul(cadd(t1,t3), w1);
    c = cmul(csub(t0,t2), w2);
    d = cmul(csub(t1,t3), w3);
}
__device__ __forceinline__ void bf4_inv(float2&a, float2&b, float2&c, float2&d,
                                        float2 w1c, float2 w2c, float2 w3c){
    float2 z1=cmul(b,w1c), z2=cmul(c,w2c), z3=cmul(d,w3c);
    float2 A=cadd(a,z2), B=csub(a,z2), Cc=cadd(z1,z3), Dd=csub(z1,z3);
    float2 iD = mi_pos(Dd);
    a = cadd(A,Cc); c = csub(A,Cc);
    b = cadd(B,iD); d = csub(B,iD);
}

#define SPAD(i) ((i) + ((i) >> 4))

__device__ __forceinline__ int pos4(int j){
    int y = __brev((unsigned)j) >> 20;
    return ((y & 0x555) << 1) | ((y >> 1) & 0x555);
}

#define C8X 0.92387953251128675613f
#define C8Y (-0.38268343236508977173f)
#define C16X 0.98078528040323044913f
#define C16Y (-0.19509032201612826785f)

template<int M, bool INV>
__device__ __forceinline__ void stage16N(float2* __restrict__ sm, int tid){
    const int S  = M >> 4;
    const int SP = S + (S >> 4);
    const int g  = (M == 4096) ? 0   : (tid >> 4);
    const int q  = (M == 4096) ? tid : (tid & 15);
    const int pb = SPAD(g * M + q);

    float2 r[16];
    #pragma unroll
    for (int j = 0; j < 16; ++j) r[j] = sm[pb + j * SP];

    float sn, cs;
    __sincosf(-PI_F * (float)q * (2.0f / (float)M), &sn, &cs);
    float2 w1 = make_float2(cs, INV ? -sn : sn);
    const float2 wst = make_float2(C8X, INV ? -C8Y : C8Y);
    float2 v1 = csqr(csqr(w1));
    float2 v2 = csqr(v1), v3 = cmul(v1, v2);

    if (!INV){
        float2 t1 = w1;
        #pragma unroll
        for (int jm = 0; jm < 4; ++jm){
            float2 t2 = csqr(t1), t3 = cmul(t1, t2);
            bf4_fwd(r[jm], r[jm+4], r[jm+8], r[jm+12], t1, t2, t3);
            t1 = cmul(t1, wst);
        }
        #pragma unroll
        for (int rr = 0; rr < 4; ++rr)
            bf4_fwd(r[4*rr], r[4*rr+1], r[4*rr+2], r[4*rr+3], v1, v2, v3);
    } else {
        #pragma unroll
        for (int rr = 0; rr < 4; ++rr)
            bf4_inv(r[4*rr], r[4*rr+1], r[4*rr+2], r[4*rr+3], v1, v2, v3);
        float2 t1 = w1;
        #pragma unroll
        for (int jm = 0; jm < 4; ++jm){
            float2 t2 = csqr(t1), t3 = cmul(t1, t2);
            bf4_inv(r[jm], r[jm+4], r[jm+8], r[jm+12], t1, t2, t3);
            t1 = cmul(t1, wst);
        }
    }
    #pragma unroll
    for (int j = 0; j < 16; ++j) sm[pb + j * SP] = r[j];
    __syncthreads();
}

__device__ __forceinline__ void stage1_fwd_fused(float2* __restrict__ sm, int tid,
                                                 const float2* __restrict__ src){
    const int q  = tid;
    const int SP = 272;
    const int pb = SPAD(q);

    float2 r[16];
    #pragma unroll
    for (int j = 0; j < 8; ++j) r[j] = src[q + j * 256];

    float sn, cs;
    __sincosf(-PI_F * (float)q * (2.0f / 4096.0f), &sn, &cs);
    float2 w1 = make_float2(cs, sn);
    const float2 wst = make_float2(C8X, C8Y);
    float2 v1 = csqr(csqr(w1));
    float2 v2 = csqr(v1), v3 = cmul(v1, v2);

    float2 t1 = w1;
    #pragma unroll
    for (int jm = 0; jm < 4; ++jm){
        float2 t2 = csqr(t1), t3 = cmul(t1, t2);
        float2 a = r[jm], b = r[jm + 4];
        float2 ib = mi_pos(b);
        r[jm]      = cadd(a, b);
        r[jm + 4]  = cmul(csub(a, ib), t1);
        r[jm + 8]  = cmul(csub(a, b),  t2);
        r[jm + 12] = cmul(cadd(a, ib), t3);
        t1 = cmul(t1, wst);
    }
    #pragma unroll
    for (int rr = 0; rr < 4; ++rr)
        bf4_fwd(r[4*rr], r[4*rr+1], r[4*rr+2], r[4*rr+3], v1, v2, v3);
    #pragma unroll
    for (int j = 0; j < 16; ++j) sm[pb + j * SP] = r[j];
    __syncthreads();
}

__device__ __forceinline__ float gelu_erf(float x){
    return 0.5f * x * (1.0f + erff(x * 0.70710678118654752f));
}

// inverse stage 1 fused with bf16 hi/lo split epilogue
__device__ __forceinline__ void stage1_inv_fused_epi(float2* __restrict__ sm, int tid,
                                                     float dA,
                                                     const float2* __restrict__ uv,
                                                     __nv_bfloat162* __restrict__ ghv,
                                                     __nv_bfloat162* __restrict__ glv){
    const int q  = tid;
    const int SP = 272;
    const int pb = SPAD(q);

    float2 r[16];
    #pragma unroll
    for (int j = 0; j < 16; ++j) r[j] = sm[pb + j * SP];

    float sn, cs;
    __sincosf(-PI_F * (float)q * (2.0f / 4096.0f), &sn, &cs);
    float2 w1 = make_float2(cs, -sn);
    const float2 wst = make_float2(C8X, -C8Y);
    float2 v1 = csqr(csqr(w1));
    float2 v2 = csqr(v1), v3 = cmul(v1, v2);

    #pragma unroll
    for (int rr = 0; rr < 4; ++rr)
        bf4_inv(r[4*rr], r[4*rr+1], r[4*rr+2], r[4*rr+3], v1, v2, v3);

    float2 t1 = w1;
    #pragma unroll
    for (int jm = 0; jm < 4; ++jm){
        float2 t2 = csqr(t1), t3 = cmul(t1, t2);
        float2 z1 = cmul(r[jm+4],  t1);
        float2 z2 = cmul(r[jm+8],  t2);
        float2 z3 = cmul(r[jm+12], t3);
        float2 A  = cadd(r[jm], z2);
        float2 B  = csub(r[jm], z2);
        float2 Cc = cadd(z1, z3);
        float2 Dd = csub(z1, z3);
        r[jm]     = cadd(A, Cc);
        r[jm + 4] = cadd(B, mi_pos(Dd));
        t1 = cmul(t1, wst);
    }

    #pragma unroll
    for (int j = 0; j < 8; ++j){
        int l = q + j * 256;
        float2 uu = uv[l];
        float v0 = gelu_erf(r[j].x + dA * uu.x);
        float v1f = gelu_erf(r[j].y + dA * uu.y);
        __nv_bfloat162 hh = __floats2bfloat162_rn(v0, v1f);
        float r0 = v0  - __bfloat162float(__low2bfloat16(hh));
        float r1 = v1f - __bfloat162float(__high2bfloat16(hh));
        ghv[l] = hh;
        glv[l] = __floats2bfloat162_rn(r0, r1);
    }
}

template<bool INV>
__device__ __forceinline__ void stage_16_4(float2* __restrict__ sm, int tid){
    const int pb = tid * 17;
    float2 r[16];
    #pragma unroll
    for (int i = 0; i < 16; ++i) r[i] = sm[pb + i];

    const float CP8 = 0.92387953251128675613f;
    const float SP8 = 0.38268343236508977173f;
    const float R2  = 0.70710678118654752440f;
    const float C3  = 0.38268343236508977173f;
    const float S3v = 0.92387953251128675613f;
    const float sg = INV ? 1.f : -1.f;
    float2 W1[4] = { make_float2(1,0), make_float2(CP8, sg*SP8), make_float2(R2, sg*R2),   make_float2(C3, sg*S3v) };
    float2 W2[4] = { make_float2(1,0), make_float2(R2, sg*R2),   make_float2(0.f, sg),     make_float2(-R2, sg*R2) };
    float2 W3[4] = { make_float2(1,0), make_float2(C3, sg*S3v),  make_float2(-R2, sg*R2),  make_float2(-CP8, -sg*SP8) };

    if (!INV){
        #pragma unroll
        for (int q = 0; q < 4; ++q)
            bf4_fwd(r[q], r[q+4], r[q+8], r[q+12], W1[q], W2[q], W3[q]);
        #pragma unroll
        for (int g = 0; g < 4; ++g){
            float2 a=r[4*g], b=r[4*g+1], c=r[4*g+2], d=r[4*g+3];
            float2 t0=cadd(a,c), t1=csub(a,c), t2=cadd(b,d), t3=mi_neg(csub(b,d));
            r[4*g]=cadd(t0,t2); r[4*g+1]=cadd(t1,t3); r[4*g+2]=csub(t0,t2); r[4*g+3]=csub(t1,t3);
        }
    } else {
        #pragma unroll
        for (int g = 0; g < 4; ++g){
            float2 y0=r[4*g], y1=r[4*g+1], y2=r[4*g+2], y3=r[4*g+3];
            float2 A=cadd(y0,y2), B=csub(y0,y2), Cc=cadd(y1,y3), Dd=csub(y1,y3);
            float2 iD=mi_pos(Dd);
            r[4*g]=cadd(A,Cc); r[4*g+2]=csub(A,Cc);
            r[4*g+1]=cadd(B,iD); r[4*g+3]=csub(B,iD);
        }
        #pragma unroll
        for (int q = 0; q < 4; ++q)
            bf4_inv(r[q], r[q+4], r[q+8], r[q+12], W1[q], W2[q], W3[q]);
    }
    #pragma unroll
    for (int i = 0; i < 16; ++i) sm[pb + i] = r[i];
    __syncthreads();
}

// ---------------- Kernel A: filter spectra --------------------------------
__global__ __launch_bounds__(256, 5)
void kfft_kernel(const float* __restrict__ k){
    extern __shared__ char smraw[];
    float2* sm = (float2*)smraw;
    const int tid = threadIdx.x;
    const int h   = blockIdx.x;

    stage1_fwd_fused(sm, tid, (const float2*)(k + (size_t)h * 4096));
    stage16N<256, false>(sm, tid);
    stage_16_4<false>(sm, tid);

    const float sc = 1.0f / 4096.0f;
    float sn, cs;
    __sincosf(-PI_F * (float)tid * (1.0f/4096.0f), &sn, &cs);
    float2 w = make_float2(cs, sn);
    const float2 CS = make_float2(C16X, C16Y);
    float2* Kf = d_Kf + (size_t)h * 4097;
    #pragma unroll 1
    for (int j = tid; j <= 2048; j += 256){
        int jn = 4096 - j;
        float2 Zj = sm[SPAD(pos4(j & 4095))];
        float2 Zn = sm[SPAD(pos4(jn & 4095))];
        float2 E = make_float2(0.5f*(Zj.x + Zn.x), 0.5f*(Zj.y - Zn.y));
        float2 O = make_float2(0.5f*(Zj.y + Zn.y), 0.5f*(Zn.x - Zj.x));
        float2 T = cmul(w, O);
        float2 Xj = cadd(E, T);
        float2 Xn = conjf2(csub(E, T));
        Kf[j]  = make_float2(sc*Xj.x, sc*Xj.y);
        Kf[jn] = make_float2(sc*Xn.x, sc*Xn.y);
        w = cmul(w, CS);
    }
}

// ---------------- Kernel B: conv + skip + gelu + bf16 split ---------------
__global__ __launch_bounds__(256, 5)
void conv_kernel(const float* __restrict__ u, const float* __restrict__ D){
    extern __shared__ char smraw[];
    float2* sm = (float2*)smraw;
    const int tid = threadIdx.x;
    const int h   = blockIdx.x;
    const int b   = blockIdx.y;
    const float2* uv = (const float2*)(u + ((size_t)b * 512 + h) * 4096);

    stage1_fwd_fused(sm, tid, uv);
    stage16N<256, false>(sm, tid);
    stage_16_4<false>(sm, tid);

    const float2* Kf = d_Kf + (size_t)h * 4097;
    float sn, cs;
    __sincosf(-PI_F * (float)tid * (1.0f/4096.0f), &sn, &cs);
    float2 w = make_float2(cs, sn);
    const float2 CS = make_float2(C16X, C16Y);
    #pragma unroll 1
    for (int j = tid; j <= 2048; j += 256){
        int jn = 4096 - j;
        int sj  = SPAD(pos4(j & 4095));
        int sn2 = SPAD(pos4(jn & 4095));
        float2 Zj = sm[sj], Zn = sm[sn2];
        float2 E = make_float2(0.5f*(Zj.x + Zn.x), 0.5f*(Zj.y - Zn.y));
        float2 O = make_float2(0.5f*(Zj.y + Zn.y), 0.5f*(Zn.x - Zj.x));
        float2 T = cmul(w, O);
        float2 Xj = cadd(E, T);
        float2 Xn = conjf2(csub(E, T));
        float2 Yj = cmul(Xj, Kf[j]);
        float2 Yn = cmul(Xn, Kf[jn]);
        float2 P  = make_float2(0.5f*(Yj.x + Yn.x), 0.5f*(Yj.y - Yn.y));
        float2 Mv = make_float2(0.5f*(Yj.x - Yn.x), 0.5f*(Yj.y + Yn.y));
        sm[sj] = cadd(P, mi_pos(cmul(conjf2(w), Mv)));
        if (j != 0){
            float2 P2 = make_float2(0.5f*(Yn.x + Yj.x), 0.5f*(Yn.y - Yj.y));
            float2 M2 = make_float2(0.5f*(Yn.x - Yj.x), 0.5f*(Yn.y + Yj.y));
            sm[sn2] = cadd(P2, mi_neg(cmul(w, M2)));
        }
        w = cmul(w, CS);
    }
    __syncthreads();

    stage_16_4<true>(sm, tid);
    stage16N<256, true>(sm, tid);
    size_t rb = ((size_t)b * 512 + h) * 4096;
    stage1_inv_fused_epi(sm, tid, D[h], uv,
                         (__nv_bfloat162*)(d_gh + rb),
                         (__nv_bfloat162*)(d_gl + rb));
}

// ---------------- W split prep --------------------------------------------
__global__ __launch_bounds__(256)
void wsplit_kernel(const float* __restrict__ W){
    int i = blockIdx.x * 1024 + threadIdx.x;
    #pragma unroll
    for (int r = 0; r < 4; ++r){
        int idx = i + r * 256;
        float v = W[idx];
        __nv_bfloat16 hb = __float2bfloat16(v);
        d_Wh[idx] = hb;
        d_Wl[idx] = __float2bfloat16(v - __bfloat162float(hb));
    }
}

// ---------------- Kernel C: mma.sync bf16 split GEMM ----------------------
// out[b,d,l] = sum_h W[d,h] g[b,h,l] + bias[d]
// CTA 128(M=d) x 128(N=l), K chunks of 32, double-buffered cp.async.
// 8 warps, warp tile 64x32, m16n8k16 row.col HMMA, fp32 accum.
// Products: Wh*gh + Wh*gl + Wl*gh (Wl*gl dropped, ~2^-18).
//
// smem layout per buffer (bytes):
//   A (Wh,Wl): 2 x 128 rows x 40 bf16 (80B pitch) = 20480
//   B (gh,gl): 2 x 32 rows x 136 bf16 (272B pitch) = 17408
//   buffer stride 37888, two buffers = 75776 bytes.
#define GEMM_SMEM 75776

__device__ __forceinline__ uint32_t smem_u32(const void* p){
    uint32_t a;
    asm("{ .reg .u64 t; cvta.to.shared.u64 t, %1; cvt.u32.u64 %0, t; }" : "=r"(a) : "l"(p));
    return a;
}
__device__ __forceinline__ void cp16(uint32_t s, const void* g){
    asm volatile("cp.async.cg.shared.global [%0], [%1], 16;" :: "r"(s), "l"(__cvta_generic_to_global(g)));
}
__device__ __forceinline__ void ldmA(uint32_t* a, uint32_t addr){
    asm volatile("ldmatrix.sync.aligned.m8n8.x4.shared.b16 {%0,%1,%2,%3}, [%4];"
                 : "=r"(a[0]), "=r"(a[1]), "=r"(a[2]), "=r"(a[3]) : "r"(addr));
}
__device__ __forceinline__ void ldmB(uint32_t* bq, uint32_t addr){
    asm volatile("ldmatrix.sync.aligned.m8n8.x2.trans.shared.b16 {%0,%1}, [%2];"
                 : "=r"(bq[0]), "=r"(bq[1]) : "r"(addr));
}
__device__ __forceinline__ void mma16816(float* c, const uint32_t* a, const uint32_t* bq){
    asm volatile("mma.sync.aligned.m16n8k16.row.col.f32.bf16.bf16.f32 "
                 "{%0,%1,%2,%3}, {%4,%5,%6,%7}, {%8,%9}, {%0,%1,%2,%3};"
                 : "+f"(c[0]), "+f"(c[1]), "+f"(c[2]), "+f"(c[3])
                 : "r"(a[0]), "r"(a[1]), "r"(a[2]), "r"(a[3]), "r"(bq[0]), "r"(bq[1]));
}

__global__ __launch_bounds__(256, 2)
void gemm_kernel(const float* __restrict__ bias, float* __restrict__ out){
    extern __shared__ char smraw[];
    const int tid  = threadIdx.x;
    const int lane = tid & 31;
    const int wid  = tid >> 5;
    const int warp_m = wid >> 2;          // 0..1 (64 rows each)
    const int warp_n = wid & 3;           // 0..3 (32 cols each)
    const int l0 = blockIdx.x * 128;
    const int d0 = blockIdx.y * 128;
    const int bb = blockIdx.z;
    const uint32_t sb = smem_u32(smraw);

    float acc[4][4][4];
    #pragma unroll
    for (int mi = 0; mi < 4; ++mi)
        #pragma unroll
        for (int ni = 0; ni < 4; ++ni)
            #pragma unroll
            for (int q = 0; q < 4; ++q) acc[mi][ni][q] = 0.f;

    // per-lane ldmatrix base offsets (bytes, within buffer)
    const uint32_t aoff = ((warp_m * 64 + (lane & 15)) * 40 + ((lane >> 4) << 3)) * 2;
    const uint32_t boff = 20480 + ((lane & 15) * 136 + warp_n * 32) * 2;

    // chunk loader: 8 x 16B per thread
    auto load_chunk = [&](int kk, uint32_t bufo){
        #pragma unroll
        for (int i = 0; i < 8; ++i){
            int u = tid + (i << 8);
            if (u < 1024){
                int sp = u >> 9, m = (u >> 2) & 127, c = u & 3;
                uint32_t sa = sb + bufo + sp * 10240 + m * 80 + c * 16;
                const __nv_bfloat16* Wp = sp ? d_Wl : d_Wh;
                cp16(sa, Wp + (((size_t)(d0 + m)) << 9) + (kk << 5) + (c << 3));
            } else {
                int v = u - 1024;
                int sp = v >> 9, kr = (v >> 4) & 31, c = v & 15;
                uint32_t sa = sb + bufo + 20480 + sp * 8704 + kr * 272 + c * 16;
                const __nv_bfloat16* Gp = sp ? d_gl : d_gh;
                cp16(sa, Gp + (((size_t)(bb * 512 + (kk << 5) + kr)) << 12) + l0 + (c << 3));
            }
        }
        asm volatile("cp.async.commit_group;");
    };

    load_chunk(0, 0);

    #pragma unroll 1
    for (int kk = 0; kk < 16; ++kk){
        const uint32_t bufo = (kk & 1) ? 37888u : 0u;
        if (kk + 1 < 16){
            load_chunk(kk + 1, (kk & 1) ? 0u : 37888u);
            asm volatile("cp.async.wait_group 1;" ::: "memory");
        } else {
            asm volatile("cp.async.wait_group 0;" ::: "memory");
        }
        __syncthreads();

        #pragma unroll
        for (int ks = 0; ks < 2; ++ks){
            const uint32_t aA = sb + bufo + aoff + ks * 32;           // +16 cols = 32B
            const uint32_t aB = sb + bufo + boff + ks * 16 * 272;     // +16 k rows
            uint32_t a[4][4], bh[4][2], bl[4][2];
            #pragma unroll
            for (int mi = 0; mi < 4; ++mi) ldmA(a[mi], aA + mi * 1280);
            #pragma unroll
            for (int ni = 0; ni < 4; ++ni) ldmB(bh[ni], aB + ni * 16);
            #pragma unroll
            for (int mi = 0; mi < 4; ++mi)
                #pragma unroll
                for (int ni = 0; ni < 4; ++ni) mma16816(acc[mi][ni], a[mi], bh[ni]);
            #pragma unroll
            for (int ni = 0; ni < 4; ++ni) ldmB(bl[ni], aB + 8704 + ni * 16);
            #pragma unroll
            for (int mi = 0; mi < 4; ++mi)
                #pragma unroll
                for (int ni = 0; ni < 4; ++ni) mma16816(acc[mi][ni], a[mi], bl[ni]);
            #pragma unroll
            for (int mi = 0; mi < 4; ++mi) ldmA(a[mi], aA + 10240 + mi * 1280);
            #pragma unroll
            for (int mi = 0; mi < 4; ++mi)
                #pragma unroll
                for (int ni = 0; ni < 4; ++ni) mma16816(acc[mi][ni], a[mi], bh[ni]);
        }
        __syncthreads();
    }

    // epilogue: fragment (c0,c1)->row lane/4, cols 2*(lane%3..); (c2,c3)->row+8
    #pragma unroll
    for (int mi = 0; mi < 4; ++mi){
        int r0 = d0 + warp_m * 64 + mi * 16 + (lane >> 2);
        float bv0 = bias[r0], bv1 = bias[r0 + 8];
        float* p0 = out + (((size_t)(bb * 512 + r0)) << 12) + l0 + warp_n * 32 + (lane & 3) * 2;
        float* p1 = p0 + ((size_t)8 << 12);
        #pragma unroll
        for (int ni = 0; ni < 4; ++ni){
            *(float2*)(p0 + ni * 8) = make_float2(acc[mi][ni][0] + bv0, acc[mi][ni][1] + bv0);
            *(float2*)(p1 + ni * 8) = make_float2(acc[mi][ni][2] + bv1, acc[mi][ni][3] + bv1);
        }
    }
}

// ---------------- Launch ---------------------------------------------------
extern "C" void kernel_launch(void* const* d_in, const int* in_sizes, int n_in,
                              void* d_out, int out_size){
    const float* u    = (const float*)d_in[0];   // (8, 512, 4096)
    const float* k    = (const float*)d_in[1];   // (1, 512, 4096)
    const float* D    = (const float*)d_in[2];   // (1, 512)
    const float* W    = (const float*)d_in[3];   // (512, 512)
    const float* bias = (const float*)d_in[4];   // (512,)
    float* out = (float*)d_out;                  // (8, 512, 4096)

    const size_t smem = 4352 * sizeof(float2);   // 34 KB for FFT kernels
    cudaFuncSetAttribute(kfft_kernel, cudaFuncAttributeMaxDynamicSharedMemorySize, (int)smem);
    cudaFuncSetAttribute(conv_kernel, cudaFuncAttributeMaxDynamicSharedMemorySize, (int)smem);
    cudaFuncSetAttribute(gemm_kernel, cudaFuncAttributeMaxDynamicSharedMemorySize, GEMM_SMEM);

    wsplit_kernel<<<256, 256>>>(W);
    kfft_kernel<<<512, 256, smem>>>(k);
    conv_kernel<<<dim3(512, 8), 256, smem>>>(u, D);
    gemm_kernel<<<dim3(4096 / 128, 512 / 128, 8), 256, GEMM_SMEM>>>(bias, out);
}

// round 14
// speedup vs baseline: 2.4244x; 1.0079x over previous
#include <cuda_runtime.h>
#include <cuda_bf16.h>
#include <cstdint>
#include <math.h>

#define PI_F 3.14159265358979323846f

// Scratch (allocation-free rule: __device__ globals)
__device__ float2 d_Kf[512 * 4097];                    // filter half-spectra
__device__ __nv_bfloat16 d_gh[8ULL * 512 * 4096];      // gelu(conv+skip) hi
__device__ __nv_bfloat16 d_gl[8ULL * 512 * 4096];      // gelu(conv+skip) lo
__device__ __nv_bfloat16 d_Wh[512 * 512];              // W hi
__device__ __nv_bfloat16 d_Wl[512 * 512];              // W lo

// ---------------- complex helpers ----------------------------------------
__device__ __forceinline__ float2 cadd(float2 a, float2 b){ return make_float2(a.x+b.x, a.y+b.y); }
__device__ __forceinline__ float2 csub(float2 a, float2 b){ return make_float2(a.x-b.x, a.y-b.y); }
__device__ __forceinline__ float2 cmul(float2 a, float2 b){
    return make_float2(fmaf(a.x, b.x, -a.y*b.y), fmaf(a.x, b.y, a.y*b.x));
}
__device__ __forceinline__ float2 csqr(float2 a){
    return make_float2(fmaf(a.x,a.x,-a.y*a.y), 2.f*a.x*a.y);
}
__device__ __forceinline__ float2 conjf2(float2 a){ return make_float2(a.x, -a.y); }
__device__ __forceinline__ float2 mi_neg(float2 a){ return make_float2(a.y, -a.x); }
__device__ __forceinline__ float2 mi_pos(float2 a){ return make_float2(-a.y, a.x); }

__device__ __forceinline__ void bf4_fwd(float2&a, float2&b, float2&c, float2&d,
                                        float2 w1, float2 w2, float2 w3){
    float2 t0=cadd(a,c), t1=csub(a,c), t2=cadd(b,d), t3=mi_neg(csub(b,d));
    a = cadd(t0,t2);
    b = cmul(cadd(t1,t3), w1);
    c = cmul(csub(t0,t2), w2);
    d = cmul(csub(t1,t3), w3);
}
__device__ __forceinline__ void bf4_inv(float2&a, float2&b, float2&c, float2&d,
                                        float2 w1c, float2 w2c, float2 w3c){
    float2 z1=cmul(b,w1c), z2=cmul(c,w2c), z3=cmul(d,w3c);
    float2 A=cadd(a,z2), B=csub(a,z2), Cc=cadd(z1,z3), Dd=csub(z1,z3);
    float2 iD = mi_pos(Dd);
    a = cadd(A,Cc); c = csub(A,Cc);
    b = cadd(B,iD); d = csub(B,iD);
}

#define SPAD(i) ((i) + ((i) >> 4))

__device__ __forceinline__ int pos4(int j){
    int y = __brev((unsigned)j) >> 20;
    return ((y & 0x555) << 1) | ((y >> 1) & 0x555);
}

#define C8X 0.92387953251128675613f
#define C8Y (-0.38268343236508977173f)
#define C16X 0.98078528040323044913f
#define C16Y (-0.19509032201612826785f)

template<int M, bool INV>
__device__ __forceinline__ void stage16N(float2* __restrict__ sm, int tid){
    const int S  = M >> 4;
    const int SP = S + (S >> 4);
    const int g  = (M == 4096) ? 0   : (tid >> 4);
    const int q  = (M == 4096) ? tid : (tid & 15);
    const int pb = SPAD(g * M + q);

    float2 r[16];
    #pragma unroll
    for (int j = 0; j < 16; ++j) r[j] = sm[pb + j * SP];

    float sn, cs;
    __sincosf(-PI_F * (float)q * (2.0f / (float)M), &sn, &cs);
    float2 w1 = make_float2(cs, INV ? -sn : sn);
    const float2 wst = make_float2(C8X, INV ? -C8Y : C8Y);
    float2 v1 = csqr(csqr(w1));
    float2 v2 = csqr(v1), v3 = cmul(v1, v2);

    if (!INV){
        float2 t1 = w1;
        #pragma unroll
        for (int jm = 0; jm < 4; ++jm){
            float2 t2 = csqr(t1), t3 = cmul(t1, t2);
            bf4_fwd(r[jm], r[jm+4], r[jm+8], r[jm+12], t1, t2, t3);
            t1 = cmul(t1, wst);
        }
        #pragma unroll
        for (int rr = 0; rr < 4; ++rr)
            bf4_fwd(r[4*rr], r[4*rr+1], r[4*rr+2], r[4*rr+3], v1, v2, v3);
    } else {
        #pragma unroll
        for (int rr = 0; rr < 4; ++rr)
            bf4_inv(r[4*rr], r[4*rr+1], r[4*rr+2], r[4*rr+3], v1, v2, v3);
        float2 t1 = w1;
        #pragma unroll
        for (int jm = 0; jm < 4; ++jm){
            float2 t2 = csqr(t1), t3 = cmul(t1, t2);
            bf4_inv(r[jm], r[jm+4], r[jm+8], r[jm+12], t1, t2, t3);
            t1 = cmul(t1, wst);
        }
    }
    #pragma unroll
    for (int j = 0; j < 16; ++j) sm[pb + j * SP] = r[j];
    __syncthreads();
}

__device__ __forceinline__ void stage1_fwd_fused(float2* __restrict__ sm, int tid,
                                                 const float2* __restrict__ src){
    const int q  = tid;
    const int SP = 272;
    const int pb = SPAD(q);

    float2 r[16];
    #pragma unroll
    for (int j = 0; j < 8; ++j) r[j] = src[q + j * 256];

    float sn, cs;
    __sincosf(-PI_F * (float)q * (2.0f / 4096.0f), &sn, &cs);
    float2 w1 = make_float2(cs, sn);
    const float2 wst = make_float2(C8X, C8Y);
    float2 v1 = csqr(csqr(w1));
    float2 v2 = csqr(v1), v3 = cmul(v1, v2);

    float2 t1 = w1;
    #pragma unroll
    for (int jm = 0; jm < 4; ++jm){
        float2 t2 = csqr(t1), t3 = cmul(t1, t2);
        float2 a = r[jm], b = r[jm + 4];
        float2 ib = mi_pos(b);
        r[jm]      = cadd(a, b);
        r[jm + 4]  = cmul(csub(a, ib), t1);
        r[jm + 8]  = cmul(csub(a, b),  t2);
        r[jm + 12] = cmul(cadd(a, ib), t3);
        t1 = cmul(t1, wst);
    }
    #pragma unroll
    for (int rr = 0; rr < 4; ++rr)
        bf4_fwd(r[4*rr], r[4*rr+1], r[4*rr+2], r[4*rr+3], v1, v2, v3);
    #pragma unroll
    for (int j = 0; j < 16; ++j) sm[pb + j * SP] = r[j];
    __syncthreads();
}

__device__ __forceinline__ float gelu_erf(float x){
    return 0.5f * x * (1.0f + erff(x * 0.70710678118654752f));
}

// inverse stage 1 fused with bf16 hi/lo split epilogue
__device__ __forceinline__ void stage1_inv_fused_epi(float2* __restrict__ sm, int tid,
                                                     float dA,
                                                     const float2* __restrict__ uv,
                                                     __nv_bfloat162* __restrict__ ghv,
                                                     __nv_bfloat162* __restrict__ glv){
    const int q  = tid;
    const int SP = 272;
    const int pb = SPAD(q);

    float2 r[16];
    #pragma unroll
    for (int j = 0; j < 16; ++j) r[j] = sm[pb + j * SP];

    float sn, cs;
    __sincosf(-PI_F * (float)q * (2.0f / 4096.0f), &sn, &cs);
    float2 w1 = make_float2(cs, -sn);
    const float2 wst = make_float2(C8X, -C8Y);
    float2 v1 = csqr(csqr(w1));
    float2 v2 = csqr(v1), v3 = cmul(v1, v2);

    #pragma unroll
    for (int rr = 0; rr < 4; ++rr)
        bf4_inv(r[4*rr], r[4*rr+1], r[4*rr+2], r[4*rr+3], v1, v2, v3);

    float2 t1 = w1;
    #pragma unroll
    for (int jm = 0; jm < 4; ++jm){
        float2 t2 = csqr(t1), t3 = cmul(t1, t2);
        float2 z1 = cmul(r[jm+4],  t1);
        float2 z2 = cmul(r[jm+8],  t2);
        float2 z3 = cmul(r[jm+12], t3);
        float2 A  = cadd(r[jm], z2);
        float2 B  = csub(r[jm], z2);
        float2 Cc = cadd(z1, z3);
        float2 Dd = csub(z1, z3);
        r[jm]     = cadd(A, Cc);
        r[jm + 4] = cadd(B, mi_pos(Dd));
        t1 = cmul(t1, wst);
    }

    #pragma unroll
    for (int j = 0; j < 8; ++j){
        int l = q + j * 256;
        float2 uu = uv[l];
        float v0 = gelu_erf(r[j].x + dA * uu.x);
        float v1f = gelu_erf(r[j].y + dA * uu.y);
        __nv_bfloat162 hh = __floats2bfloat162_rn(v0, v1f);
        float r0 = v0  - __bfloat162float(__low2bfloat16(hh));
        float r1 = v1f - __bfloat162float(__high2bfloat16(hh));
        ghv[l] = hh;
        glv[l] = __floats2bfloat162_rn(r0, r1);
    }
}

template<bool INV>
__device__ __forceinline__ void stage_16_4(float2* __restrict__ sm, int tid){
    const int pb = tid * 17;
    float2 r[16];
    #pragma unroll
    for (int i = 0; i < 16; ++i) r[i] = sm[pb + i];

    const float CP8 = 0.92387953251128675613f;
    const float SP8 = 0.38268343236508977173f;
    const float R2  = 0.70710678118654752440f;
    const float C3  = 0.38268343236508977173f;
    const float S3v = 0.92387953251128675613f;
    const float sg = INV ? 1.f : -1.f;
    float2 W1[4] = { make_float2(1,0), make_float2(CP8, sg*SP8), make_float2(R2, sg*R2),   make_float2(C3, sg*S3v) };
    float2 W2[4] = { make_float2(1,0), make_float2(R2, sg*R2),   make_float2(0.f, sg),     make_float2(-R2, sg*R2) };
    float2 W3[4] = { make_float2(1,0), make_float2(C3, sg*S3v),  make_float2(-R2, sg*R2),  make_float2(-CP8, -sg*SP8) };

    if (!INV){
        #pragma unroll
        for (int q = 0; q < 4; ++q)
            bf4_fwd(r[q], r[q+4], r[q+8], r[q+12], W1[q], W2[q], W3[q]);
        #pragma unroll
        for (int g = 0; g < 4; ++g){
            float2 a=r[4*g], b=r[4*g+1], c=r[4*g+2], d=r[4*g+3];
            float2 t0=cadd(a,c), t1=csub(a,c), t2=cadd(b,d), t3=mi_neg(csub(b,d));
            r[4*g]=cadd(t0,t2); r[4*g+1]=cadd(t1,t3); r[4*g+2]=csub(t0,t2); r[4*g+3]=csub(t1,t3);
        }
    } else {
        #pragma unroll
        for (int g = 0; g < 4; ++g){
            float2 y0=r[4*g], y1=r[4*g+1], y2=r[4*g+2], y3=r[4*g+3];
            float2 A=cadd(y0,y2), B=csub(y0,y2), Cc=cadd(y1,y3), Dd=csub(y1,y3);
            float2 iD=mi_pos(Dd);
            r[4*g]=cadd(A,Cc); r[4*g+2]=csub(A,Cc);
            r[4*g+1]=cadd(B,iD); r[4*g+3]=csub(B,iD);
        }
        #pragma unroll
        for (int q = 0; q < 4; ++q)
            bf4_inv(r[q], r[q+4], r[q+8], r[q+12], W1[q], W2[q], W3[q]);
    }
    #pragma unroll
    for (int i = 0; i < 16; ++i) sm[pb + i] = r[i];
    __syncthreads();
}

// ---------------- Kernel A: filter spectra --------------------------------
__global__ __launch_bounds__(256, 5)
void kfft_kernel(const float* __restrict__ k){
    extern __shared__ char smraw[];
    float2* sm = (float2*)smraw;
    const int tid = threadIdx.x;
    const int h   = blockIdx.x;

    stage1_fwd_fused(sm, tid, (const float2*)(k + (size_t)h * 4096));
    stage16N<256, false>(sm, tid);
    stage_16_4<false>(sm, tid);

    const float sc = 1.0f / 4096.0f;
    float sn, cs;
    __sincosf(-PI_F * (float)tid * (1.0f/4096.0f), &sn, &cs);
    float2 w = make_float2(cs, sn);
    const float2 CS = make_float2(C16X, C16Y);
    float2* Kf = d_Kf + (size_t)h * 4097;
    #pragma unroll 1
    for (int j = tid; j <= 2048; j += 256){
        int jn = 4096 - j;
        float2 Zj = sm[SPAD(pos4(j & 4095))];
        float2 Zn = sm[SPAD(pos4(jn & 4095))];
        float2 E = make_float2(0.5f*(Zj.x + Zn.x), 0.5f*(Zj.y - Zn.y));
        float2 O = make_float2(0.5f*(Zj.y + Zn.y), 0.5f*(Zn.x - Zj.x));
        float2 T = cmul(w, O);
        float2 Xj = cadd(E, T);
        float2 Xn = conjf2(csub(E, T));
        Kf[j]  = make_float2(sc*Xj.x, sc*Xj.y);
        Kf[jn] = make_float2(sc*Xn.x, sc*Xn.y);
        w = cmul(w, CS);
    }
}

// ---------------- Kernel B: conv + skip + gelu + bf16 split ---------------
__global__ __launch_bounds__(256, 5)
void conv_kernel(const float* __restrict__ u, const float* __restrict__ D){
    extern __shared__ char smraw[];
    float2* sm = (float2*)smraw;
    const int tid = threadIdx.x;
    const int h   = blockIdx.x;
    const int b   = blockIdx.y;
    const float2* uv = (const float2*)(u + ((size_t)b * 512 + h) * 4096);

    stage1_fwd_fused(sm, tid, uv);
    stage16N<256, false>(sm, tid);
    stage_16_4<false>(sm, tid);

    const float2* Kf = d_Kf + (size_t)h * 4097;
    float sn, cs;
    __sincosf(-PI_F * (float)tid * (1.0f/4096.0f), &sn, &cs);
    float2 w = make_float2(cs, sn);
    const float2 CS = make_float2(C16X, C16Y);
    #pragma unroll 1
    for (int j = tid; j <= 2048; j += 256){
        int jn = 4096 - j;
        int sj  = SPAD(pos4(j & 4095));
        int sn2 = SPAD(pos4(jn & 4095));
        float2 Zj = sm[sj], Zn = sm[sn2];
        float2 E = make_float2(0.5f*(Zj.x + Zn.x), 0.5f*(Zj.y - Zn.y));
        float2 O = make_float2(0.5f*(Zj.y + Zn.y), 0.5f*(Zn.x - Zj.x));
        float2 T = cmul(w, O);
        float2 Xj = cadd(E, T);
        float2 Xn = conjf2(csub(E, T));
        float2 Yj = cmul(Xj, Kf[j]);
        float2 Yn = cmul(Xn, Kf[jn]);
        float2 P  = make_float2(0.5f*(Yj.x + Yn.x), 0.5f*(Yj.y - Yn.y));
        float2 Mv = make_float2(0.5f*(Yj.x - Yn.x), 0.5f*(Yj.y + Yn.y));
        sm[sj] = cadd(P, mi_pos(cmul(conjf2(w), Mv)));
        if (j != 0){
            float2 P2 = make_float2(0.5f*(Yn.x + Yj.x), 0.5f*(Yn.y - Yj.y));
            float2 M2 = make_float2(0.5f*(Yn.x - Yj.x), 0.5f*(Yn.y + Yj.y));
            sm[sn2] = cadd(P2, mi_neg(cmul(w, M2)));
        }
        w = cmul(w, CS);
    }
    __syncthreads();

    stage_16_4<true>(sm, tid);
    stage16N<256, true>(sm, tid);
    size_t rb = ((size_t)b * 512 + h) * 4096;
    stage1_inv_fused_epi(sm, tid, D[h], uv,
                         (__nv_bfloat162*)(d_gh + rb),
                         (__nv_bfloat162*)(d_gl + rb));
}

// ---------------- W split prep --------------------------------------------
__global__ __launch_bounds__(256)
void wsplit_kernel(const float* __restrict__ W){
    int i = blockIdx.x * 1024 + threadIdx.x;
    #pragma unroll
    for (int r = 0; r < 4; ++r){
        int idx = i + r * 256;
        float v = W[idx];
        __nv_bfloat16 hb = __float2bfloat16(v);
        d_Wh[idx] = hb;
        d_Wl[idx] = __float2bfloat16(v - __bfloat162float(hb));
    }
}

// ---------------- Kernel C: mma.sync bf16 split GEMM ----------------------
// out[b,d,l] = sum_h W[d,h] g[b,h,l] + bias[d]
// CTA 128(M=d) x 128(N=l), K chunks of 32, 3-stage cp.async pipeline,
// ONE __syncthreads per chunk. 8 warps, warp tile 64x32, m16n8k16 HMMA.
// Products: Wh*gh + Wh*gl + Wl*gh (Wl*gl dropped, ~2^-18).
//
// smem per stage (bytes): A 2x128x80B = 20480, B 2x32x272B = 17408 -> 37888
// 3 stages = 113664 bytes (2 CTA/SM = 222KB).
#define GSTAGE 37888
#define GEMM_SMEM (3 * GSTAGE)

__device__ __forceinline__ uint32_t smem_u32(const void* p){
    uint32_t a;
    asm("{ .reg .u64 t; cvta.to.shared.u64 t, %1; cvt.u32.u64 %0, t; }" : "=r"(a) : "l"(p));
    return a;
}
__device__ __forceinline__ void cp16(uint32_t s, const void* g){
    asm volatile("cp.async.cg.shared.global [%0], [%1], 16;" :: "r"(s), "l"(__cvta_generic_to_global(g)));
}
__device__ __forceinline__ void ldmA(uint32_t* a, uint32_t addr){
    asm volatile("ldmatrix.sync.aligned.m8n8.x4.shared.b16 {%0,%1,%2,%3}, [%4];"
                 : "=r"(a[0]), "=r"(a[1]), "=r"(a[2]), "=r"(a[3]) : "r"(addr));
}
__device__ __forceinline__ void ldmB(uint32_t* bq, uint32_t addr){
    asm volatile("ldmatrix.sync.aligned.m8n8.x2.trans.shared.b16 {%0,%1}, [%2];"
                 : "=r"(bq[0]), "=r"(bq[1]) : "r"(addr));
}
__device__ __forceinline__ void mma16816(float* c, const uint32_t* a, const uint32_t* bq){
    asm volatile("mma.sync.aligned.m16n8k16.row.col.f32.bf16.bf16.f32 "
                 "{%0,%1,%2,%3}, {%4,%5,%6,%7}, {%8,%9}, {%0,%1,%2,%3};"
                 : "+f"(c[0]), "+f"(c[1]), "+f"(c[2]), "+f"(c[3])
                 : "r"(a[0]), "r"(a[1]), "r"(a[2]), "r"(a[3]), "r"(bq[0]), "r"(bq[1]));
}

__global__ __launch_bounds__(256, 2)
void gemm_kernel(const float* __restrict__ bias, float* __restrict__ out){
    extern __shared__ char smraw[];
    const int tid  = threadIdx.x;
    const int lane = tid & 31;
    const int wid  = tid >> 5;
    const int warp_m = wid >> 2;          // 0..1 (64 rows each)
    const int warp_n = wid & 3;           // 0..3 (32 cols each)
    const int l0 = blockIdx.x * 128;
    const int d0 = blockIdx.y * 128;
    const int bb = blockIdx.z;
    const uint32_t sb = smem_u32(smraw);

    float acc[4][4][4];
    #pragma unroll
    for (int mi = 0; mi < 4; ++mi)
        #pragma unroll
        for (int ni = 0; ni < 4; ++ni)
            #pragma unroll
            for (int q = 0; q < 4; ++q) acc[mi][ni][q] = 0.f;

    // per-lane ldmatrix base offsets (bytes, within stage)
    const uint32_t aoff = ((warp_m * 64 + (lane & 15)) * 40 + ((lane >> 4) << 3)) * 2;
    const uint32_t boff = 20480 + ((lane & 15) * 136 + warp_n * 32) * 2;

    // chunk loader: 8 x 16B per thread into a given stage
    auto load_chunk = [&](int kk, uint32_t bufo){
        #pragma unroll
        for (int i = 0; i < 8; ++i){
            int u = tid + (i << 8);
            if (u < 1024){
                int sp = u >> 9, m = (u >> 2) & 127, c = u & 3;
                uint32_t sa = sb + bufo + sp * 10240 + m * 80 + c * 16;
                const __nv_bfloat16* Wp = sp ? d_Wl : d_Wh;
                cp16(sa, Wp + (((size_t)(d0 + m)) << 9) + (kk << 5) + (c << 3));
            } else {
                int v = u - 1024;
                int sp = v >> 9, kr = (v >> 4) & 31, c = v & 15;
                uint32_t sa = sb + bufo + 20480 + sp * 8704 + kr * 272 + c * 16;
                const __nv_bfloat16* Gp = sp ? d_gl : d_gh;
                cp16(sa, Gp + (((size_t)(bb * 512 + (kk << 5) + kr)) << 12) + l0 + (c << 3));
            }
        }
        asm volatile("cp.async.commit_group;");
    };

    // prologue: stages 0 and 1 in flight
    load_chunk(0, 0u);
    load_chunk(1, GSTAGE);

    #pragma unroll 1
    for (int kk = 0; kk < 16; ++kk){
        // chunk kk resident (allow the kk+1 group to stay in flight)
        if (kk + 1 < 16)
            asm volatile("cp.async.wait_group 1;" ::: "memory");
        else
            asm volatile("cp.async.wait_group 0;" ::: "memory");
        __syncthreads();   // also guarantees stage (kk+2)%3 fully consumed

        if (kk + 2 < 16)
            load_chunk(kk + 2, (uint32_t)(((kk + 2) % 3) * GSTAGE));

        const uint32_t bufo = (uint32_t)((kk % 3) * GSTAGE);
        #pragma unroll
        for (int ks = 0; ks < 2; ++ks){
            const uint32_t aA = sb + bufo + aoff + ks * 32;           // +16 cols = 32B
            const uint32_t aB = sb + bufo + boff + ks * 16 * 272;     // +16 k rows
            uint32_t a[4][4], bh[4][2], bl[4][2];
            #pragma unroll
            for (int mi = 0; mi < 4; ++mi) ldmA(a[mi], aA + mi * 1280);
            #pragma unroll
            for (int ni = 0; ni < 4; ++ni) ldmB(bh[ni], aB + ni * 16);
            #pragma unroll
            for (int mi = 0; mi < 4; ++mi)
                #pragma unroll
                for (int ni = 0; ni < 4; ++ni) mma16816(acc[mi][ni], a[mi], bh[ni]);
            #pragma unroll
            for (int ni = 0; ni < 4; ++ni) ldmB(bl[ni], aB + 8704 + ni * 16);
            #pragma unroll
            for (int mi = 0; mi < 4; ++mi)
                #pragma unroll
                for (int ni = 0; ni < 4; ++ni) mma16816(acc[mi][ni], a[mi], bl[ni]);
            #pragma unroll
            for (int mi = 0; mi < 4; ++mi) ldmA(a[mi], aA + 10240 + mi * 1280);
            #pragma unroll
            for (int mi = 0; mi < 4; ++mi)
                #pragma unroll
                for (int ni = 0; ni < 4; ++ni) mma16816(acc[mi][ni], a[mi], bh[ni]);
        }
    }

    // epilogue: m16n8 fragment rows lane>>2 and +8; cols 2*(lane&3) within n8
    #pragma unroll
    for (int mi = 0; mi < 4; ++mi){
        int r0 = d0 + warp_m * 64 + mi * 16 + (lane >> 2);
        float bv0 = bias[r0], bv1 = bias[r0 + 8];
        float* p0 = out + (((size_t)(bb * 512 + r0)) << 12) + l0 + warp_n * 32 + (lane & 3) * 2;
        float* p1 = p0 + ((size_t)8 << 12);
        #pragma unroll
        for (int ni = 0; ni < 4; ++ni){
            *(float2*)(p0 + ni * 8) = make_float2(acc[mi][ni][0] + bv0, acc[mi][ni][1] + bv0);
            *(float2*)(p1 + ni * 8) = make_float2(acc[mi][ni][2] + bv1, acc[mi][ni][3] + bv1);
        }
    }
}

// ---------------- Launch ---------------------------------------------------
extern "C" void kernel_launch(void* const* d_in, const int* in_sizes, int n_in,
                              void* d_out, int out_size){
    const float* u    = (const float*)d_in[0];   // (8, 512, 4096)
    const float* k    = (const float*)d_in[1];   // (1, 512, 4096)
    const float* D    = (const float*)d_in[2];   // (1, 512)
    const float* W    = (const float*)d_in[3];   // (512, 512)
    const float* bias = (const float*)d_in[4];   // (512,)
    float* out = (float*)d_out;                  // (8, 512, 4096)

    const size_t smem = 4352 * sizeof(float2);   // 34 KB for FFT kernels
    cudaFuncSetAttribute(kfft_kernel, cudaFuncAttributeMaxDynamicSharedMemorySize, (int)smem);
    cudaFuncSetAttribute(conv_kernel, cudaFuncAttributeMaxDynamicSharedMemorySize, (int)smem);
    cudaFuncSetAttribute(gemm_kernel, cudaFuncAttributeMaxDynamicSharedMemorySize, GEMM_SMEM);

    wsplit_kernel<<<256, 256>>>(W);
    kfft_kernel<<<512, 256, smem>>>(k);
    conv_kernel<<<dim3(512, 8), 256, smem>>>(u, D);
    gemm_kernel<<<dim3(4096 / 128, 512 / 128, 8), 256, GEMM_SMEM>>>(bias, out);
}

// round 15
// speedup vs baseline: 3.0850x; 1.2725x over previous
#include <cuda_runtime.h>
#include <cuda_bf16.h>
#include <cstdint>
#include <math.h>

#define PI_F 3.14159265358979323846f

// Scratch (allocation-free rule: __device__ globals)
__device__ float2 d_Kf[512 * 4097];                    // filter half-spectra
__device__ __nv_bfloat16 d_gh[8ULL * 512 * 4096];      // gelu(conv+skip) hi
__device__ __nv_bfloat16 d_gl[8ULL * 512 * 4096];      // gelu(conv+skip) lo
__device__ __nv_bfloat16 d_Wh[512 * 512];              // W hi
__device__ __nv_bfloat16 d_Wl[512 * 512];              // W lo

// ---------------- complex helpers ----------------------------------------
__device__ __forceinline__ float2 cadd(float2 a, float2 b){ return make_float2(a.x+b.x, a.y+b.y); }
__device__ __forceinline__ float2 csub(float2 a, float2 b){ return make_float2(a.x-b.x, a.y-b.y); }
__device__ __forceinline__ float2 cmul(float2 a, float2 b){
    return make_float2(fmaf(a.x, b.x, -a.y*b.y), fmaf(a.x, b.y, a.y*b.x));
}
__device__ __forceinline__ float2 csqr(float2 a){
    return make_float2(fmaf(a.x,a.x,-a.y*a.y), 2.f*a.x*a.y);
}
__device__ __forceinline__ float2 conjf2(float2 a){ return make_float2(a.x, -a.y); }
__device__ __forceinline__ float2 mi_neg(float2 a){ return make_float2(a.y, -a.x); }
__device__ __forceinline__ float2 mi_pos(float2 a){ return make_float2(-a.y, a.x); }

__device__ __forceinline__ void bf4_fwd(float2&a, float2&b, float2&c, float2&d,
                                        float2 w1, float2 w2, float2 w3){
    float2 t0=cadd(a,c), t1=csub(a,c), t2=cadd(b,d), t3=mi_neg(csub(b,d));
    a = cadd(t0,t2);
    b = cmul(cadd(t1,t3), w1);
    c = cmul(csub(t0,t2), w2);
    d = cmul(csub(t1,t3), w3);
}
__device__ __forceinline__ void bf4_inv(float2&a, float2&b, float2&c, float2&d,
                                        float2 w1c, float2 w2c, float2 w3c){
    float2 z1=cmul(b,w1c), z2=cmul(c,w2c), z3=cmul(d,w3c);
    float2 A=cadd(a,z2), B=csub(a,z2), Cc=cadd(z1,z3), Dd=csub(z1,z3);
    float2 iD = mi_pos(Dd);
    a = cadd(A,Cc); c = csub(A,Cc);
    b = cadd(B,iD); d = csub(B,iD);
}

// second-order smem padding: breaks the 1024/256/64 stride degeneracy of the
// digit-reversed pointwise gather (16-way -> 2-way bank conflicts) while
// staying linear (carry-free) for every stage stride used below.
#define SPAD(i) ((i) + ((i) >> 4) + ((i) >> 8))
#define SMEM_F2 4368   // SPAD(4095) = 4365, rounded up

__device__ __forceinline__ int pos4(int j){
    int y = __brev((unsigned)j) >> 20;
    return ((y & 0x555) << 1) | ((y >> 1) & 0x555);
}

#define C8X 0.92387953251128675613f
#define C8Y (-0.38268343236508977173f)
#define C16X 0.98078528040323044913f
#define C16Y (-0.19509032201612826785f)

template<int M, bool INV>
__device__ __forceinline__ void stage16N(float2* __restrict__ sm, int tid){
    const int S  = M >> 4;
    const int SP = S + (S >> 4) + (S >> 8);
    const int g  = (M == 4096) ? 0   : (tid >> 4);
    const int q  = (M == 4096) ? tid : (tid & 15);
    const int pb = SPAD(g * M + q);

    float2 r[16];
    #pragma unroll
    for (int j = 0; j < 16; ++j) r[j] = sm[pb + j * SP];

    float sn, cs;
    __sincosf(-PI_F * (float)q * (2.0f / (float)M), &sn, &cs);
    float2 w1 = make_float2(cs, INV ? -sn : sn);
    const float2 wst = make_float2(C8X, INV ? -C8Y : C8Y);
    float2 v1 = csqr(csqr(w1));
    float2 v2 = csqr(v1), v3 = cmul(v1, v2);

    if (!INV){
        float2 t1 = w1;
        #pragma unroll
        for (int jm = 0; jm < 4; ++jm){
            float2 t2 = csqr(t1), t3 = cmul(t1, t2);
            bf4_fwd(r[jm], r[jm+4], r[jm+8], r[jm+12], t1, t2, t3);
            t1 = cmul(t1, wst);
        }
        #pragma unroll
        for (int rr = 0; rr < 4; ++rr)
            bf4_fwd(r[4*rr], r[4*rr+1], r[4*rr+2], r[4*rr+3], v1, v2, v3);
    } else {
        #pragma unroll
        for (int rr = 0; rr < 4; ++rr)
            bf4_inv(r[4*rr], r[4*rr+1], r[4*rr+2], r[4*rr+3], v1, v2, v3);
        float2 t1 = w1;
        #pragma unroll
        for (int jm = 0; jm < 4; ++jm){
            float2 t2 = csqr(t1), t3 = cmul(t1, t2);
            bf4_inv(r[jm], r[jm+4], r[jm+8], r[jm+12], t1, t2, t3);
            t1 = cmul(t1, wst);
        }
    }
    #pragma unroll
    for (int j = 0; j < 16; ++j) sm[pb + j * SP] = r[j];
    __syncthreads();
}

__device__ __forceinline__ void stage1_fwd_fused(float2* __restrict__ sm, int tid,
                                                 const float2* __restrict__ src){
    const int q  = tid;
    const int SP = 273;              // SPAD stride for 256
    const int pb = SPAD(q);

    float2 r[16];
    #pragma unroll
    for (int j = 0; j < 8; ++j) r[j] = src[q + j * 256];

    float sn, cs;
    __sincosf(-PI_F * (float)q * (2.0f / 4096.0f), &sn, &cs);
    float2 w1 = make_float2(cs, sn);
    const float2 wst = make_float2(C8X, C8Y);
    float2 v1 = csqr(csqr(w1));
    float2 v2 = csqr(v1), v3 = cmul(v1, v2);

    float2 t1 = w1;
    #pragma unroll
    for (int jm = 0; jm < 4; ++jm){
        float2 t2 = csqr(t1), t3 = cmul(t1, t2);
        float2 a = r[jm], b = r[jm + 4];
        float2 ib = mi_pos(b);
        r[jm]      = cadd(a, b);
        r[jm + 4]  = cmul(csub(a, ib), t1);
        r[jm + 8]  = cmul(csub(a, b),  t2);
        r[jm + 12] = cmul(cadd(a, ib), t3);
        t1 = cmul(t1, wst);
    }
    #pragma unroll
    for (int rr = 0; rr < 4; ++rr)
        bf4_fwd(r[4*rr], r[4*rr+1], r[4*rr+2], r[4*rr+3], v1, v2, v3);
    #pragma unroll
    for (int j = 0; j < 16; ++j) sm[pb + j * SP] = r[j];
    __syncthreads();
}

__device__ __forceinline__ float gelu_erf(float x){
    return 0.5f * x * (1.0f + erff(x * 0.70710678118654752f));
}

// inverse stage 1 fused with bf16 hi/lo split epilogue
__device__ __forceinline__ void stage1_inv_fused_epi(float2* __restrict__ sm, int tid,
                                                     float dA,
                                                     const float2* __restrict__ uv,
                                                     __nv_bfloat162* __restrict__ ghv,
                                                     __nv_bfloat162* __restrict__ glv){
    const int q  = tid;
    const int SP = 273;
    const int pb = SPAD(q);

    float2 r[16];
    #pragma unroll
    for (int j = 0; j < 16; ++j) r[j] = sm[pb + j * SP];

    float sn, cs;
    __sincosf(-PI_F * (float)q * (2.0f / 4096.0f), &sn, &cs);
    float2 w1 = make_float2(cs, -sn);
    const float2 wst = make_float2(C8X, -C8Y);
    float2 v1 = csqr(csqr(w1));
    float2 v2 = csqr(v1), v3 = cmul(v1, v2);

    #pragma unroll
    for (int rr = 0; rr < 4; ++rr)
        bf4_inv(r[4*rr], r[4*rr+1], r[4*rr+2], r[4*rr+3], v1, v2, v3);

    float2 t1 = w1;
    #pragma unroll
    for (int jm = 0; jm < 4; ++jm){
        float2 t2 = csqr(t1), t3 = cmul(t1, t2);
        float2 z1 = cmul(r[jm+4],  t1);
        float2 z2 = cmul(r[jm+8],  t2);
        float2 z3 = cmul(r[jm+12], t3);
        float2 A  = cadd(r[jm], z2);
        float2 B  = csub(r[jm], z2);
        float2 Cc = cadd(z1, z3);
        float2 Dd = csub(z1, z3);
        r[jm]     = cadd(A, Cc);
        r[jm + 4] = cadd(B, mi_pos(Dd));
        t1 = cmul(t1, wst);
    }

    #pragma unroll
    for (int j = 0; j < 8; ++j){
        int l = q + j * 256;
        float2 uu = uv[l];
        float v0 = gelu_erf(r[j].x + dA * uu.x);
        float v1f = gelu_erf(r[j].y + dA * uu.y);
        __nv_bfloat162 hh = __floats2bfloat162_rn(v0, v1f);
        float r0 = v0  - __bfloat162float(__low2bfloat16(hh));
        float r1 = v1f - __bfloat162float(__high2bfloat16(hh));
        ghv[l] = hh;
        glv[l] = __floats2bfloat162_rn(r0, r1);
    }
}

template<bool INV>
__device__ __forceinline__ void stage_16_4(float2* __restrict__ sm, int tid){
    const int pb = SPAD(tid << 4);
    float2 r[16];
    #pragma unroll
    for (int i = 0; i < 16; ++i) r[i] = sm[pb + i];

    const float CP8 = 0.92387953251128675613f;
    const float SP8 = 0.38268343236508977173f;
    const float R2  = 0.70710678118654752440f;
    const float C3  = 0.38268343236508977173f;
    const float S3v = 0.92387953251128675613f;
    const float sg = INV ? 1.f : -1.f;
    float2 W1[4] = { make_float2(1,0), make_float2(CP8, sg*SP8), make_float2(R2, sg*R2),   make_float2(C3, sg*S3v) };
    float2 W2[4] = { make_float2(1,0), make_float2(R2, sg*R2),   make_float2(0.f, sg),     make_float2(-R2, sg*R2) };
    float2 W3[4] = { make_float2(1,0), make_float2(C3, sg*S3v),  make_float2(-R2, sg*R2),  make_float2(-CP8, -sg*SP8) };

    if (!INV){
        #pragma unroll
        for (int q = 0; q < 4; ++q)
            bf4_fwd(r[q], r[q+4], r[q+8], r[q+12], W1[q], W2[q], W3[q]);
        #pragma unroll
        for (int g = 0; g < 4; ++g){
            float2 a=r[4*g], b=r[4*g+1], c=r[4*g+2], d=r[4*g+3];
            float2 t0=cadd(a,c), t1=csub(a,c), t2=cadd(b,d), t3=mi_neg(csub(b,d));
            r[4*g]=cadd(t0,t2); r[4*g+1]=cadd(t1,t3); r[4*g+2]=csub(t0,t2); r[4*g+3]=csub(t1,t3);
        }
    } else {
        #pragma unroll
        for (int g = 0; g < 4; ++g){
            float2 y0=r[4*g], y1=r[4*g+1], y2=r[4*g+2], y3=r[4*g+3];
            float2 A=cadd(y0,y2), B=csub(y0,y2), Cc=cadd(y1,y3), Dd=csub(y1,y3);
            float2 iD=mi_pos(Dd);
            r[4*g]=cadd(A,Cc); r[4*g+2]=csub(A,Cc);
            r[4*g+1]=cadd(B,iD); r[4*g+3]=csub(B,iD);
        }
        #pragma unroll
        for (int q = 0; q < 4; ++q)
            bf4_inv(r[q], r[q+4], r[q+8], r[q+12], W1[q], W2[q], W3[q]);
    }
    #pragma unroll
    for (int i = 0; i < 16; ++i) sm[pb + i] = r[i];
    __syncthreads();
}

// ---------------- Kernel A: filter spectra --------------------------------
__global__ __launch_bounds__(256, 5)
void kfft_kernel(const float* __restrict__ k){
    extern __shared__ char smraw[];
    float2* sm = (float2*)smraw;
    const int tid = threadIdx.x;
    const int h   = blockIdx.x;

    stage1_fwd_fused(sm, tid, (const float2*)(k + (size_t)h * 4096));
    stage16N<256, false>(sm, tid);
    stage_16_4<false>(sm, tid);

    const float sc = 1.0f / 4096.0f;
    float sn, cs;
    __sincosf(-PI_F * (float)tid * (1.0f/4096.0f), &sn, &cs);
    float2 w = make_float2(cs, sn);
    const float2 CS = make_float2(C16X, C16Y);
    float2* Kf = d_Kf + (size_t)h * 4097;
    #pragma unroll 1
    for (int j = tid; j <= 2048; j += 256){
        int jn = 4096 - j;
        float2 Zj = sm[SPAD(pos4(j & 4095))];
        float2 Zn = sm[SPAD(pos4(jn & 4095))];
        float2 E = make_float2(0.5f*(Zj.x + Zn.x), 0.5f*(Zj.y - Zn.y));
        float2 O = make_float2(0.5f*(Zj.y + Zn.y), 0.5f*(Zn.x - Zj.x));
        float2 T = cmul(w, O);
        float2 Xj = cadd(E, T);
        float2 Xn = conjf2(csub(E, T));
        Kf[j]  = make_float2(sc*Xj.x, sc*Xj.y);
        Kf[jn] = make_float2(sc*Xn.x, sc*Xn.y);
        w = cmul(w, CS);
    }
}

// ---------------- Kernel B: conv + skip + gelu + bf16 split ---------------
__global__ __launch_bounds__(256, 5)
void conv_kernel(const float* __restrict__ u, const float* __restrict__ D){
    extern __shared__ char smraw[];
    float2* sm = (float2*)smraw;
    const int tid = threadIdx.x;
    const int h   = blockIdx.x;
    const int b   = blockIdx.y;
    const float2* uv = (const float2*)(u + ((size_t)b * 512 + h) * 4096);

    stage1_fwd_fused(sm, tid, uv);
    stage16N<256, false>(sm, tid);
    stage_16_4<false>(sm, tid);

    const float2* Kf = d_Kf + (size_t)h * 4097;
    float sn, cs;
    __sincosf(-PI_F * (float)tid * (1.0f/4096.0f), &sn, &cs);
    float2 w = make_float2(cs, sn);
    const float2 CS = make_float2(C16X, C16Y);
    #pragma unroll 1
    for (int j = tid; j <= 2048; j += 256){
        int jn = 4096 - j;
        int sj  = SPAD(pos4(j & 4095));
        int sn2 = SPAD(pos4(jn & 4095));
        float2 Zj = sm[sj], Zn = sm[sn2];
        float2 E = make_float2(0.5f*(Zj.x + Zn.x), 0.5f*(Zj.y - Zn.y));
        float2 O = make_float2(0.5f*(Zj.y + Zn.y), 0.5f*(Zn.x - Zj.x));
        float2 T = cmul(w, O);
        float2 Xj = cadd(E, T);
        float2 Xn = conjf2(csub(E, T));
        float2 Yj = cmul(Xj, Kf[j]);
        float2 Yn = cmul(Xn, Kf[jn]);
        float2 P  = make_float2(0.5f*(Yj.x + Yn.x), 0.5f*(Yj.y - Yn.y));
        float2 Mv = make_float2(0.5f*(Yj.x - Yn.x), 0.5f*(Yj.y + Yn.y));
        sm[sj] = cadd(P, mi_pos(cmul(conjf2(w), Mv)));
        if (j != 0){
            float2 P2 = make_float2(0.5f*(Yn.x + Yj.x), 0.5f*(Yn.y - Yj.y));
            float2 M2 = make_float2(0.5f*(Yn.x - Yj.x), 0.5f*(Yn.y + Yj.y));
            sm[sn2] = cadd(P2, mi_neg(cmul(w, M2)));
        }
        w = cmul(w, CS);
    }
    __syncthreads();

    stage_16_4<true>(sm, tid);
    stage16N<256, true>(sm, tid);
    size_t rb = ((size_t)b * 512 + h) * 4096;
    stage1_inv_fused_epi(sm, tid, D[h], uv,
                         (__nv_bfloat162*)(d_gh + rb),
                         (__nv_bfloat162*)(d_gl + rb));
}

// ---------------- W split prep --------------------------------------------
__global__ __launch_bounds__(256)
void wsplit_kernel(const float* __restrict__ W){
    int i = blockIdx.x * 1024 + threadIdx.x;
    #pragma unroll
    for (int r = 0; r < 4; ++r){
        int idx = i + r * 256;
        float v = W[idx];
        __nv_bfloat16 hb = __float2bfloat16(v);
        d_Wh[idx] = hb;
        d_Wl[idx] = __float2bfloat16(v - __bfloat162float(hb));
    }
}

// ---------------- Kernel C: mma.sync bf16 split GEMM ----------------------
// out[b,d,l] = sum_h W[d,h] g[b,h,l] + bias[d]
// CTA 128(M=d) x 128(N=l), K chunks of 32, 3-stage cp.async pipeline,
// ONE __syncthreads per chunk. 8 warps, warp tile 64x32, m16n8k16 HMMA.
// Products: Wh*gh + Wh*gl + Wl*gh (Wl*gl dropped, ~2^-18).
#define GSTAGE 37888
#define GEMM_SMEM (3 * GSTAGE)

__device__ __forceinline__ uint32_t smem_u32(const void* p){
    uint32_t a;
    asm("{ .reg .u64 t; cvta.to.shared.u64 t, %1; cvt.u32.u64 %0, t; }" : "=r"(a) : "l"(p));
    return a;
}
__device__ __forceinline__ void cp16(uint32_t s, const void* g){
    asm volatile("cp.async.cg.shared.global [%0], [%1], 16;" :: "r"(s), "l"(__cvta_generic_to_global(g)));
}
__device__ __forceinline__ void ldmA(uint32_t* a, uint32_t addr){
    asm volatile("ldmatrix.sync.aligned.m8n8.x4.shared.b16 {%0,%1,%2,%3}, [%4];"
                 : "=r"(a[0]), "=r"(a[1]), "=r"(a[2]), "=r"(a[3]) : "r"(addr));
}
__device__ __forceinline__ void ldmB(uint32_t* bq, uint32_t addr){
    asm volatile("ldmatrix.sync.aligned.m8n8.x2.trans.shared.b16 {%0,%1}, [%2];"
                 : "=r"(bq[0]), "=r"(bq[1]) : "r"(addr));
}
__device__ __forceinline__ void mma16816(float* c, const uint32_t* a, const uint32_t* bq){
    asm volatile("mma.sync.aligned.m16n8k16.row.col.f32.bf16.bf16.f32 "
                 "{%0,%1,%2,%3}, {%4,%5,%6,%7}, {%8,%9}, {%0,%1,%2,%3};"
                 : "+f"(c[0]), "+f"(c[1]), "+f"(c[2]), "+f"(c[3])
                 : "r"(a[0]), "r"(a[1]), "r"(a[2]), "r"(a[3]), "r"(bq[0]), "r"(bq[1]));
}

__global__ __launch_bounds__(256, 2)
void gemm_kernel(const float* __restrict__ bias, float* __restrict__ out){
    extern __shared__ char smraw[];
    const int tid  = threadIdx.x;
    const int lane = tid & 31;
    const int wid  = tid >> 5;
    const int warp_m = wid >> 2;          // 0..1 (64 rows each)
    const int warp_n = wid & 3;           // 0..3 (32 cols each)
    const int l0 = blockIdx.x * 128;
    const int d0 = blockIdx.y * 128;
    const int bb = blockIdx.z;
    const uint32_t sb = smem_u32(smraw);

    float acc[4][4][4];
    #pragma unroll
    for (int mi = 0; mi < 4; ++mi)
        #pragma unroll
        for (int ni = 0; ni < 4; ++ni)
            #pragma unroll
            for (int q = 0; q < 4; ++q) acc[mi][ni][q] = 0.f;

    const uint32_t aoff = ((warp_m * 64 + (lane & 15)) * 40 + ((lane >> 4) << 3)) * 2;
    const uint32_t boff = 20480 + ((lane & 15) * 136 + warp_n * 32) * 2;

    auto load_chunk = [&](int kk, uint32_t bufo){
        #pragma unroll
        for (int i = 0; i < 8; ++i){
            int u = tid + (i << 8);
            if (u < 1024){
                int sp = u >> 9, m = (u >> 2) & 127, c = u & 3;
                uint32_t sa = sb + bufo + sp * 10240 + m * 80 + c * 16;
                const __nv_bfloat16* Wp = sp ? d_Wl : d_Wh;
                cp16(sa, Wp + (((size_t)(d0 + m)) << 9) + (kk << 5) + (c << 3));
            } else {
                int v = u - 1024;
                int sp = v >> 9, kr = (v >> 4) & 31, c = v & 15;
                uint32_t sa = sb + bufo + 20480 + sp * 8704 + kr * 272 + c * 16;
                const __nv_bfloat16* Gp = sp ? d_gl : d_gh;
                cp16(sa, Gp + (((size_t)(bb * 512 + (kk << 5) + kr)) << 12) + l0 + (c << 3));
            }
        }
        asm volatile("cp.async.commit_group;");
    };

    load_chunk(0, 0u);
    load_chunk(1, GSTAGE);

    #pragma unroll 1
    for (int kk = 0; kk < 16; ++kk){
        if (kk + 1 < 16)
            asm volatile("cp.async.wait_group 1;" ::: "memory");
        else
            asm volatile("cp.async.wait_group 0;" ::: "memory");
        __syncthreads();

        if (kk + 2 < 16)
            load_chunk(kk + 2, (uint32_t)(((kk + 2) % 3) * GSTAGE));

        const uint32_t bufo = (uint32_t)((kk % 3) * GSTAGE);
        #pragma unroll
        for (int ks = 0; ks < 2; ++ks){
            const uint32_t aA = sb + bufo + aoff + ks * 32;
            const uint32_t aB = sb + bufo + boff + ks * 16 * 272;
            uint32_t a[4][4], bh[4][2], bl[4][2];
            #pragma unroll
            for (int mi = 0; mi < 4; ++mi) ldmA(a[mi], aA + mi * 1280);
            #pragma unroll
            for (int ni = 0; ni < 4; ++ni) ldmB(bh[ni], aB + ni * 16);
            #pragma unroll
            for (int mi = 0; mi < 4; ++mi)
                #pragma unroll
                for (int ni = 0; ni < 4; ++ni) mma16816(acc[mi][ni], a[mi], bh[ni]);
            #pragma unroll
            for (int ni = 0; ni < 4; ++ni) ldmB(bl[ni], aB + 8704 + ni * 16);
            #pragma unroll
            for (int mi = 0; mi < 4; ++mi)
                #pragma unroll
                for (int ni = 0; ni < 4; ++ni) mma16816(acc[mi][ni], a[mi], bl[ni]);
            #pragma unroll
            for (int mi = 0; mi < 4; ++mi) ldmA(a[mi], aA + 10240 + mi * 1280);
            #pragma unroll
            for (int mi = 0; mi < 4; ++mi)
                #pragma unroll
                for (int ni = 0; ni < 4; ++ni) mma16816(acc[mi][ni], a[mi], bh[ni]);
        }
    }

    #pragma unroll
    for (int mi = 0; mi < 4; ++mi){
        int r0 = d0 + warp_m * 64 + mi * 16 + (lane >> 2);
        float bv0 = bias[r0], bv1 = bias[r0 + 8];
        float* p0 = out + (((size_t)(bb * 512 + r0)) << 12) + l0 + warp_n * 32 + (lane & 3) * 2;
        float* p1 = p0 + ((size_t)8 << 12);
        #pragma unroll
        for (int ni = 0; ni < 4; ++ni){
            *(float2*)(p0 + ni * 8) = make_float2(acc[mi][ni][0] + bv0, acc[mi][ni][1] + bv0);
            *(float2*)(p1 + ni * 8) = make_float2(acc[mi][ni][2] + bv1, acc[mi][ni][3] + bv1);
        }
    }
}

// ---------------- Launch ---------------------------------------------------
extern "C" void kernel_launch(void* const* d_in, const int* in_sizes, int n_in,
                              void* d_out, int out_size){
    const float* u    = (const float*)d_in[0];   // (8, 512, 4096)
    const float* k    = (const float*)d_in[1];   // (1, 512, 4096)
    const float* D    = (const float*)d_in[2];   // (1, 512)
    const float* W    = (const float*)d_in[3];   // (512, 512)
    const float* bias = (const float*)d_in[4];   // (512,)
    float* out = (float*)d_out;                  // (8, 512, 4096)

    const size_t smem = SMEM_F2 * sizeof(float2);   // ~34.9 KB for FFT kernels
    cudaFuncSetAttribute(kfft_kernel, cudaFuncAttributeMaxDynamicSharedMemorySize, (int)smem);
    cudaFuncSetAttribute(conv_kernel, cudaFuncAttributeMaxDynamicSharedMemorySize, (int)smem);
    cudaFuncSetAttribute(gemm_kernel, cudaFuncAttributeMaxDynamicSharedMemorySize, GEMM_SMEM);

    wsplit_kernel<<<256, 256>>>(W);
    kfft_kernel<<<512, 256, smem>>>(k);
    conv_kernel<<<dim3(512, 8), 256, smem>>>(u, D);
    gemm_kernel<<<dim3(4096 / 128, 512 / 128, 8), 256, GEMM_SMEM>>>(bias, out);
}

// round 16
// speedup vs baseline: 3.5980x; 1.1663x over previous
#include <cuda_runtime.h>
#include <cuda_bf16.h>
#include <cuda_fp16.h>
#include <cstdint>
#include <math.h>

#define PI_F 3.14159265358979323846f

// Scratch (allocation-free rule: __device__ globals)
__device__ float2 d_Kf[512 * 4097];               // filter half-spectra
__device__ __half d_g16[8ULL * 512 * 4096];       // gelu(conv+skip), fp16
__device__ __half d_Wh[512 * 512];                // W hi (fp16)
__device__ __half d_Wl[512 * 512];                // W lo (fp16 residual)

// ---------------- complex helpers ----------------------------------------
__device__ __forceinline__ float2 cadd(float2 a, float2 b){ return make_float2(a.x+b.x, a.y+b.y); }
__device__ __forceinline__ float2 csub(float2 a, float2 b){ return make_float2(a.x-b.x, a.y-b.y); }
__device__ __forceinline__ float2 cmul(float2 a, float2 b){
    return make_float2(fmaf(a.x, b.x, -a.y*b.y), fmaf(a.x, b.y, a.y*b.x));
}
__device__ __forceinline__ float2 csqr(float2 a){
    return make_float2(fmaf(a.x,a.x,-a.y*a.y), 2.f*a.x*a.y);
}
__device__ __forceinline__ float2 conjf2(float2 a){ return make_float2(a.x, -a.y); }
__device__ __forceinline__ float2 mi_neg(float2 a){ return make_float2(a.y, -a.x); }
__device__ __forceinline__ float2 mi_pos(float2 a){ return make_float2(-a.y, a.x); }

__device__ __forceinline__ void bf4_fwd(float2&a, float2&b, float2&c, float2&d,
                                        float2 w1, float2 w2, float2 w3){
    float2 t0=cadd(a,c), t1=csub(a,c), t2=cadd(b,d), t3=mi_neg(csub(b,d));
    a = cadd(t0,t2);
    b = cmul(cadd(t1,t3), w1);
    c = cmul(csub(t0,t2), w2);
    d = cmul(csub(t1,t3), w3);
}
__device__ __forceinline__ void bf4_inv(float2&a, float2&b, float2&c, float2&d,
                                        float2 w1c, float2 w2c, float2 w3c){
    float2 z1=cmul(b,w1c), z2=cmul(c,w2c), z3=cmul(d,w3c);
    float2 A=cadd(a,z2), B=csub(a,z2), Cc=cadd(z1,z3), Dd=csub(z1,z3);
    float2 iD = mi_pos(Dd);
    a = cadd(A,Cc); c = csub(A,Cc);
    b = cadd(B,iD); d = csub(B,iD);
}

// second-order smem padding: 16-way -> 2-way conflicts on the digit-reversed
// pointwise gather; linear (carry-free) for every stage stride used below.
#define SPAD(i) ((i) + ((i) >> 4) + ((i) >> 8))
#define SMEM_F2 4368

__device__ __forceinline__ int pos4(int j){
    int y = __brev((unsigned)j) >> 20;
    return ((y & 0x555) << 1) | ((y >> 1) & 0x555);
}

#define C8X 0.92387953251128675613f
#define C8Y (-0.38268343236508977173f)
#define C16X 0.98078528040323044913f
#define C16Y (-0.19509032201612826785f)

template<int M, bool INV>
__device__ __forceinline__ void stage16N(float2* __restrict__ sm, int tid){
    const int S  = M >> 4;
    const int SP = S + (S >> 4) + (S >> 8);
    const int g  = (M == 4096) ? 0   : (tid >> 4);
    const int q  = (M == 4096) ? tid : (tid & 15);
    const int pb = SPAD(g * M + q);

    float2 r[16];
    #pragma unroll
    for (int j = 0; j < 16; ++j) r[j] = sm[pb + j * SP];

    float sn, cs;
    __sincosf(-PI_F * (float)q * (2.0f / (float)M), &sn, &cs);
    float2 w1 = make_float2(cs, INV ? -sn : sn);
    const float2 wst = make_float2(C8X, INV ? -C8Y : C8Y);
    float2 v1 = csqr(csqr(w1));
    float2 v2 = csqr(v1), v3 = cmul(v1, v2);

    if (!INV){
        float2 t1 = w1;
        #pragma unroll
        for (int jm = 0; jm < 4; ++jm){
            float2 t2 = csqr(t1), t3 = cmul(t1, t2);
            bf4_fwd(r[jm], r[jm+4], r[jm+8], r[jm+12], t1, t2, t3);
            t1 = cmul(t1, wst);
        }
        #pragma unroll
        for (int rr = 0; rr < 4; ++rr)
            bf4_fwd(r[4*rr], r[4*rr+1], r[4*rr+2], r[4*rr+3], v1, v2, v3);
    } else {
        #pragma unroll
        for (int rr = 0; rr < 4; ++rr)
            bf4_inv(r[4*rr], r[4*rr+1], r[4*rr+2], r[4*rr+3], v1, v2, v3);
        float2 t1 = w1;
        #pragma unroll
        for (int jm = 0; jm < 4; ++jm){
            float2 t2 = csqr(t1), t3 = cmul(t1, t2);
            bf4_inv(r[jm], r[jm+4], r[jm+8], r[jm+12], t1, t2, t3);
            t1 = cmul(t1, wst);
        }
    }
    #pragma unroll
    for (int j = 0; j < 16; ++j) sm[pb + j * SP] = r[j];
    __syncthreads();
}

__device__ __forceinline__ void stage1_fwd_fused(float2* __restrict__ sm, int tid,
                                                 const float2* __restrict__ src){
    const int q  = tid;
    const int SP = 273;
    const int pb = SPAD(q);

    float2 r[16];
    #pragma unroll
    for (int j = 0; j < 8; ++j) r[j] = src[q + j * 256];

    float sn, cs;
    __sincosf(-PI_F * (float)q * (2.0f / 4096.0f), &sn, &cs);
    float2 w1 = make_float2(cs, sn);
    const float2 wst = make_float2(C8X, C8Y);
    float2 v1 = csqr(csqr(w1));
    float2 v2 = csqr(v1), v3 = cmul(v1, v2);

    float2 t1 = w1;
    #pragma unroll
    for (int jm = 0; jm < 4; ++jm){
        float2 t2 = csqr(t1), t3 = cmul(t1, t2);
        float2 a = r[jm], b = r[jm + 4];
        float2 ib = mi_pos(b);
        r[jm]      = cadd(a, b);
        r[jm + 4]  = cmul(csub(a, ib), t1);
        r[jm + 8]  = cmul(csub(a, b),  t2);
        r[jm + 12] = cmul(cadd(a, ib), t3);
        t1 = cmul(t1, wst);
    }
    #pragma unroll
    for (int rr = 0; rr < 4; ++rr)
        bf4_fwd(r[4*rr], r[4*rr+1], r[4*rr+2], r[4*rr+3], v1, v2, v3);
    #pragma unroll
    for (int j = 0; j < 16; ++j) sm[pb + j * SP] = r[j];
    __syncthreads();
}

__device__ __forceinline__ float gelu_erf(float x){
    return 0.5f * x * (1.0f + erff(x * 0.70710678118654752f));
}

// inverse stage 1 fused with fp16 epilogue
__device__ __forceinline__ void stage1_inv_fused_epi(float2* __restrict__ sm, int tid,
                                                     float dA,
                                                     const float2* __restrict__ uv,
                                                     __half2* __restrict__ gv){
    const int q  = tid;
    const int SP = 273;
    const int pb = SPAD(q);

    float2 r[16];
    #pragma unroll
    for (int j = 0; j < 16; ++j) r[j] = sm[pb + j * SP];

    float sn, cs;
    __sincosf(-PI_F * (float)q * (2.0f / 4096.0f), &sn, &cs);
    float2 w1 = make_float2(cs, -sn);
    const float2 wst = make_float2(C8X, -C8Y);
    float2 v1 = csqr(csqr(w1));
    float2 v2 = csqr(v1), v3 = cmul(v1, v2);

    #pragma unroll
    for (int rr = 0; rr < 4; ++rr)
        bf4_inv(r[4*rr], r[4*rr+1], r[4*rr+2], r[4*rr+3], v1, v2, v3);

    float2 t1 = w1;
    #pragma unroll
    for (int jm = 0; jm < 4; ++jm){
        float2 t2 = csqr(t1), t3 = cmul(t1, t2);
        float2 z1 = cmul(r[jm+4],  t1);
        float2 z2 = cmul(r[jm+8],  t2);
        float2 z3 = cmul(r[jm+12], t3);
        float2 A  = cadd(r[jm], z2);
        float2 B  = csub(r[jm], z2);
        float2 Cc = cadd(z1, z3);
        float2 Dd = csub(z1, z3);
        r[jm]     = cadd(A, Cc);
        r[jm + 4] = cadd(B, mi_pos(Dd));
        t1 = cmul(t1, wst);
    }

    #pragma unroll
    for (int j = 0; j < 8; ++j){
        int l = q + j * 256;
        float2 uu = uv[l];
        float v0 = gelu_erf(r[j].x + dA * uu.x);
        float v1f = gelu_erf(r[j].y + dA * uu.y);
        gv[l] = __floats2half2_rn(v0, v1f);
    }
}

template<bool INV>
__device__ __forceinline__ void stage_16_4(float2* __restrict__ sm, int tid){
    const int pb = SPAD(tid << 4);
    float2 r[16];
    #pragma unroll
    for (int i = 0; i < 16; ++i) r[i] = sm[pb + i];

    const float CP8 = 0.92387953251128675613f;
    const float SP8 = 0.38268343236508977173f;
    const float R2  = 0.70710678118654752440f;
    const float C3  = 0.38268343236508977173f;
    const float S3v = 0.92387953251128675613f;
    const float sg = INV ? 1.f : -1.f;
    float2 W1[4] = { make_float2(1,0), make_float2(CP8, sg*SP8), make_float2(R2, sg*R2),   make_float2(C3, sg*S3v) };
    float2 W2[4] = { make_float2(1,0), make_float2(R2, sg*R2),   make_float2(0.f, sg),     make_float2(-R2, sg*R2) };
    float2 W3[4] = { make_float2(1,0), make_float2(C3, sg*S3v),  make_float2(-R2, sg*R2),  make_float2(-CP8, -sg*SP8) };

    if (!INV){
        #pragma unroll
        for (int q = 0; q < 4; ++q)
            bf4_fwd(r[q], r[q+4], r[q+8], r[q+12], W1[q], W2[q], W3[q]);
        #pragma unroll
        for (int g = 0; g < 4; ++g){
            float2 a=r[4*g], b=r[4*g+1], c=r[4*g+2], d=r[4*g+3];
            float2 t0=cadd(a,c), t1=csub(a,c), t2=cadd(b,d), t3=mi_neg(csub(b,d));
            r[4*g]=cadd(t0,t2); r[4*g+1]=cadd(t1,t3); r[4*g+2]=csub(t0,t2); r[4*g+3]=csub(t1,t3);
        }
    } else {
        #pragma unroll
        for (int g = 0; g < 4; ++g){
            float2 y0=r[4*g], y1=r[4*g+1], y2=r[4*g+2], y3=r[4*g+3];
            float2 A=cadd(y0,y2), B=csub(y0,y2), Cc=cadd(y1,y3), Dd=csub(y1,y3);
            float2 iD=mi_pos(Dd);
            r[4*g]=cadd(A,Cc); r[4*g+2]=csub(A,Cc);
            r[4*g+1]=cadd(B,iD); r[4*g+3]=csub(B,iD);
        }
        #pragma unroll
        for (int q = 0; q < 4; ++q)
            bf4_inv(r[q], r[q+4], r[q+8], r[q+12], W1[q], W2[q], W3[q]);
    }
    #pragma unroll
    for (int i = 0; i < 16; ++i) sm[pb + i] = r[i];
    __syncthreads();
}

// ---------------- Kernel A: filter spectra --------------------------------
__global__ __launch_bounds__(256, 5)
void kfft_kernel(const float* __restrict__ k){
    extern __shared__ char smraw[];
    float2* sm = (float2*)smraw;
    const int tid = threadIdx.x;
    const int h   = blockIdx.x;

    stage1_fwd_fused(sm, tid, (const float2*)(k + (size_t)h * 4096));
    stage16N<256, false>(sm, tid);
    stage_16_4<false>(sm, tid);

    const float sc = 1.0f / 4096.0f;
    float sn, cs;
    __sincosf(-PI_F * (float)tid * (1.0f/4096.0f), &sn, &cs);
    float2 w = make_float2(cs, sn);
    const float2 CS = make_float2(C16X, C16Y);
    float2* Kf = d_Kf + (size_t)h * 4097;
    #pragma unroll 1
    for (int j = tid; j <= 2048; j += 256){
        int jn = 4096 - j;
        float2 Zj = sm[SPAD(pos4(j & 4095))];
        float2 Zn = sm[SPAD(pos4(jn & 4095))];
        float2 E = make_float2(0.5f*(Zj.x + Zn.x), 0.5f*(Zj.y - Zn.y));
        float2 O = make_float2(0.5f*(Zj.y + Zn.y), 0.5f*(Zn.x - Zj.x));
        float2 T = cmul(w, O);
        float2 Xj = cadd(E, T);
        float2 Xn = conjf2(csub(E, T));
        Kf[j]  = make_float2(sc*Xj.x, sc*Xj.y);
        Kf[jn] = make_float2(sc*Xn.x, sc*Xn.y);
        w = cmul(w, CS);
    }
}

// ---------------- Kernel B: conv + skip + gelu + fp16 store ---------------
__global__ __launch_bounds__(256, 5)
void conv_kernel(const float* __restrict__ u, const float* __restrict__ D){
    extern __shared__ char smraw[];
    float2* sm = (float2*)smraw;
    const int tid = threadIdx.x;
    const int h   = blockIdx.x;
    const int b   = blockIdx.y;
    const float2* uv = (const float2*)(u + ((size_t)b * 512 + h) * 4096);

    stage1_fwd_fused(sm, tid, uv);
    stage16N<256, false>(sm, tid);
    stage_16_4<false>(sm, tid);

    const float2* Kf = d_Kf + (size_t)h * 4097;
    float sn, cs;
    __sincosf(-PI_F * (float)tid * (1.0f/4096.0f), &sn, &cs);
    float2 w = make_float2(cs, sn);
    const float2 CS = make_float2(C16X, C16Y);
    #pragma unroll 1
    for (int j = tid; j <= 2048; j += 256){
        int jn = 4096 - j;
        int sj  = SPAD(pos4(j & 4095));
        int sn2 = SPAD(pos4(jn & 4095));
        float2 Zj = sm[sj], Zn = sm[sn2];
        float2 E = make_float2(0.5f*(Zj.x + Zn.x), 0.5f*(Zj.y - Zn.y));
        float2 O = make_float2(0.5f*(Zj.y + Zn.y), 0.5f*(Zn.x - Zj.x));
        float2 T = cmul(w, O);
        float2 Xj = cadd(E, T);
        float2 Xn = conjf2(csub(E, T));
        float2 Yj = cmul(Xj, Kf[j]);
        float2 Yn = cmul(Xn, Kf[jn]);
        float2 P  = make_float2(0.5f*(Yj.x + Yn.x), 0.5f*(Yj.y - Yn.y));
        float2 Mv = make_float2(0.5f*(Yj.x - Yn.x), 0.5f*(Yj.y + Yn.y));
        sm[sj] = cadd(P, mi_pos(cmul(conjf2(w), Mv)));
        if (j != 0){
            float2 P2 = make_float2(0.5f*(Yn.x + Yj.x), 0.5f*(Yn.y - Yj.y));
            float2 M2 = make_float2(0.5f*(Yn.x - Yj.x), 0.5f*(Yn.y + Yj.y));
            sm[sn2] = cadd(P2, mi_neg(cmul(w, M2)));
        }
        w = cmul(w, CS);
    }
    __syncthreads();

    stage_16_4<true>(sm, tid);
    stage16N<256, true>(sm, tid);
    size_t rb = ((size_t)b * 512 + h) * 4096;
    stage1_inv_fused_epi(sm, tid, D[h], uv, (__half2*)(d_g16 + rb));
}

// ---------------- W split prep (fp16 hi/lo) --------------------------------
__global__ __launch_bounds__(256)
void wsplit_kernel(const float* __restrict__ W){
    int i = blockIdx.x * 1024 + threadIdx.x;
    #pragma unroll
    for (int r = 0; r < 4; ++r){
        int idx = i + r * 256;
        float v = W[idx];
        __half hb = __float2half(v);
        d_Wh[idx] = hb;
        d_Wl[idx] = __float2half(v - __half2float(hb));
    }
}

// ---------------- Kernel C: mma.sync fp16 split GEMM ----------------------
// out[b,d,l] = sum_h W[d,h] g[b,h,l] + bias[d]
// 2 products: Wh*g16 + Wl*g16 (g fp16 quantization error ~1.4e-4, dropped).
// CTA 128x128, K chunks of 32, 3-stage cp.async, one sync per chunk.
// 8 warps, warp tile 64x32, m16n8k16 f16 HMMA, fp32 accum.
//
// smem per stage: A 2x128x80B = 20480, B 32x272B = 8704 -> 29184
#define GSTAGE 29184
#define GEMM_SMEM (3 * GSTAGE)

__device__ __forceinline__ uint32_t smem_u32(const void* p){
    uint32_t a;
    asm("{ .reg .u64 t; cvta.to.shared.u64 t, %1; cvt.u32.u64 %0, t; }" : "=r"(a) : "l"(p));
    return a;
}
__device__ __forceinline__ void cp16(uint32_t s, const void* g){
    asm volatile("cp.async.cg.shared.global [%0], [%1], 16;" :: "r"(s), "l"(__cvta_generic_to_global(g)));
}
__device__ __forceinline__ void ldmA(uint32_t* a, uint32_t addr){
    asm volatile("ldmatrix.sync.aligned.m8n8.x4.shared.b16 {%0,%1,%2,%3}, [%4];"
                 : "=r"(a[0]), "=r"(a[1]), "=r"(a[2]), "=r"(a[3]) : "r"(addr));
}
__device__ __forceinline__ void ldmB(uint32_t* bq, uint32_t addr){
    asm volatile("ldmatrix.sync.aligned.m8n8.x2.trans.shared.b16 {%0,%1}, [%2];"
                 : "=r"(bq[0]), "=r"(bq[1]) : "r"(addr));
}
__device__ __forceinline__ void mma16816(float* c, const uint32_t* a, const uint32_t* bq){
    asm volatile("mma.sync.aligned.m16n8k16.row.col.f32.f16.f16.f32 "
                 "{%0,%1,%2,%3}, {%4,%5,%6,%7}, {%8,%9}, {%0,%1,%2,%3};"
                 : "+f"(c[0]), "+f"(c[1]), "+f"(c[2]), "+f"(c[3])
                 : "r"(a[0]), "r"(a[1]), "r"(a[2]), "r"(a[3]), "r"(bq[0]), "r"(bq[1]));
}

__global__ __launch_bounds__(256, 2)
void gemm_kernel(const float* __restrict__ bias, float* __restrict__ out){
    extern __shared__ char smraw[];
    const int tid  = threadIdx.x;
    const int lane = tid & 31;
    const int wid  = tid >> 5;
    const int warp_m = wid >> 2;          // 0..1 (64 rows each)
    const int warp_n = wid & 3;           // 0..3 (32 cols each)
    const int l0 = blockIdx.x * 128;
    const int d0 = blockIdx.y * 128;
    const int bb = blockIdx.z;
    const uint32_t sb = smem_u32(smraw);

    float acc[4][4][4];
    #pragma unroll
    for (int mi = 0; mi < 4; ++mi)
        #pragma unroll
        for (int ni = 0; ni < 4; ++ni)
            #pragma unroll
            for (int q = 0; q < 4; ++q) acc[mi][ni][q] = 0.f;

    const uint32_t aoff = ((warp_m * 64 + (lane & 15)) * 40 + ((lane >> 4) << 3)) * 2;
    const uint32_t boff = 20480 + (lane & 15) * 272 + warp_n * 64;

    // chunk loader: A 1024 + B 512 16B-units over 256 threads = 6 per thread
    auto load_chunk = [&](int kk, uint32_t bufo){
        #pragma unroll
        for (int i = 0; i < 6; ++i){
            int u = tid + (i << 8);
            if (u < 1024){
                int sp = u >> 9, m = (u >> 2) & 127, c = u & 3;
                uint32_t sa = sb + bufo + sp * 10240 + m * 80 + c * 16;
                const __half* Wp = sp ? d_Wl : d_Wh;
                cp16(sa, Wp + (((size_t)(d0 + m)) << 9) + (kk << 5) + (c << 3));
            } else {
                int v = u - 1024;                 // 0..511
                int kr = v >> 4, c = v & 15;
                uint32_t sa = sb + bufo + 20480 + kr * 272 + c * 16;
                cp16(sa, d_g16 + (((size_t)(bb * 512 + (kk << 5) + kr)) << 12) + l0 + (c << 3));
            }
        }
        asm volatile("cp.async.commit_group;");
    };

    load_chunk(0, 0u);
    load_chunk(1, GSTAGE);

    #pragma unroll 1
    for (int kk = 0; kk < 16; ++kk){
        if (kk + 1 < 16)
            asm volatile("cp.async.wait_group 1;" ::: "memory");
        else
            asm volatile("cp.async.wait_group 0;" ::: "memory");
        __syncthreads();

        if (kk + 2 < 16)
            load_chunk(kk + 2, (uint32_t)(((kk + 2) % 3) * GSTAGE));

        const uint32_t bufo = (uint32_t)((kk % 3) * GSTAGE);
        #pragma unroll
        for (int ks = 0; ks < 2; ++ks){
            const uint32_t aA = sb + bufo + aoff + ks * 32;
            const uint32_t aB = sb + bufo + boff + ks * 16 * 272;
            uint32_t a[4][4], bf[4][2];
            #pragma unroll
            for (int ni = 0; ni < 4; ++ni) ldmB(bf[ni], aB + ni * 16);
            #pragma unroll
            for (int mi = 0; mi < 4; ++mi) ldmA(a[mi], aA + mi * 1280);
            #pragma unroll
            for (int mi = 0; mi < 4; ++mi)
                #pragma unroll
                for (int ni = 0; ni < 4; ++ni) mma16816(acc[mi][ni], a[mi], bf[ni]);
            #pragma unroll
            for (int mi = 0; mi < 4; ++mi) ldmA(a[mi], aA + 10240 + mi * 1280);
            #pragma unroll
            for (int mi = 0; mi < 4; ++mi)
                #pragma unroll
                for (int ni = 0; ni < 4; ++ni) mma16816(acc[mi][ni], a[mi], bf[ni]);
        }
    }

    #pragma unroll
    for (int mi = 0; mi < 4; ++mi){
        int r0 = d0 + warp_m * 64 + mi * 16 + (lane >> 2);
        float bv0 = bias[r0], bv1 = bias[r0 + 8];
        float* p0 = out + (((size_t)(bb * 512 + r0)) << 12) + l0 + warp_n * 32 + (lane & 3) * 2;
        float* p1 = p0 + ((size_t)8 << 12);
        #pragma unroll
        for (int ni = 0; ni < 4; ++ni){
            *(float2*)(p0 + ni * 8) = make_float2(acc[mi][ni][0] + bv0, acc[mi][ni][1] + bv0);
            *(float2*)(p1 + ni * 8) = make_float2(acc[mi][ni][2] + bv1, acc[mi][ni][3] + bv1);
        }
    }
}

// ---------------- Launch ---------------------------------------------------
extern "C" void kernel_launch(void* const* d_in, const int* in_sizes, int n_in,
                              void* d_out, int out_size){
    const float* u    = (const float*)d_in[0];   // (8, 512, 4096)
    const float* k    = (const float*)d_in[1];   // (1, 512, 4096)
    const float* D    = (const float*)d_in[2];   // (1, 512)
    const float* W    = (const float*)d_in[3];   // (512, 512)
    const float* bias = (const float*)d_in[4];   // (512,)
    float* out = (float*)d_out;                  // (8, 512, 4096)

    const size_t smem = SMEM_F2 * sizeof(float2);   // ~34.9 KB for FFT kernels
    cudaFuncSetAttribute(kfft_kernel, cudaFuncAttributeMaxDynamicSharedMemorySize, (int)smem);
    cudaFuncSetAttribute(conv_kernel, cudaFuncAttributeMaxDynamicSharedMemorySize, (int)smem);
    cudaFuncSetAttribute(gemm_kernel, cudaFuncAttributeMaxDynamicSharedMemorySize, GEMM_SMEM);

    wsplit_kernel<<<256, 256>>>(W);
    kfft_kernel<<<512, 256, smem>>>(k);
    conv_kernel<<<dim3(512, 8), 256, smem>>>(u, D);
    gemm_kernel<<<dim3(4096 / 128, 512 / 128, 8), 256, GEMM_SMEM>>>(bias, out);
}

// round 17
// speedup vs baseline: 4.3519x; 1.2095x over previous
#include <cuda_runtime.h>
#include <cuda_bf16.h>
#include <cuda_fp16.h>
#include <cstdint>
#include <math.h>

#define PI_F 3.14159265358979323846f

// Scratch (allocation-free rule: __device__ globals)
__device__ float2 d_Kf[512 * 4097];               // filter half-spectra
__device__ __half d_g16[8ULL * 512 * 4096];       // gelu(conv+skip), fp16
__device__ __half d_W16[512 * 512];               // W (fp16)

// ---------------- complex helpers ----------------------------------------
__device__ __forceinline__ float2 cadd(float2 a, float2 b){ return make_float2(a.x+b.x, a.y+b.y); }
__device__ __forceinline__ float2 csub(float2 a, float2 b){ return make_float2(a.x-b.x, a.y-b.y); }
__device__ __forceinline__ float2 cmul(float2 a, float2 b){
    return make_float2(fmaf(a.x, b.x, -a.y*b.y), fmaf(a.x, b.y, a.y*b.x));
}
__device__ __forceinline__ float2 csqr(float2 a){
    return make_float2(fmaf(a.x,a.x,-a.y*a.y), 2.f*a.x*a.y);
}
__device__ __forceinline__ float2 conjf2(float2 a){ return make_float2(a.x, -a.y); }
__device__ __forceinline__ float2 mi_neg(float2 a){ return make_float2(a.y, -a.x); }
__device__ __forceinline__ float2 mi_pos(float2 a){ return make_float2(-a.y, a.x); }

__device__ __forceinline__ void bf4_fwd(float2&a, float2&b, float2&c, float2&d,
                                        float2 w1, float2 w2, float2 w3){
    float2 t0=cadd(a,c), t1=csub(a,c), t2=cadd(b,d), t3=mi_neg(csub(b,d));
    a = cadd(t0,t2);
    b = cmul(cadd(t1,t3), w1);
    c = cmul(csub(t0,t2), w2);
    d = cmul(csub(t1,t3), w3);
}
__device__ __forceinline__ void bf4_inv(float2&a, float2&b, float2&c, float2&d,
                                        float2 w1c, float2 w2c, float2 w3c){
    float2 z1=cmul(b,w1c), z2=cmul(c,w2c), z3=cmul(d,w3c);
    float2 A=cadd(a,z2), B=csub(a,z2), Cc=cadd(z1,z3), Dd=csub(z1,z3);
    float2 iD = mi_pos(Dd);
    a = cadd(A,Cc); c = csub(A,Cc);
    b = cadd(B,iD); d = csub(B,iD);
}

// second-order smem padding: 16-way -> 2-way conflicts on the digit-reversed
// pointwise gather; linear (carry-free) for every stage stride used below.
#define SPAD(i) ((i) + ((i) >> 4) + ((i) >> 8))
#define SMEM_F2 4368

__device__ __forceinline__ int pos4(int j){
    int y = __brev((unsigned)j) >> 20;
    return ((y & 0x555) << 1) | ((y >> 1) & 0x555);
}

#define C8X 0.92387953251128675613f
#define C8Y (-0.38268343236508977173f)
#define C16X 0.98078528040323044913f
#define C16Y (-0.19509032201612826785f)

template<int M, bool INV>
__device__ __forceinline__ void stage16N(float2* __restrict__ sm, int tid){
    const int S  = M >> 4;
    const int SP = S + (S >> 4) + (S >> 8);
    const int g  = (M == 4096) ? 0   : (tid >> 4);
    const int q  = (M == 4096) ? tid : (tid & 15);
    const int pb = SPAD(g * M + q);

    float2 r[16];
    #pragma unroll
    for (int j = 0; j < 16; ++j) r[j] = sm[pb + j * SP];

    float sn, cs;
    __sincosf(-PI_F * (float)q * (2.0f / (float)M), &sn, &cs);
    float2 w1 = make_float2(cs, INV ? -sn : sn);
    const float2 wst = make_float2(C8X, INV ? -C8Y : C8Y);
    float2 v1 = csqr(csqr(w1));
    float2 v2 = csqr(v1), v3 = cmul(v1, v2);

    if (!INV){
        float2 t1 = w1;
        #pragma unroll
        for (int jm = 0; jm < 4; ++jm){
            float2 t2 = csqr(t1), t3 = cmul(t1, t2);
            bf4_fwd(r[jm], r[jm+4], r[jm+8], r[jm+12], t1, t2, t3);
            t1 = cmul(t1, wst);
        }
        #pragma unroll
        for (int rr = 0; rr < 4; ++rr)
            bf4_fwd(r[4*rr], r[4*rr+1], r[4*rr+2], r[4*rr+3], v1, v2, v3);
    } else {
        #pragma unroll
        for (int rr = 0; rr < 4; ++rr)
            bf4_inv(r[4*rr], r[4*rr+1], r[4*rr+2], r[4*rr+3], v1, v2, v3);
        float2 t1 = w1;
        #pragma unroll
        for (int jm = 0; jm < 4; ++jm){
            float2 t2 = csqr(t1), t3 = cmul(t1, t2);
            bf4_inv(r[jm], r[jm+4], r[jm+8], r[jm+12], t1, t2, t3);
            t1 = cmul(t1, wst);
        }
    }
    #pragma unroll
    for (int j = 0; j < 16; ++j) sm[pb + j * SP] = r[j];
    __syncthreads();
}

__device__ __forceinline__ void stage1_fwd_fused(float2* __restrict__ sm, int tid,
                                                 const float2* __restrict__ src){
    const int q  = tid;
    const int SP = 273;
    const int pb = SPAD(q);

    float2 r[16];
    #pragma unroll
    for (int j = 0; j < 8; ++j) r[j] = src[q + j * 256];

    float sn, cs;
    __sincosf(-PI_F * (float)q * (2.0f / 4096.0f), &sn, &cs);
    float2 w1 = make_float2(cs, sn);
    const float2 wst = make_float2(C8X, C8Y);
    float2 v1 = csqr(csqr(w1));
    float2 v2 = csqr(v1), v3 = cmul(v1, v2);

    float2 t1 = w1;
    #pragma unroll
    for (int jm = 0; jm < 4; ++jm){
        float2 t2 = csqr(t1), t3 = cmul(t1, t2);
        float2 a = r[jm], b = r[jm + 4];
        float2 ib = mi_pos(b);
        r[jm]      = cadd(a, b);
        r[jm + 4]  = cmul(csub(a, ib), t1);
        r[jm + 8]  = cmul(csub(a, b),  t2);
        r[jm + 12] = cmul(cadd(a, ib), t3);
        t1 = cmul(t1, wst);
    }
    #pragma unroll
    for (int rr = 0; rr < 4; ++rr)
        bf4_fwd(r[4*rr], r[4*rr+1], r[4*rr+2], r[4*rr+3], v1, v2, v3);
    #pragma unroll
    for (int j = 0; j < 16; ++j) sm[pb + j * SP] = r[j];
    __syncthreads();
}

__device__ __forceinline__ float gelu_erf(float x){
    return 0.5f * x * (1.0f + erff(x * 0.70710678118654752f));
}

// inverse stage 1 fused with fp16 epilogue
__device__ __forceinline__ void stage1_inv_fused_epi(float2* __restrict__ sm, int tid,
                                                     float dA,
                                                     const float2* __restrict__ uv,
                                                     __half2* __restrict__ gv){
    const int q  = tid;
    const int SP = 273;
    const int pb = SPAD(q);

    float2 r[16];
    #pragma unroll
    for (int j = 0; j < 16; ++j) r[j] = sm[pb + j * SP];

    float sn, cs;
    __sincosf(-PI_F * (float)q * (2.0f / 4096.0f), &sn, &cs);
    float2 w1 = make_float2(cs, -sn);
    const float2 wst = make_float2(C8X, -C8Y);
    float2 v1 = csqr(csqr(w1));
    float2 v2 = csqr(v1), v3 = cmul(v1, v2);

    #pragma unroll
    for (int rr = 0; rr < 4; ++rr)
        bf4_inv(r[4*rr], r[4*rr+1], r[4*rr+2], r[4*rr+3], v1, v2, v3);

    float2 t1 = w1;
    #pragma unroll
    for (int jm = 0; jm < 4; ++jm){
        float2 t2 = csqr(t1), t3 = cmul(t1, t2);
        float2 z1 = cmul(r[jm+4],  t1);
        float2 z2 = cmul(r[jm+8],  t2);
        float2 z3 = cmul(r[jm+12], t3);
        float2 A  = cadd(r[jm], z2);
        float2 B  = csub(r[jm], z2);
        float2 Cc = cadd(z1, z3);
        float2 Dd = csub(z1, z3);
        r[jm]     = cadd(A, Cc);
        r[jm + 4] = cadd(B, mi_pos(Dd));
        t1 = cmul(t1, wst);
    }

    #pragma unroll
    for (int j = 0; j < 8; ++j){
        int l = q + j * 256;
        float2 uu = uv[l];
        float v0 = gelu_erf(r[j].x + dA * uu.x);
        float v1f = gelu_erf(r[j].y + dA * uu.y);
        gv[l] = __floats2half2_rn(v0, v1f);
    }
}

template<bool INV>
__device__ __forceinline__ void stage_16_4(float2* __restrict__ sm, int tid){
    const int pb = SPAD(tid << 4);
    float2 r[16];
    #pragma unroll
    for (int i = 0; i < 16; ++i) r[i] = sm[pb + i];

    const float CP8 = 0.92387953251128675613f;
    const float SP8 = 0.38268343236508977173f;
    const float R2  = 0.70710678118654752440f;
    const float C3  = 0.38268343236508977173f;
    const float S3v = 0.92387953251128675613f;
    const float sg = INV ? 1.f : -1.f;
    float2 W1[4] = { make_float2(1,0), make_float2(CP8, sg*SP8), make_float2(R2, sg*R2),   make_float2(C3, sg*S3v) };
    float2 W2[4] = { make_float2(1,0), make_float2(R2, sg*R2),   make_float2(0.f, sg),     make_float2(-R2, sg*R2) };
    float2 W3[4] = { make_float2(1,0), make_float2(C3, sg*S3v),  make_float2(-R2, sg*R2),  make_float2(-CP8, -sg*SP8) };

    if (!INV){
        #pragma unroll
        for (int q = 0; q < 4; ++q)
            bf4_fwd(r[q], r[q+4], r[q+8], r[q+12], W1[q], W2[q], W3[q]);
        #pragma unroll
        for (int g = 0; g < 4; ++g){
            float2 a=r[4*g], b=r[4*g+1], c=r[4*g+2], d=r[4*g+3];
            float2 t0=cadd(a,c), t1=csub(a,c), t2=cadd(b,d), t3=mi_neg(csub(b,d));
            r[4*g]=cadd(t0,t2); r[4*g+1]=cadd(t1,t3); r[4*g+2]=csub(t0,t2); r[4*g+3]=csub(t1,t3);
        }
    } else {
        #pragma unroll
        for (int g = 0; g < 4; ++g){
            float2 y0=r[4*g], y1=r[4*g+1], y2=r[4*g+2], y3=r[4*g+3];
            float2 A=cadd(y0,y2), B=csub(y0,y2), Cc=cadd(y1,y3), Dd=csub(y1,y3);
            float2 iD=mi_pos(Dd);
            r[4*g]=cadd(A,Cc); r[4*g+2]=csub(A,Cc);
            r[4*g+1]=cadd(B,iD); r[4*g+3]=csub(B,iD);
        }
        #pragma unroll
        for (int q = 0; q < 4; ++q)
            bf4_inv(r[q], r[q+4], r[q+8], r[q+12], W1[q], W2[q], W3[q]);
    }
    #pragma unroll
    for (int i = 0; i < 16; ++i) sm[pb + i] = r[i];
    __syncthreads();
}

// ---------------- Kernel A: filter spectra --------------------------------
__global__ __launch_bounds__(256, 5)
void kfft_kernel(const float* __restrict__ k){
    extern __shared__ char smraw[];
    float2* sm = (float2*)smraw;
    const int tid = threadIdx.x;
    const int h   = blockIdx.x;

    stage1_fwd_fused(sm, tid, (const float2*)(k + (size_t)h * 4096));
    stage16N<256, false>(sm, tid);
    stage_16_4<false>(sm, tid);

    const float sc = 1.0f / 4096.0f;
    float sn, cs;
    __sincosf(-PI_F * (float)tid * (1.0f/4096.0f), &sn, &cs);
    float2 w = make_float2(cs, sn);
    const float2 CS = make_float2(C16X, C16Y);
    float2* Kf = d_Kf + (size_t)h * 4097;
    #pragma unroll 1
    for (int j = tid; j <= 2048; j += 256){
        int jn = 4096 - j;
        float2 Zj = sm[SPAD(pos4(j & 4095))];
        float2 Zn = sm[SPAD(pos4(jn & 4095))];
        float2 E = make_float2(0.5f*(Zj.x + Zn.x), 0.5f*(Zj.y - Zn.y));
        float2 O = make_float2(0.5f*(Zj.y + Zn.y), 0.5f*(Zn.x - Zj.x));
        float2 T = cmul(w, O);
        float2 Xj = cadd(E, T);
        float2 Xn = conjf2(csub(E, T));
        Kf[j]  = make_float2(sc*Xj.x, sc*Xj.y);
        Kf[jn] = make_float2(sc*Xn.x, sc*Xn.y);
        w = cmul(w, CS);
    }
}

// ---------------- Kernel B: conv + skip + gelu + fp16 store ---------------
__global__ __launch_bounds__(256, 5)
void conv_kernel(const float* __restrict__ u, const float* __restrict__ D){
    extern __shared__ char smraw[];
    float2* sm = (float2*)smraw;
    const int tid = threadIdx.x;
    const int h   = blockIdx.x;
    const int b   = blockIdx.y;
    const float2* uv = (const float2*)(u + ((size_t)b * 512 + h) * 4096);

    stage1_fwd_fused(sm, tid, uv);
    stage16N<256, false>(sm, tid);
    stage_16_4<false>(sm, tid);

    const float2* Kf = d_Kf + (size_t)h * 4097;
    float sn, cs;
    __sincosf(-PI_F * (float)tid * (1.0f/4096.0f), &sn, &cs);
    float2 w = make_float2(cs, sn);
    const float2 CS = make_float2(C16X, C16Y);
    #pragma unroll 1
    for (int j = tid; j <= 2048; j += 256){
        int jn = 4096 - j;
        int sj  = SPAD(pos4(j & 4095));
        int sn2 = SPAD(pos4(jn & 4095));
        float2 Zj = sm[sj], Zn = sm[sn2];
        float2 E = make_float2(0.5f*(Zj.x + Zn.x), 0.5f*(Zj.y - Zn.y));
        float2 O = make_float2(0.5f*(Zj.y + Zn.y), 0.5f*(Zn.x - Zj.x));
        float2 T = cmul(w, O);
        float2 Xj = cadd(E, T);
        float2 Xn = conjf2(csub(E, T));
        float2 Yj = cmul(Xj, Kf[j]);
        float2 Yn = cmul(Xn, Kf[jn]);
        float2 P  = make_float2(0.5f*(Yj.x + Yn.x), 0.5f*(Yj.y - Yn.y));
        float2 Mv = make_float2(0.5f*(Yj.x - Yn.x), 0.5f*(Yj.y + Yn.y));
        sm[sj] = cadd(P, mi_pos(cmul(conjf2(w), Mv)));
        if (j != 0){
            float2 P2 = make_float2(0.5f*(Yn.x + Yj.x), 0.5f*(Yn.y - Yj.y));
            float2 M2 = make_float2(0.5f*(Yn.x - Yj.x), 0.5f*(Yn.y + Yj.y));
            sm[sn2] = cadd(P2, mi_neg(cmul(w, M2)));
        }
        w = cmul(w, CS);
    }
    __syncthreads();

    stage_16_4<true>(sm, tid);
    stage16N<256, true>(sm, tid);
    size_t rb = ((size_t)b * 512 + h) * 4096;
    stage1_inv_fused_epi(sm, tid, D[h], uv, (__half2*)(d_g16 + rb));
}

// ---------------- W fp16 prep ----------------------------------------------
__global__ __launch_bounds__(256)
void wsplit_kernel(const float* __restrict__ W){
    int i = blockIdx.x * 1024 + threadIdx.x;
    #pragma unroll
    for (int r = 0; r < 4; ++r){
        int idx = i + r * 256;
        d_W16[idx] = __float2half(W[idx]);
    }
}

// ---------------- Kernel C: mma.sync fp16 GEMM ----------------------------
// out[b,d,l] = sum_h W[d,h] g[b,h,l] + bias[d]
// Single product fp16(W)*fp16(g), fp32 accumulate (rel err ~3e-4).
// CTA 128x128, K chunks of 32, 3-stage cp.async, one sync per chunk.
// 8 warps, warp tile 64x32, m16n8k16 f16 HMMA.
//
// smem per stage: A 128x80B = 10240, B 32x272B = 8704 -> 18944
#define GSTAGE 18944
#define GEMM_SMEM (3 * GSTAGE)

__device__ __forceinline__ uint32_t smem_u32(const void* p){
    uint32_t a;
    asm("{ .reg .u64 t; cvta.to.shared.u64 t, %1; cvt.u32.u64 %0, t; }" : "=r"(a) : "l"(p));
    return a;
}
__device__ __forceinline__ void cp16(uint32_t s, const void* g){
    asm volatile("cp.async.cg.shared.global [%0], [%1], 16;" :: "r"(s), "l"(__cvta_generic_to_global(g)));
}
__device__ __forceinline__ void ldmA(uint32_t* a, uint32_t addr){
    asm volatile("ldmatrix.sync.aligned.m8n8.x4.shared.b16 {%0,%1,%2,%3}, [%4];"
                 : "=r"(a[0]), "=r"(a[1]), "=r"(a[2]), "=r"(a[3]) : "r"(addr));
}
__device__ __forceinline__ void ldmB(uint32_t* bq, uint32_t addr){
    asm volatile("ldmatrix.sync.aligned.m8n8.x2.trans.shared.b16 {%0,%1}, [%2];"
                 : "=r"(bq[0]), "=r"(bq[1]) : "r"(addr));
}
__device__ __forceinline__ void mma16816(float* c, const uint32_t* a, const uint32_t* bq){
    asm volatile("mma.sync.aligned.m16n8k16.row.col.f32.f16.f16.f32 "
                 "{%0,%1,%2,%3}, {%4,%5,%6,%7}, {%8,%9}, {%0,%1,%2,%3};"
                 : "+f"(c[0]), "+f"(c[1]), "+f"(c[2]), "+f"(c[3])
                 : "r"(a[0]), "r"(a[1]), "r"(a[2]), "r"(a[3]), "r"(bq[0]), "r"(bq[1]));
}

__global__ __launch_bounds__(256, 2)
void gemm_kernel(const float* __restrict__ bias, float* __restrict__ out){
    extern __shared__ char smraw[];
    const int tid  = threadIdx.x;
    const int lane = tid & 31;
    const int wid  = tid >> 5;
    const int warp_m = wid >> 2;          // 0..1 (64 rows each)
    const int warp_n = wid & 3;           // 0..3 (32 cols each)
    const int l0 = blockIdx.x * 128;
    const int d0 = blockIdx.y * 128;
    const int bb = blockIdx.z;
    const uint32_t sb = smem_u32(smraw);

    float acc[4][4][4];
    #pragma unroll
    for (int mi = 0; mi < 4; ++mi)
        #pragma unroll
        for (int ni = 0; ni < 4; ++ni)
            #pragma unroll
            for (int q = 0; q < 4; ++q) acc[mi][ni][q] = 0.f;

    const uint32_t aoff = ((warp_m * 64 + (lane & 15)) * 40 + ((lane >> 4) << 3)) * 2;
    const uint32_t boff = 10240 + (lane & 15) * 272 + warp_n * 64;

    // chunk loader: A 512 + B 512 16B-units over 256 threads = 4 per thread
    auto load_chunk = [&](int kk, uint32_t bufo){
        #pragma unroll
        for (int i = 0; i < 4; ++i){
            int u = tid + (i << 8);
            if (u < 512){
                int m = u >> 2, c = u & 3;
                uint32_t sa = sb + bufo + m * 80 + c * 16;
                cp16(sa, d_W16 + (((size_t)(d0 + m)) << 9) + (kk << 5) + (c << 3));
            } else {
                int v = u - 512;                 // 0..511
                int kr = v >> 4, c = v & 15;
                uint32_t sa = sb + bufo + 10240 + kr * 272 + c * 16;
                cp16(sa, d_g16 + (((size_t)(bb * 512 + (kk << 5) + kr)) << 12) + l0 + (c << 3));
            }
        }
        asm volatile("cp.async.commit_group;");
    };

    load_chunk(0, 0u);
    load_chunk(1, GSTAGE);

    #pragma unroll 1
    for (int kk = 0; kk < 16; ++kk){
        if (kk + 1 < 16)
            asm volatile("cp.async.wait_group 1;" ::: "memory");
        else
            asm volatile("cp.async.wait_group 0;" ::: "memory");
        __syncthreads();

        if (kk + 2 < 16)
            load_chunk(kk + 2, (uint32_t)(((kk + 2) % 3) * GSTAGE));

        const uint32_t bufo = (uint32_t)((kk % 3) * GSTAGE);
        #pragma unroll
        for (int ks = 0; ks < 2; ++ks){
            const uint32_t aA = sb + bufo + aoff + ks * 32;
            const uint32_t aB = sb + bufo + boff + ks * 16 * 272;
            uint32_t a[4][4], bf[4][2];
            #pragma unroll
            for (int ni = 0; ni < 4; ++ni) ldmB(bf[ni], aB + ni * 16);
            #pragma unroll
            for (int mi = 0; mi < 4; ++mi) ldmA(a[mi], aA + mi * 1280);
            #pragma unroll
            for (int mi = 0; mi < 4; ++mi)
                #pragma unroll
                for (int ni = 0; ni < 4; ++ni) mma16816(acc[mi][ni], a[mi], bf[ni]);
        }
    }

    #pragma unroll
    for (int mi = 0; mi < 4; ++mi){
        int r0 = d0 + warp_m * 64 + mi * 16 + (lane >> 2);
        float bv0 = bias[r0], bv1 = bias[r0 + 8];
        float* p0 = out + (((size_t)(bb * 512 + r0)) << 12) + l0 + warp_n * 32 + (lane & 3) * 2;
        float* p1 = p0 + ((size_t)8 << 12);
        #pragma unroll
        for (int ni = 0; ni < 4; ++ni){
            *(float2*)(p0 + ni * 8) = make_float2(acc[mi][ni][0] + bv0, acc[mi][ni][1] + bv0);
            *(float2*)(p1 + ni * 8) = make_float2(acc[mi][ni][2] + bv1, acc[mi][ni][3] + bv1);
        }
    }
}

// ---------------- Launch ---------------------------------------------------
extern "C" void kernel_launch(void* const* d_in, const int* in_sizes, int n_in,
                              void* d_out, int out_size){
    const float* u    = (const float*)d_in[0];   // (8, 512, 4096)
    const float* k    = (const float*)d_in[1];   // (1, 512, 4096)
    const float* D    = (const float*)d_in[2];   // (1, 512)
    const float* W    = (const float*)d_in[3];   // (512, 512)
    const float* bias = (const float*)d_in[4];   // (512,)
    float* out = (float*)d_out;                  // (8, 512, 4096)

    const size_t smem = SMEM_F2 * sizeof(float2);   // ~34.9 KB for FFT kernels
    cudaFuncSetAttribute(kfft_kernel, cudaFuncAttributeMaxDynamicSharedMemorySize, (int)smem);
    cudaFuncSetAttribute(conv_kernel, cudaFuncAttributeMaxDynamicSharedMemorySize, (int)smem);
    cudaFuncSetAttribute(gemm_kernel, cudaFuncAttributeMaxDynamicSharedMemorySize, GEMM_SMEM);

    wsplit_kernel<<<256, 256>>>(W);
    kfft_kernel<<<512, 256, smem>>>(k);
    conv_kernel<<<dim3(512, 8), 256, smem>>>(u, D);
    gemm_kernel<<<dim3(4096 / 128, 512 / 128, 8), 256, GEMM_SMEM>>>(bias, out);
}